// round 3
// baseline (speedup 1.0000x reference)
#include <cuda_runtime.h>

#define DIMC  1024
#define NSEQ  1024
#define BATCH 4
#define NHEAD 16
#define HD    64
#define BHTOT (BATCH*NHEAD)

// -------- scratch (static device globals; no allocation in kernel_launch) ------
__device__ float g_Q[(size_t)BHTOT*NSEQ*HD];      // 16 MB  [b*16+h][n][d]
__device__ float g_K[(size_t)BHTOT*NSEQ*HD];      // 16 MB
__device__ float g_V[(size_t)BHTOT*NSEQ*HD];      // 16 MB
__device__ float g_attn[(size_t)BATCH*NSEQ*DIMC]; // 16 MB  [b][n][h*64+d]

// ============================================================================
// SGEMM: C = A (M,K) * B(Nc,K)^T.  128x128 tile, BK=16, 256 thr, 8x8 microtile.
// MODE 0: A = x, scatter outputs into g_Q/g_K/g_V per (sec,head).
// MODE 1: A = g_attn, add bias, write row-major C.
// ============================================================================
template<int MODE>
__global__ __launch_bounds__(256)
void sgemm_kernel(const float* __restrict__ A, const float* __restrict__ Bm,
                  const float* __restrict__ bias, float* __restrict__ C,
                  int M, int Nc, int K)
{
    __shared__ float As[16][132];
    __shared__ float Bs[16][132];

    const float* Ap = (MODE == 0) ? A : (const float*)g_attn;

    const int tid = threadIdx.x;
    const int tx = tid & 15;          // 8 output cols each
    const int ty = tid >> 4;          // 8 output rows each
    const int m0 = blockIdx.y * 128;
    const int n0 = blockIdx.x * 128;

    float acc[8][8];
#pragma unroll
    for (int i = 0; i < 8; i++)
#pragma unroll
        for (int j = 0; j < 8; j++) acc[i][j] = 0.0f;

    for (int k0 = 0; k0 < K; k0 += 16) {
#pragma unroll
        for (int r = 0; r < 2; r++) {
            int lin = tid + r * 256;            // 0..511
            int row = lin >> 2;                 // 0..127
            int kc  = (lin & 3) << 2;           // 0,4,8,12
            float4 av = *(const float4*)(Ap + (size_t)(m0 + row) * K + (k0 + kc));
            As[kc + 0][row] = av.x; As[kc + 1][row] = av.y;
            As[kc + 2][row] = av.z; As[kc + 3][row] = av.w;
            float4 bv = *(const float4*)(Bm + (size_t)(n0 + row) * K + (k0 + kc));
            Bs[kc + 0][row] = bv.x; Bs[kc + 1][row] = bv.y;
            Bs[kc + 2][row] = bv.z; Bs[kc + 3][row] = bv.w;
        }
        __syncthreads();
#pragma unroll
        for (int k = 0; k < 16; k++) {
            float a[8], b[8];
            *(float4*)(a)     = *(const float4*)&As[k][ty * 8];
            *(float4*)(a + 4) = *(const float4*)&As[k][ty * 8 + 4];
            *(float4*)(b)     = *(const float4*)&Bs[k][tx * 8];
            *(float4*)(b + 4) = *(const float4*)&Bs[k][tx * 8 + 4];
#pragma unroll
            for (int i = 0; i < 8; i++)
#pragma unroll
                for (int j = 0; j < 8; j++)
                    acc[i][j] += a[i] * b[j];
        }
        __syncthreads();
    }

    // ---- epilogue ----
#pragma unroll
    for (int i = 0; i < 8; i++) {
        int m = m0 + ty * 8 + i;
#pragma unroll
        for (int j4 = 0; j4 < 8; j4 += 4) {
            int f = n0 + tx * 8 + j4;
            float4 v = make_float4(acc[i][j4], acc[i][j4 + 1],
                                   acc[i][j4 + 2], acc[i][j4 + 3]);
            if (MODE == 0) {
                int b_i = m >> 10, n = m & 1023;
                int sec = f >> 10;
                int h = (f >> 6) & 15, d = f & 63;
                float* dst = (sec == 0) ? g_Q : (sec == 1) ? g_K : g_V;
                *(float4*)&dst[((size_t)(b_i * NHEAD + h) * NSEQ + n) * HD + d] = v;
            } else {
                float4 bb = *(const float4*)&bias[f];
                v.x += bb.x; v.y += bb.y; v.z += bb.z; v.w += bb.w;
                *(float4*)&C[(size_t)m * Nc + f] = v;
            }
        }
    }
}

// ============================================================================
// Fused causal flash attention with relative position term.
// score[n,m] = (q[n].k[m] + q[n].Er[N-1-n+m]) * 0.125,  m <= n.
// Block = 64 queries, loop key tiles of 64. 256 thr, 4x4 microtile (16x16 grid).
// SMEM: Qs/Ks [d][i] (64x68), Vs [j][d] (64x68), Ps (64x68), Es [d][t] (64x132).
// ============================================================================
__global__ __launch_bounds__(256, 2)
void attn_kernel(const float* __restrict__ Er)
{
    extern __shared__ float sm[];
    float* Qs = sm;                    // 64*68
    float* Ks = Qs + 64 * 68;
    float* Vs = Ks + 64 * 68;
    float* Ps = Vs + 64 * 68;
    float* Es = Ps + 64 * 68;          // 64*132

    const int tid = threadIdx.x;
    const int tx = tid & 15;           // 4 cols
    const int ty = tid >> 4;           // 4 rows
    const int bq = 15 - (int)blockIdx.x;   // heavy blocks first
    const int bh = blockIdx.y;             // b*16+h
    const int n0 = bq * 64;

    const float* Qg = g_Q + (size_t)bh * NSEQ * HD;
    const float* Kg = g_K + (size_t)bh * NSEQ * HD;
    const float* Vg = g_V + (size_t)bh * NSEQ * HD;

    // load Q tile (transposed -> Qs[d][i])
#pragma unroll
    for (int r = 0; r < 4; r++) {
        int lin = tid + r * 256;
        int i = lin >> 4, dc = (lin & 15) << 2;
        float4 v = *(const float4*)(Qg + (n0 + i) * HD + dc);
        Qs[(dc + 0) * 68 + i] = v.x;
        Qs[(dc + 1) * 68 + i] = v.y;
        Qs[(dc + 2) * 68 + i] = v.z;
        Qs[(dc + 3) * 68 + i] = v.w;
    }

    const float NEG_INF = __int_as_float(0xff800000);
    float m_i[4], l_i[4], o[4][4];
#pragma unroll
    for (int ii = 0; ii < 4; ii++) {
        m_i[ii] = NEG_INF; l_i[ii] = 0.0f;
#pragma unroll
        for (int dd = 0; dd < 4; dd++) o[ii][dd] = 0.0f;
    }

    const int tb = 60 + 4 * (tx - ty);   // aligned base into Es t-dim (0..120)

    for (int kt = 0; kt <= bq; kt++) {
        const int km0 = kt * 64;
        const int base = NSEQ - 64 - n0 + km0;   // >= 0

        __syncthreads();   // previous PV reads done before overwrite

        // K (transposed) + V (direct)
#pragma unroll
        for (int r = 0; r < 4; r++) {
            int lin = tid + r * 256;
            int j = lin >> 4, dc = (lin & 15) << 2;
            float4 kv = *(const float4*)(Kg + (km0 + j) * HD + dc);
            Ks[(dc + 0) * 68 + j] = kv.x;
            Ks[(dc + 1) * 68 + j] = kv.y;
            Ks[(dc + 2) * 68 + j] = kv.z;
            Ks[(dc + 3) * 68 + j] = kv.w;
            float4 vv = *(const float4*)(Vg + (km0 + j) * HD + dc);
            *(float4*)&Vs[j * 68 + dc] = vv;
        }
        // Er band: rows base..base+126 (transposed -> Es[d][t]); e>=N => masked, load 0
#pragma unroll
        for (int r = 0; r < 8; r++) {
            int lin = tid + r * 256;
            if (lin < 127 * 16) {
                int t = lin >> 4, dc = (lin & 15) << 2;
                int e = base + t;
                float4 ev = (e < NSEQ) ? *(const float4*)(Er + e * HD + dc)
                                       : make_float4(0.f, 0.f, 0.f, 0.f);
                Es[(dc + 0) * 132 + t] = ev.x;
                Es[(dc + 1) * 132 + t] = ev.y;
                Es[(dc + 2) * 132 + t] = ev.z;
                Es[(dc + 3) * 132 + t] = ev.w;
            }
        }
        __syncthreads();

        // ---- S = Q.K^T + Q.Er_band (diagonal gather) ----
        float acc[4][4];
#pragma unroll
        for (int ii = 0; ii < 4; ii++)
#pragma unroll
            for (int jj = 0; jj < 4; jj++) acc[ii][jj] = 0.0f;

#pragma unroll 8
        for (int d = 0; d < 64; d++) {
            float4 q4 = *(const float4*)&Qs[d * 68 + 4 * ty];
            float4 k4 = *(const float4*)&Ks[d * 68 + 4 * tx];
            float4 e0 = *(const float4*)&Es[d * 132 + tb];
            float4 e1 = *(const float4*)&Es[d * 132 + tb + 4];
            float q[4]  = {q4.x, q4.y, q4.z, q4.w};
            float kk[4] = {k4.x, k4.y, k4.z, k4.w};
            float e[8]  = {e0.x, e0.y, e0.z, e0.w, e1.x, e1.y, e1.z, e1.w};
#pragma unroll
            for (int ii = 0; ii < 4; ii++)
#pragma unroll
                for (int jj = 0; jj < 4; jj++) {
                    acc[ii][jj] += q[ii] * kk[jj];
                    acc[ii][jj] += q[ii] * e[jj - ii + 3];  // t = 63 + j - i
                }
        }

        float s[4][4];
#pragma unroll
        for (int ii = 0; ii < 4; ii++)
#pragma unroll
            for (int jj = 0; jj < 4; jj++)
                s[ii][jj] = acc[ii][jj] * 0.125f;

        if (kt == bq) {   // diagonal tile: mask j > i
#pragma unroll
            for (int ii = 0; ii < 4; ii++)
#pragma unroll
                for (int jj = 0; jj < 4; jj++)
                    if (4 * tx + jj > 4 * ty + ii) s[ii][jj] = NEG_INF;
        }

        // ---- online softmax (16 lanes share each row group) ----
#pragma unroll
        for (int ii = 0; ii < 4; ii++) {
            float tmax = fmaxf(fmaxf(s[ii][0], s[ii][1]), fmaxf(s[ii][2], s[ii][3]));
#pragma unroll
            for (int off = 8; off >= 1; off >>= 1)
                tmax = fmaxf(tmax, __shfl_xor_sync(0xffffffffu, tmax, off));
            float mnew  = fmaxf(m_i[ii], tmax);
            float alpha = __expf(m_i[ii] - mnew);
            float p0 = __expf(s[ii][0] - mnew);
            float p1 = __expf(s[ii][1] - mnew);
            float p2 = __expf(s[ii][2] - mnew);
            float p3 = __expf(s[ii][3] - mnew);
            float psum = (p0 + p1) + (p2 + p3);
#pragma unroll
            for (int off = 8; off >= 1; off >>= 1)
                psum += __shfl_xor_sync(0xffffffffu, psum, off);
            l_i[ii] = l_i[ii] * alpha + psum;
            m_i[ii] = mnew;
#pragma unroll
            for (int dd = 0; dd < 4; dd++) o[ii][dd] *= alpha;
            *(float4*)&Ps[(4 * ty + ii) * 68 + 4 * tx] = make_float4(p0, p1, p2, p3);
        }
        __syncthreads();

        // ---- O += P.V ----
#pragma unroll 8
        for (int j = 0; j < 64; j++) {
            float4 v4 = *(const float4*)&Vs[j * 68 + 4 * tx];
#pragma unroll
            for (int ii = 0; ii < 4; ii++) {
                float p = Ps[(4 * ty + ii) * 68 + j];
                o[ii][0] += p * v4.x;
                o[ii][1] += p * v4.y;
                o[ii][2] += p * v4.z;
                o[ii][3] += p * v4.w;
            }
        }
    }

    // write: g_attn[b][n][h*64+d]
    const int b_i = bh >> 4, h = bh & 15;
#pragma unroll
    for (int ii = 0; ii < 4; ii++) {
        float inv = 1.0f / l_i[ii];
        float4 v = make_float4(o[ii][0] * inv, o[ii][1] * inv,
                               o[ii][2] * inv, o[ii][3] * inv);
        *(float4*)&g_attn[((size_t)b_i * NSEQ + (n0 + 4 * ty + ii)) * DIMC
                          + h * HD + 4 * tx] = v;
    }
}

// ============================================================================
extern "C" void kernel_launch(void* const* d_in, const int* in_sizes, int n_in,
                              void* d_out, int out_size)
{
    const float* x      = (const float*)d_in[0];   // [4,1024,1024]
    const float* W_qkv  = (const float*)d_in[1];   // [3072,1024]
    const float* W_proj = (const float*)d_in[2];   // [1024,1024]
    const float* b_proj = (const float*)d_in[3];   // [1024]
    const float* Er     = (const float*)d_in[4];   // [1024,64]
    float* out = (float*)d_out;                    // [4,1024,1024]

    // 1) QKV GEMM: M=4096, Nc=3072, K=1024 -> scatter into g_Q/g_K/g_V
    sgemm_kernel<0><<<dim3(24, 32), 256>>>(x, W_qkv, nullptr, nullptr,
                                           4096, 3072, 1024);

    // 2) fused attention (16 q-tiles x 64 bh), 101 KB dynamic SMEM
    const int smem_bytes = (4 * 64 * 68 + 64 * 132) * (int)sizeof(float);
    cudaFuncSetAttribute(attn_kernel,
                         cudaFuncAttributeMaxDynamicSharedMemorySize, smem_bytes);
    attn_kernel<<<dim3(16, 64), 256, smem_bytes>>>(Er);

    // 3) proj GEMM + bias: M=4096, Nc=1024, K=1024
    sgemm_kernel<1><<<dim3(8, 32), 256>>>(nullptr, W_proj, b_proj, out,
                                          4096, 1024, 1024);
}

// round 5
// speedup vs baseline: 1.6555x; 1.6555x over previous
#include <cuda_runtime.h>
#include <cuda_bf16.h>
#include <cstdint>

#define DIMC  1024
#define NSEQ  1024
#define BATCH 4
#define NHEAD 16
#define HD    64
#define BHTOT (BATCH*NHEAD)

// ---------------- scratch (device globals; no allocation at runtime) ----------
__device__ float g_Q[(size_t)BHTOT*NSEQ*HD];
__device__ float g_K[(size_t)BHTOT*NSEQ*HD];
__device__ float g_V[(size_t)BHTOT*NSEQ*HD];
__device__ float g_attn[(size_t)BATCH*NSEQ*DIMC];

__device__ __nv_bfloat16 g_xhi[(size_t)BATCH*NSEQ*DIMC];
__device__ __nv_bfloat16 g_xlo[(size_t)BATCH*NSEQ*DIMC];
__device__ __nv_bfloat16 g_wqhi[(size_t)3*DIMC*DIMC];
__device__ __nv_bfloat16 g_wqlo[(size_t)3*DIMC*DIMC];
__device__ __nv_bfloat16 g_wphi[(size_t)DIMC*DIMC];
__device__ __nv_bfloat16 g_wplo[(size_t)DIMC*DIMC];
__device__ __nv_bfloat16 g_athi[(size_t)BATCH*NSEQ*DIMC];
__device__ __nv_bfloat16 g_atlo[(size_t)BATCH*NSEQ*DIMC];

// ---------------- helpers ------------------------------------------------------
__device__ __forceinline__ uint32_t smem_u32(const void* p) {
    uint32_t a;
    asm("{ .reg .u64 t; cvta.to.shared.u64 t, %1; cvt.u32.u64 %0, t; }"
        : "=r"(a) : "l"(p));
    return a;
}

__device__ __forceinline__ void cp_async16(uint32_t saddr, const void* gaddr) {
    asm volatile("cp.async.cg.shared.global [%0], [%1], 16;"
                 :: "r"(saddr), "l"(gaddr));
}
#define CP_COMMIT() asm volatile("cp.async.commit_group;" ::: "memory")
#define CP_WAIT(n)  asm volatile("cp.async.wait_group %0;" :: "n"(n) : "memory")

#define LDSM_X4(R0, R1, R2, R3, addr) \
    asm volatile("ldmatrix.sync.aligned.m8n8.x4.shared.b16 {%0,%1,%2,%3}, [%4];" \
                 : "=r"(R0), "=r"(R1), "=r"(R2), "=r"(R3) : "r"(addr))

#define MMA16816(d, a, b0, b1) \
    asm volatile("mma.sync.aligned.m16n8k16.row.col.f32.bf16.bf16.f32 " \
                 "{%0,%1,%2,%3}, {%4,%5,%6,%7}, {%8,%9}, {%0,%1,%2,%3};" \
                 : "+f"((d)[0]), "+f"((d)[1]), "+f"((d)[2]), "+f"((d)[3]) \
                 : "r"((a)[0]), "r"((a)[1]), "r"((a)[2]), "r"((a)[3]),   \
                   "r"(b0), "r"(b1))

// SW128 (Swizzle<3,4,3>) on byte offsets inside a 1024B-aligned tile
#define SW128(off) ((off) ^ (((off) >> 3) & 0x70))

// ============================================================================
// Split fp32 -> bf16 hi/lo.  WHICH: 0=x, 1=W_qkv, 2=W_proj, 3=g_attn
// ============================================================================
template<int WHICH>
__global__ void split_kernel(const float* __restrict__ src, int n4)
{
    int i = blockIdx.x * blockDim.x + threadIdx.x;
    if (i >= n4) return;
    const float* sp = (WHICH == 3) ? (const float*)g_attn : src;
    __nv_bfloat16* hi = (WHICH == 0) ? g_xhi : (WHICH == 1) ? g_wqhi
                      : (WHICH == 2) ? g_wphi : g_athi;
    __nv_bfloat16* lo = (WHICH == 0) ? g_xlo : (WHICH == 1) ? g_wqlo
                      : (WHICH == 2) ? g_wplo : g_atlo;
    float4 v = ((const float4*)sp)[i];
    __nv_bfloat16 h0 = __float2bfloat16(v.x);
    __nv_bfloat16 h1 = __float2bfloat16(v.y);
    __nv_bfloat16 h2 = __float2bfloat16(v.z);
    __nv_bfloat16 h3 = __float2bfloat16(v.w);
    __nv_bfloat16 l0 = __float2bfloat16(v.x - __bfloat162float(h0));
    __nv_bfloat16 l1 = __float2bfloat16(v.y - __bfloat162float(h1));
    __nv_bfloat16 l2 = __float2bfloat16(v.z - __bfloat162float(h2));
    __nv_bfloat16 l3 = __float2bfloat16(v.w - __bfloat162float(h3));
    ((__nv_bfloat162*)hi)[2*i]   = __nv_bfloat162(h0, h1);
    ((__nv_bfloat162*)hi)[2*i+1] = __nv_bfloat162(h2, h3);
    ((__nv_bfloat162*)lo)[2*i]   = __nv_bfloat162(l0, l1);
    ((__nv_bfloat162*)lo)[2*i+1] = __nv_bfloat162(l2, l3);
}

// ============================================================================
// HMMA split-precision GEMM.  C = A(M,1024) * B(Nc,1024)^T, fp32 out.
// Virtual K = 3*1024: [Ahi*Bhi | Blo pass | Alo pass].  CTA tile 128x128,
// 8 warps (4 m x 2 n), warp tile 32x64, mma.sync m16n8k16, SW128 smem,
// cp.async double-buffered K=64 stages.
// MODE 0: QKV (A=g_x*, B=g_wq*), scatter into g_Q/g_K/g_V.
// MODE 1: proj (A=g_at*, B=g_wp*), +bias, row-major out.
// ============================================================================
#define NSTAGES 48

template<int MODE>
__global__ __launch_bounds__(256)
void hmma_gemm(const float* __restrict__ bias, float* __restrict__ C)
{
    extern __shared__ char dynsm[];   // 2 stages x (16KB A + 16KB B)
    const uint32_t sbase = smem_u32(dynsm);

    const int tid  = threadIdx.x;
    const int wid  = tid >> 5;
    const int lane = tid & 31;
    const int wm = wid & 3;           // 4 warps along m (32 rows each)
    const int wn = wid >> 2;          // 2 warps along n (64 cols each)
    const int m0 = blockIdx.y * 128;
    const int n0 = blockIdx.x * 128;

    const __nv_bfloat16* Ahi = (MODE == 0) ? g_xhi : g_athi;
    const __nv_bfloat16* Alo = (MODE == 0) ? g_xlo : g_atlo;
    const __nv_bfloat16* Bhi = (MODE == 0) ? g_wqhi : g_wphi;
    const __nv_bfloat16* Blo = (MODE == 0) ? g_wqlo : g_wplo;

    float d[2][8][4];
#pragma unroll
    for (int mt = 0; mt < 2; mt++)
#pragma unroll
        for (int nt = 0; nt < 8; nt++)
#pragma unroll
            for (int r = 0; r < 4; r++) d[mt][nt][r] = 0.0f;

    // precomputed per-thread load slots (8 x 16B chunks per thread per stage)
    // c = tid + t*256 ; op = c>>10 ; row=(c>>3)&127 ; seg=c&7
    auto issue_stage = [&](int s) {
        const __nv_bfloat16* aS = (s < 32) ? Ahi : Alo;
        const __nv_bfloat16* bS = (s >= 16 && s < 32) ? Blo : Bhi;
        const int kin = (s & 15) * 64;
        const uint32_t stbase = sbase + (uint32_t)(s & 1) * 32768u;
#pragma unroll
        for (int t = 0; t < 8; t++) {
            int c   = tid + t * 256;
            int op  = c >> 10;
            int row = (c >> 3) & 127;
            int seg = c & 7;
            const __nv_bfloat16* src = op ? bS : aS;
            int r0 = op ? n0 : m0;
            const void* g = src + (size_t)(r0 + row) * 1024 + kin + seg * 8;
            uint32_t sa = stbase + (op ? 16384u : 0u)
                        + SW128((uint32_t)(row * 128 + seg * 16));
            cp_async16(sa, g);
        }
    };

    issue_stage(0);
    CP_COMMIT();

    for (int s = 0; s < NSTAGES; s++) {
        __syncthreads();               // all reads of buf[(s+1)&1] (stage s-1) done
        if (s + 1 < NSTAGES) {
            issue_stage(s + 1);
            CP_COMMIT();
            CP_WAIT(1);                // stage s resident
        } else {
            CP_WAIT(0);
        }
        __syncthreads();

        const uint32_t aBase = sbase + (uint32_t)(s & 1) * 32768u;
        const uint32_t bBase = aBase + 16384u;

#pragma unroll
        for (int ks = 0; ks < 4; ks++) {
            const int kb = ks * 32;    // byte offset of k16 chunk within 128B row

            uint32_t a[2][4];
#pragma unroll
            for (int mt = 0; mt < 2; mt++) {
                int row = wm * 32 + mt * 16 + (lane & 15);
                uint32_t ad = aBase + SW128((uint32_t)(row * 128 + kb + ((lane >> 4) << 4)));
                LDSM_X4(a[mt][0], a[mt][1], a[mt][2], a[mt][3], ad);
            }

            uint32_t b[4][4];          // each x4 covers two n8 tiles
#pragma unroll
            for (int bt = 0; bt < 4; bt++) {
                int row = wn * 64 + bt * 16 + (lane & 7) + (((lane >> 4) & 1) << 3);
                uint32_t bd = bBase + SW128((uint32_t)(row * 128 + kb + (((lane >> 3) & 1) << 4)));
                LDSM_X4(b[bt][0], b[bt][1], b[bt][2], b[bt][3], bd);
            }

#pragma unroll
            for (int mt = 0; mt < 2; mt++)
#pragma unroll
                for (int nt = 0; nt < 8; nt++) {
                    int bt = nt >> 1, pr = (nt & 1) << 1;
                    MMA16816(d[mt][nt], a[mt], b[bt][pr], b[bt][pr + 1]);
                }
        }
    }

    // ---- epilogue ----
#pragma unroll
    for (int mt = 0; mt < 2; mt++) {
        int rbase = m0 + wm * 32 + mt * 16 + (lane >> 2);
#pragma unroll
        for (int nt = 0; nt < 8; nt++) {
            int f = n0 + wn * 64 + nt * 8 + (lane & 3) * 2;
#pragma unroll
            for (int half = 0; half < 2; half++) {
                int m = rbase + half * 8;
                float2 v = make_float2(d[mt][nt][half * 2], d[mt][nt][half * 2 + 1]);
                if (MODE == 0) {
                    int b_i = m >> 10, n = m & 1023;
                    int sec = f >> 10;
                    int h = (f >> 6) & 15, dd = f & 63;
                    float* dst = (sec == 0) ? g_Q : (sec == 1) ? g_K : g_V;
                    *(float2*)&dst[((size_t)(b_i * NHEAD + h) * NSEQ + n) * HD + dd] = v;
                } else {
                    v.x += bias[f];
                    v.y += bias[f + 1];
                    *(float2*)&C[(size_t)m * DIMC + f] = v;
                }
            }
        }
    }
}

// ============================================================================
// Fused causal flash attention with relative position term (fp32 SIMT).
// score[n,m] = (q[n].k[m] + q[n].Er[N-1-n+m]) * 0.125,  m <= n.
// ============================================================================
__global__ __launch_bounds__(256, 2)
void attn_kernel(const float* __restrict__ Er)
{
    extern __shared__ float smf[];
    float* Qs = smf;
    float* Ks = Qs + 64 * 68;
    float* Vs = Ks + 64 * 68;
    float* Ps = Vs + 64 * 68;
    float* Es = Ps + 64 * 68;

    const int tid = threadIdx.x;
    const int tx = tid & 15;
    const int ty = tid >> 4;
    const int bq = 15 - (int)blockIdx.x;
    const int bh = blockIdx.y;
    const int n0 = bq * 64;

    const float* Qg = g_Q + (size_t)bh * NSEQ * HD;
    const float* Kg = g_K + (size_t)bh * NSEQ * HD;
    const float* Vg = g_V + (size_t)bh * NSEQ * HD;

#pragma unroll
    for (int r = 0; r < 4; r++) {
        int lin = tid + r * 256;
        int i = lin >> 4, dc = (lin & 15) << 2;
        float4 v = *(const float4*)(Qg + (n0 + i) * HD + dc);
        Qs[(dc + 0) * 68 + i] = v.x;
        Qs[(dc + 1) * 68 + i] = v.y;
        Qs[(dc + 2) * 68 + i] = v.z;
        Qs[(dc + 3) * 68 + i] = v.w;
    }

    const float NEG_INF = __int_as_float(0xff800000);
    float m_i[4], l_i[4], o[4][4];
#pragma unroll
    for (int ii = 0; ii < 4; ii++) {
        m_i[ii] = NEG_INF; l_i[ii] = 0.0f;
#pragma unroll
        for (int dd = 0; dd < 4; dd++) o[ii][dd] = 0.0f;
    }

    const int tb = 60 + 4 * (tx - ty);

    for (int kt = 0; kt <= bq; kt++) {
        const int km0 = kt * 64;
        const int base = NSEQ - 64 - n0 + km0;

        __syncthreads();

#pragma unroll
        for (int r = 0; r < 4; r++) {
            int lin = tid + r * 256;
            int j = lin >> 4, dc = (lin & 15) << 2;
            float4 kv = *(const float4*)(Kg + (km0 + j) * HD + dc);
            Ks[(dc + 0) * 68 + j] = kv.x;
            Ks[(dc + 1) * 68 + j] = kv.y;
            Ks[(dc + 2) * 68 + j] = kv.z;
            Ks[(dc + 3) * 68 + j] = kv.w;
            float4 vv = *(const float4*)(Vg + (km0 + j) * HD + dc);
            *(float4*)&Vs[j * 68 + dc] = vv;
        }
#pragma unroll
        for (int r = 0; r < 8; r++) {
            int lin = tid + r * 256;
            if (lin < 127 * 16) {
                int t = lin >> 4, dc = (lin & 15) << 2;
                int e = base + t;
                float4 ev = (e < NSEQ) ? *(const float4*)(Er + e * HD + dc)
                                       : make_float4(0.f, 0.f, 0.f, 0.f);
                Es[(dc + 0) * 132 + t] = ev.x;
                Es[(dc + 1) * 132 + t] = ev.y;
                Es[(dc + 2) * 132 + t] = ev.z;
                Es[(dc + 3) * 132 + t] = ev.w;
            }
        }
        __syncthreads();

        float acc[4][4];
#pragma unroll
        for (int ii = 0; ii < 4; ii++)
#pragma unroll
            for (int jj = 0; jj < 4; jj++) acc[ii][jj] = 0.0f;

#pragma unroll 8
        for (int dd = 0; dd < 64; dd++) {
            float4 q4 = *(const float4*)&Qs[dd * 68 + 4 * ty];
            float4 k4 = *(const float4*)&Ks[dd * 68 + 4 * tx];
            float4 e0 = *(const float4*)&Es[dd * 132 + tb];
            float4 e1 = *(const float4*)&Es[dd * 132 + tb + 4];
            float q[4]  = {q4.x, q4.y, q4.z, q4.w};
            float kk[4] = {k4.x, k4.y, k4.z, k4.w};
            float e[8]  = {e0.x, e0.y, e0.z, e0.w, e1.x, e1.y, e1.z, e1.w};
#pragma unroll
            for (int ii = 0; ii < 4; ii++)
#pragma unroll
                for (int jj = 0; jj < 4; jj++) {
                    acc[ii][jj] += q[ii] * kk[jj];
                    acc[ii][jj] += q[ii] * e[jj - ii + 3];
                }
        }

        float s[4][4];
#pragma unroll
        for (int ii = 0; ii < 4; ii++)
#pragma unroll
            for (int jj = 0; jj < 4; jj++)
                s[ii][jj] = acc[ii][jj] * 0.125f;

        if (kt == bq) {
#pragma unroll
            for (int ii = 0; ii < 4; ii++)
#pragma unroll
                for (int jj = 0; jj < 4; jj++)
                    if (4 * tx + jj > 4 * ty + ii) s[ii][jj] = NEG_INF;
        }

#pragma unroll
        for (int ii = 0; ii < 4; ii++) {
            float tmax = fmaxf(fmaxf(s[ii][0], s[ii][1]), fmaxf(s[ii][2], s[ii][3]));
#pragma unroll
            for (int off = 8; off >= 1; off >>= 1)
                tmax = fmaxf(tmax, __shfl_xor_sync(0xffffffffu, tmax, off));
            float mnew  = fmaxf(m_i[ii], tmax);
            float alpha = __expf(m_i[ii] - mnew);
            float p0 = __expf(s[ii][0] - mnew);
            float p1 = __expf(s[ii][1] - mnew);
            float p2 = __expf(s[ii][2] - mnew);
            float p3 = __expf(s[ii][3] - mnew);
            float psum = (p0 + p1) + (p2 + p3);
#pragma unroll
            for (int off = 8; off >= 1; off >>= 1)
                psum += __shfl_xor_sync(0xffffffffu, psum, off);
            l_i[ii] = l_i[ii] * alpha + psum;
            m_i[ii] = mnew;
#pragma unroll
            for (int dd = 0; dd < 4; dd++) o[ii][dd] *= alpha;
            *(float4*)&Ps[(4 * ty + ii) * 68 + 4 * tx] = make_float4(p0, p1, p2, p3);
        }
        __syncthreads();

#pragma unroll 8
        for (int j = 0; j < 64; j++) {
            float4 v4 = *(const float4*)&Vs[j * 68 + 4 * tx];
#pragma unroll
            for (int ii = 0; ii < 4; ii++) {
                float p = Ps[(4 * ty + ii) * 68 + j];
                o[ii][0] += p * v4.x;
                o[ii][1] += p * v4.y;
                o[ii][2] += p * v4.z;
                o[ii][3] += p * v4.w;
            }
        }
    }

    const int b_i = bh >> 4, h = bh & 15;
#pragma unroll
    for (int ii = 0; ii < 4; ii++) {
        float inv = 1.0f / l_i[ii];
        float4 v = make_float4(o[ii][0] * inv, o[ii][1] * inv,
                               o[ii][2] * inv, o[ii][3] * inv);
        *(float4*)&g_attn[((size_t)b_i * NSEQ + (n0 + 4 * ty + ii)) * DIMC
                          + h * HD + 4 * tx] = v;
    }
}

// ============================================================================
extern "C" void kernel_launch(void* const* d_in, const int* in_sizes, int n_in,
                              void* d_out, int out_size)
{
    const float* x      = (const float*)d_in[0];
    const float* W_qkv  = (const float*)d_in[1];
    const float* W_proj = (const float*)d_in[2];
    const float* b_proj = (const float*)d_in[3];
    const float* Er     = (const float*)d_in[4];
    float* out = (float*)d_out;

    // 0) split fp32 -> bf16 hi/lo
    split_kernel<0><<<4096, 256>>>(x, 1048576);
    split_kernel<1><<<3072, 256>>>(W_qkv, 786432);
    split_kernel<2><<<1024, 256>>>(W_proj, 262144);

    // 1) QKV via HMMA: M=4096, N=3072 (double-buffered smem = 64 KB)
    const int gsmem = 2 * 32768;
    cudaFuncSetAttribute(hmma_gemm<0>,
                         cudaFuncAttributeMaxDynamicSharedMemorySize, gsmem);
    cudaFuncSetAttribute(hmma_gemm<1>,
                         cudaFuncAttributeMaxDynamicSharedMemorySize, gsmem);
    hmma_gemm<0><<<dim3(24, 32), 256, gsmem>>>(nullptr, nullptr);

    // 2) fused attention
    const int smem_bytes = (4 * 64 * 68 + 64 * 132) * (int)sizeof(float);
    cudaFuncSetAttribute(attn_kernel,
                         cudaFuncAttributeMaxDynamicSharedMemorySize, smem_bytes);
    attn_kernel<<<dim3(16, 64), 256, smem_bytes>>>(Er);

    // 3) split attention output, then proj via HMMA: M=4096, N=1024
    split_kernel<3><<<4096, 256>>>(nullptr, 1048576);
    hmma_gemm<1><<<dim3(8, 32), 256, gsmem>>>(b_proj, out);
}

// round 6
// speedup vs baseline: 2.3918x; 1.4448x over previous
#include <cuda_runtime.h>
#include <cuda_bf16.h>
#include <cstdint>

#define DIMC  1024
#define NSEQ  1024
#define BATCH 4
#define NHEAD 16
#define HD    64
#define BHTOT (BATCH*NHEAD)

// ---------------- scratch (device globals; no allocation at runtime) ----------
__device__ __nv_bfloat16 g_Qhi[(size_t)BHTOT*NSEQ*HD];
__device__ __nv_bfloat16 g_Qlo[(size_t)BHTOT*NSEQ*HD];
__device__ __nv_bfloat16 g_Khi[(size_t)BHTOT*NSEQ*HD];
__device__ __nv_bfloat16 g_Klo[(size_t)BHTOT*NSEQ*HD];
__device__ __nv_bfloat16 g_Vhi[(size_t)BHTOT*NSEQ*HD];
__device__ __nv_bfloat16 g_Vlo[(size_t)BHTOT*NSEQ*HD];

__device__ __nv_bfloat16 g_xhi[(size_t)BATCH*NSEQ*DIMC];
__device__ __nv_bfloat16 g_xlo[(size_t)BATCH*NSEQ*DIMC];
__device__ __nv_bfloat16 g_wqhi[(size_t)3*DIMC*DIMC];
__device__ __nv_bfloat16 g_wqlo[(size_t)3*DIMC*DIMC];
__device__ __nv_bfloat16 g_wphi[(size_t)DIMC*DIMC];
__device__ __nv_bfloat16 g_wplo[(size_t)DIMC*DIMC];
__device__ __nv_bfloat16 g_athi[(size_t)BATCH*NSEQ*DIMC];
__device__ __nv_bfloat16 g_atlo[(size_t)BATCH*NSEQ*DIMC];
__device__ __nv_bfloat16 g_erhi[(size_t)NSEQ*HD];
__device__ __nv_bfloat16 g_erlo[(size_t)NSEQ*HD];

// ---------------- helpers ------------------------------------------------------
__device__ __forceinline__ uint32_t smem_u32(const void* p) {
    uint32_t a;
    asm("{ .reg .u64 t; cvta.to.shared.u64 t, %1; cvt.u32.u64 %0, t; }"
        : "=r"(a) : "l"(p));
    return a;
}

__device__ __forceinline__ void cp_async16(uint32_t saddr, const void* gaddr) {
    asm volatile("cp.async.cg.shared.global [%0], [%1], 16;"
                 :: "r"(saddr), "l"(gaddr));
}
#define CP_COMMIT() asm volatile("cp.async.commit_group;" ::: "memory")
#define CP_WAIT(n)  asm volatile("cp.async.wait_group %0;" :: "n"(n) : "memory")

#define LDSM_X4(R0, R1, R2, R3, addr) \
    asm volatile("ldmatrix.sync.aligned.m8n8.x4.shared.b16 {%0,%1,%2,%3}, [%4];" \
                 : "=r"(R0), "=r"(R1), "=r"(R2), "=r"(R3) : "r"(addr))

#define MMA16816(d, a, b0, b1) \
    asm volatile("mma.sync.aligned.m16n8k16.row.col.f32.bf16.bf16.f32 " \
                 "{%0,%1,%2,%3}, {%4,%5,%6,%7}, {%8,%9}, {%0,%1,%2,%3};" \
                 : "+f"((d)[0]), "+f"((d)[1]), "+f"((d)[2]), "+f"((d)[3]) \
                 : "r"((a)[0]), "r"((a)[1]), "r"((a)[2]), "r"((a)[3]),   \
                   "r"(b0), "r"(b1))

// SW128 (Swizzle<3,4,3>) on byte offsets inside a 1024B-aligned tile
#define SW128(off) (((uint32_t)(off)) ^ ((((uint32_t)(off)) >> 3) & 0x70))

// ============================================================================
// Split fp32 -> bf16 hi/lo.  WHICH: 0=x, 1=W_qkv, 2=W_proj, 4=Er
// ============================================================================
template<int WHICH>
__global__ void split_kernel(const float* __restrict__ src, int n4)
{
    int i = blockIdx.x * blockDim.x + threadIdx.x;
    if (i >= n4) return;
    __nv_bfloat16* hi = (WHICH == 0) ? g_xhi : (WHICH == 1) ? g_wqhi
                      : (WHICH == 2) ? g_wphi : g_erhi;
    __nv_bfloat16* lo = (WHICH == 0) ? g_xlo : (WHICH == 1) ? g_wqlo
                      : (WHICH == 2) ? g_wplo : g_erlo;
    float4 v = ((const float4*)src)[i];
    __nv_bfloat16 h0 = __float2bfloat16(v.x);
    __nv_bfloat16 h1 = __float2bfloat16(v.y);
    __nv_bfloat16 h2 = __float2bfloat16(v.z);
    __nv_bfloat16 h3 = __float2bfloat16(v.w);
    __nv_bfloat16 l0 = __float2bfloat16(v.x - __bfloat162float(h0));
    __nv_bfloat16 l1 = __float2bfloat16(v.y - __bfloat162float(h1));
    __nv_bfloat16 l2 = __float2bfloat16(v.z - __bfloat162float(h2));
    __nv_bfloat16 l3 = __float2bfloat16(v.w - __bfloat162float(h3));
    ((__nv_bfloat162*)hi)[2*i]   = __nv_bfloat162(h0, h1);
    ((__nv_bfloat162*)hi)[2*i+1] = __nv_bfloat162(h2, h3);
    ((__nv_bfloat162*)lo)[2*i]   = __nv_bfloat162(l0, l1);
    ((__nv_bfloat162*)lo)[2*i+1] = __nv_bfloat162(l2, l3);
}

// ============================================================================
// HMMA split-precision GEMM.  C = A(M,1024) * B(Nc,1024)^T.
// MODE 0: QKV -> write bf16 hi/lo into g_{Q,K,V}{hi,lo} [bh][n][d].
// MODE 1: proj (A=g_at*, B=g_wp*), +bias, fp32 row-major out.
// ============================================================================
#define NSTAGES 48

template<int MODE>
__global__ __launch_bounds__(256)
void hmma_gemm(const float* __restrict__ bias, float* __restrict__ C)
{
    extern __shared__ char dynsm[];
    const uint32_t sbase = smem_u32(dynsm);

    const int tid  = threadIdx.x;
    const int wid  = tid >> 5;
    const int lane = tid & 31;
    const int wm = wid & 3;
    const int wn = wid >> 2;
    const int m0 = blockIdx.y * 128;
    const int n0 = blockIdx.x * 128;

    const __nv_bfloat16* Ahi = (MODE == 0) ? g_xhi : g_athi;
    const __nv_bfloat16* Alo = (MODE == 0) ? g_xlo : g_atlo;
    const __nv_bfloat16* Bhi = (MODE == 0) ? g_wqhi : g_wphi;
    const __nv_bfloat16* Blo = (MODE == 0) ? g_wqlo : g_wplo;

    float d[2][8][4];
#pragma unroll
    for (int mt = 0; mt < 2; mt++)
#pragma unroll
        for (int nt = 0; nt < 8; nt++)
#pragma unroll
            for (int r = 0; r < 4; r++) d[mt][nt][r] = 0.0f;

    auto issue_stage = [&](int s) {
        const __nv_bfloat16* aS = (s < 32) ? Ahi : Alo;
        const __nv_bfloat16* bS = (s >= 16 && s < 32) ? Blo : Bhi;
        const int kin = (s & 15) * 64;
        const uint32_t stbase = sbase + (uint32_t)(s & 1) * 32768u;
#pragma unroll
        for (int t = 0; t < 8; t++) {
            int c   = tid + t * 256;
            int op  = c >> 10;
            int row = (c >> 3) & 127;
            int seg = c & 7;
            const __nv_bfloat16* src = op ? bS : aS;
            int r0 = op ? n0 : m0;
            const void* g = src + (size_t)(r0 + row) * 1024 + kin + seg * 8;
            uint32_t sa = stbase + (op ? 16384u : 0u)
                        + SW128((uint32_t)(row * 128 + seg * 16));
            cp_async16(sa, g);
        }
    };

    issue_stage(0);
    CP_COMMIT();

    for (int s = 0; s < NSTAGES; s++) {
        __syncthreads();
        if (s + 1 < NSTAGES) {
            issue_stage(s + 1);
            CP_COMMIT();
            CP_WAIT(1);
        } else {
            CP_WAIT(0);
        }
        __syncthreads();

        const uint32_t aBase = sbase + (uint32_t)(s & 1) * 32768u;
        const uint32_t bBase = aBase + 16384u;

#pragma unroll
        for (int ks = 0; ks < 4; ks++) {
            const int kb = ks * 32;
            uint32_t a[2][4];
#pragma unroll
            for (int mt = 0; mt < 2; mt++) {
                int row = wm * 32 + mt * 16 + (lane & 15);
                uint32_t ad = aBase + SW128((uint32_t)(row * 128 + kb + ((lane >> 4) << 4)));
                LDSM_X4(a[mt][0], a[mt][1], a[mt][2], a[mt][3], ad);
            }
            uint32_t b[4][4];
#pragma unroll
            for (int bt = 0; bt < 4; bt++) {
                int row = wn * 64 + bt * 16 + (lane & 7) + (((lane >> 4) & 1) << 3);
                uint32_t bd = bBase + SW128((uint32_t)(row * 128 + kb + (((lane >> 3) & 1) << 4)));
                LDSM_X4(b[bt][0], b[bt][1], b[bt][2], b[bt][3], bd);
            }
#pragma unroll
            for (int mt = 0; mt < 2; mt++)
#pragma unroll
                for (int nt = 0; nt < 8; nt++) {
                    int bt = nt >> 1, pr = (nt & 1) << 1;
                    MMA16816(d[mt][nt], a[mt], b[bt][pr], b[bt][pr + 1]);
                }
        }
    }

    // ---- epilogue ----
#pragma unroll
    for (int mt = 0; mt < 2; mt++) {
        int rbase = m0 + wm * 32 + mt * 16 + (lane >> 2);
#pragma unroll
        for (int nt = 0; nt < 8; nt++) {
            int f = n0 + wn * 64 + nt * 8 + (lane & 3) * 2;
#pragma unroll
            for (int half = 0; half < 2; half++) {
                int m = rbase + half * 8;
                float2 v = make_float2(d[mt][nt][half * 2], d[mt][nt][half * 2 + 1]);
                if (MODE == 0) {
                    int b_i = m >> 10, n = m & 1023;
                    int sec = f >> 10;
                    int hh = (f >> 6) & 15, dd = f & 63;
                    size_t idx = ((size_t)(b_i * NHEAD + hh) * NSEQ + n) * HD + dd;
                    __nv_bfloat16* dhi = (sec == 0) ? g_Qhi : (sec == 1) ? g_Khi : g_Vhi;
                    __nv_bfloat16* dlo = (sec == 0) ? g_Qlo : (sec == 1) ? g_Klo : g_Vlo;
                    __nv_bfloat16 h0 = __float2bfloat16(v.x);
                    __nv_bfloat16 h1 = __float2bfloat16(v.y);
                    __nv_bfloat16 l0 = __float2bfloat16(v.x - __bfloat162float(h0));
                    __nv_bfloat16 l1 = __float2bfloat16(v.y - __bfloat162float(h1));
                    *(__nv_bfloat162*)&dhi[idx] = __nv_bfloat162(h0, h1);
                    *(__nv_bfloat162*)&dlo[idx] = __nv_bfloat162(l0, l1);
                } else {
                    v.x += bias[f];
                    v.y += bias[f + 1];
                    *(float2*)&C[(size_t)m * DIMC + f] = v;
                }
            }
        }
    }
}

// ============================================================================
// Tensor-core fused causal flash attention with relative position term.
// q-block 128, key tile 64, 8 warps (16 rows each, full-row ownership).
// score[n,m] = (q.k + q.Er[N-1-n+m]) * 0.125. Split-bf16 3-pass everywhere.
// ============================================================================
#define OFF_QHI  0u
#define OFF_QLO  16384u
#define OFF_KHI  32768u
#define OFF_KLO  40960u
#define OFF_EHI  49152u
#define OFF_ELO  73728u
#define OFF_VTHI 98304u
#define OFF_VTLO 106496u
#define OFF_PHI  114688u
#define OFF_PLO  131072u
#define OFF_R    147456u
#define ATTN_SMEM 190464

__global__ __launch_bounds__(256)
void attn_kernel()
{
    extern __shared__ char smc[];
    const uint32_t sb = smem_u32(smc);
    const int tid  = threadIdx.x;
    const int w    = tid >> 5;
    const int lane = tid & 31;
    const int bq = 7 - (int)blockIdx.x;     // heavy blocks first
    const int bh = blockIdx.y;
    const int n0 = bq * 128;

    const size_t bho = (size_t)bh * NSEQ * HD;
    const __nv_bfloat16* Qhi = g_Qhi + bho;
    const __nv_bfloat16* Qlo = g_Qlo + bho;
    const __nv_bfloat16* Khi = g_Khi + bho;
    const __nv_bfloat16* Klo = g_Klo + bho;
    const __nv_bfloat16* Vhi = g_Vhi + bho;
    const __nv_bfloat16* Vlo = g_Vlo + bho;

    // ---- load Q (128 rows hi + 128 rows lo), cp.async ----
#pragma unroll
    for (int t = 0; t < 8; t++) {
        int c = tid + t * 256;
        int buf = c >> 10;
        int row = (c >> 3) & 127;
        int seg = c & 7;
        const __nv_bfloat16* src = buf ? Qlo : Qhi;
        cp_async16(sb + (buf ? OFF_QLO : OFF_QHI) + SW128(row * 128 + seg * 16),
                   src + (size_t)(n0 + row) * HD + seg * 8);
    }

    auto issueKE = [&](int kt) {
        const int km0 = kt * 64;
        const int base = NSEQ - 128 - n0 + km0;
        // K: 64 rows hi + 64 lo
#pragma unroll
        for (int t = 0; t < 4; t++) {
            int c = tid + t * 256;
            int buf = c >> 9;
            int row = (c >> 3) & 63;
            int seg = c & 7;
            const __nv_bfloat16* src = buf ? Klo : Khi;
            cp_async16(sb + (buf ? OFF_KLO : OFF_KHI) + SW128(row * 128 + seg * 16),
                       src + (size_t)(km0 + row) * HD + seg * 8);
        }
        // E band: 192 rows hi + 192 lo (zero-fill e >= NSEQ)
#pragma unroll
        for (int t = 0; t < 12; t++) {
            int c = tid + t * 256;
            int buf = (c >= 1536) ? 1 : 0;
            int cc = c - buf * 1536;
            int row = cc >> 3;
            int seg = cc & 7;
            int e = base + row;
            uint32_t off = (buf ? OFF_ELO : OFF_EHI) + SW128(row * 128 + seg * 16);
            if (e < NSEQ) {
                const __nv_bfloat16* src = buf ? g_erlo : g_erhi;
                cp_async16(sb + off, src + (size_t)e * HD + seg * 8);
            } else {
                *(uint4*)(smc + off) = make_uint4(0u, 0u, 0u, 0u);
            }
        }
    };

    issueKE(0);
    CP_COMMIT();

    float mrow[2] = {-1e30f, -1e30f};
    float lrow[2] = {0.0f, 0.0f};
    float O[8][4];
#pragma unroll
    for (int nt = 0; nt < 8; nt++)
#pragma unroll
        for (int r = 0; r < 4; r++) O[nt][r] = 0.0f;

    const int t0w = 112 - 16 * w;
    const int ktmax = 2 * bq + 1;

    for (int kt = 0; kt <= ktmax; kt++) {
        const int km0 = kt * 64;
        __syncthreads();    // prev PV reads of sVt/sP done

        // ---- V load + transpose into sVt[d][j] ----
#pragma unroll
        for (int t = 0; t < 4; t++) {
            int c = tid + t * 256;
            int buf = c >> 9;
            int j = (c >> 3) & 63;
            int seg = c & 7;
            const __nv_bfloat16* src = buf ? Vlo : Vhi;
            uint4 u = *(const uint4*)(src + (size_t)(km0 + j) * HD + seg * 8);
            const __nv_bfloat16* pv = (const __nv_bfloat16*)&u;
            uint32_t vb = buf ? OFF_VTLO : OFF_VTHI;
#pragma unroll
            for (int m2 = 0; m2 < 8; m2++) {
                int dd = seg * 8 + m2;
                *(__nv_bfloat16*)(smc + vb + SW128(dd * 128 + j * 2)) = pv[m2];
            }
        }
        CP_WAIT(0);
        __syncthreads();    // K/E (+Q on first iter) and V visible

        // ---- S = Q.K^T (n=64) and R = Q.E_band^T (n=80, warp-private band) ----
        float S[8][4], R[10][4];
#pragma unroll
        for (int nt = 0; nt < 8; nt++)
#pragma unroll
            for (int r = 0; r < 4; r++) S[nt][r] = 0.0f;
#pragma unroll
        for (int nt = 0; nt < 10; nt++)
#pragma unroll
            for (int r = 0; r < 4; r++) R[nt][r] = 0.0f;

#pragma unroll
        for (int seg3 = 0; seg3 < 3; seg3++) {
            const uint32_t aB = sb + (seg3 == 1 ? OFF_QLO : OFF_QHI);
            const uint32_t kB = sb + (seg3 == 2 ? OFF_KLO : OFF_KHI);
            const uint32_t eB = sb + (seg3 == 2 ? OFF_ELO : OFF_EHI);
#pragma unroll
            for (int ks = 0; ks < 4; ks++) {
                const int kb = ks * 32;
                uint32_t a[4];
                {
                    int row = 16 * w + (lane & 15);
                    uint32_t ad = aB + SW128(row * 128 + kb + ((lane >> 4) << 4));
                    LDSM_X4(a[0], a[1], a[2], a[3], ad);
                }
                uint32_t bk[4][4];
#pragma unroll
                for (int bt = 0; bt < 4; bt++) {
                    int row = bt * 16 + (lane & 7) + (((lane >> 4) & 1) << 3);
                    uint32_t bd = kB + SW128(row * 128 + kb + (((lane >> 3) & 1) << 4));
                    LDSM_X4(bk[bt][0], bk[bt][1], bk[bt][2], bk[bt][3], bd);
                }
                uint32_t be[5][4];
#pragma unroll
                for (int bt = 0; bt < 5; bt++) {
                    int row = t0w + bt * 16 + (lane & 7) + (((lane >> 4) & 1) << 3);
                    uint32_t bd = eB + SW128(row * 128 + kb + (((lane >> 3) & 1) << 4));
                    LDSM_X4(be[bt][0], be[bt][1], be[bt][2], be[bt][3], bd);
                }
#pragma unroll
                for (int nt = 0; nt < 8; nt++) {
                    int bt = nt >> 1, pr = (nt & 1) << 1;
                    MMA16816(S[nt], a, bk[bt][pr], bk[bt][pr + 1]);
                }
#pragma unroll
                for (int nt = 0; nt < 10; nt++) {
                    int bt = nt >> 1, pr = (nt & 1) << 1;
                    MMA16816(R[nt], a, be[bt][pr], be[bt][pr + 1]);
                }
            }
        }

        // ---- store R (warp-private region), gather diagonal, scale, mask ----
        float* sR = (float*)(smc + OFF_R) + w * 16 * 84;
        {
            int r0 = lane >> 2;
#pragma unroll
            for (int nt = 0; nt < 10; nt++) {
                int col = nt * 8 + (lane & 3) * 2;
                *(float2*)&sR[r0 * 84 + col]       = make_float2(R[nt][0], R[nt][1]);
                *(float2*)&sR[(r0 + 8) * 84 + col] = make_float2(R[nt][2], R[nt][3]);
            }
        }
        __syncwarp();

        const bool maskt = (kt >= 2 * bq);
#pragma unroll
        for (int nt = 0; nt < 8; nt++) {
            int j0 = nt * 8 + (lane & 3) * 2;
#pragma unroll
            for (int h = 0; h < 2; h++) {
                int il = (lane >> 2) + 8 * h;
                int col = 15 + j0 - il;
                float s0 = (S[nt][2 * h]     + sR[il * 84 + col])     * 0.125f;
                float s1 = (S[nt][2 * h + 1] + sR[il * 84 + col + 1]) * 0.125f;
                if (maskt) {
                    int ig = n0 + 16 * w + il;
                    int jg = km0 + j0;
                    if (jg > ig)     s0 = -1e30f;
                    if (jg + 1 > ig) s1 = -1e30f;
                }
                S[nt][2 * h]     = s0;
                S[nt][2 * h + 1] = s1;
            }
        }

        // ---- online softmax (rows warp-local; quad = 4 lanes per row) ----
        float alpha[2];
#pragma unroll
        for (int h = 0; h < 2; h++) {
            float v = -1e30f;
#pragma unroll
            for (int nt = 0; nt < 8; nt++)
                v = fmaxf(v, fmaxf(S[nt][2 * h], S[nt][2 * h + 1]));
            v = fmaxf(v, __shfl_xor_sync(0xffffffffu, v, 1));
            v = fmaxf(v, __shfl_xor_sync(0xffffffffu, v, 2));
            float mnew = fmaxf(mrow[h], v);
            alpha[h] = __expf(mrow[h] - mnew);
            mrow[h] = mnew;
        }
        float rsum[2] = {0.0f, 0.0f};
#pragma unroll
        for (int nt = 0; nt < 8; nt++)
#pragma unroll
            for (int h = 0; h < 2; h++) {
                float p0 = __expf(S[nt][2 * h]     - mrow[h]);
                float p1 = __expf(S[nt][2 * h + 1] - mrow[h]);
                S[nt][2 * h] = p0; S[nt][2 * h + 1] = p1;
                rsum[h] += p0 + p1;
            }
#pragma unroll
        for (int h = 0; h < 2; h++) {
            rsum[h] += __shfl_xor_sync(0xffffffffu, rsum[h], 1);
            rsum[h] += __shfl_xor_sync(0xffffffffu, rsum[h], 2);
            lrow[h] = lrow[h] * alpha[h] + rsum[h];
        }
#pragma unroll
        for (int nt = 0; nt < 8; nt++) {
            O[nt][0] *= alpha[0]; O[nt][1] *= alpha[0];
            O[nt][2] *= alpha[1]; O[nt][3] *= alpha[1];
        }

        // ---- split P -> bf16 hi/lo into warp-local rows of sP ----
#pragma unroll
        for (int nt = 0; nt < 8; nt++) {
            int colb = (nt * 8 + (lane & 3) * 2) * 2;
#pragma unroll
            for (int h = 0; h < 2; h++) {
                int row = 16 * w + (lane >> 2) + 8 * h;
                float p0 = S[nt][2 * h], p1 = S[nt][2 * h + 1];
                __nv_bfloat16 h0 = __float2bfloat16(p0);
                __nv_bfloat16 h1 = __float2bfloat16(p1);
                __nv_bfloat16 l0 = __float2bfloat16(p0 - __bfloat162float(h0));
                __nv_bfloat16 l1 = __float2bfloat16(p1 - __bfloat162float(h1));
                *(__nv_bfloat162*)(smc + OFF_PHI + SW128(row * 128 + colb)) =
                    __nv_bfloat162(h0, h1);
                *(__nv_bfloat162*)(smc + OFF_PLO + SW128(row * 128 + colb)) =
                    __nv_bfloat162(l0, l1);
            }
        }
        __syncwarp();
        __syncthreads();      // all warps done reading K/E -> safe to prefetch

        if (kt < ktmax) { issueKE(kt + 1); CP_COMMIT(); }

        // ---- O += P.V  (split 3-pass) ----
#pragma unroll
        for (int seg3 = 0; seg3 < 3; seg3++) {
            const uint32_t aB = sb + (seg3 == 1 ? OFF_PLO : OFF_PHI);
            const uint32_t vB = sb + (seg3 == 2 ? OFF_VTLO : OFF_VTHI);
#pragma unroll
            for (int ks = 0; ks < 4; ks++) {
                const int kb = ks * 32;
                uint32_t a[4];
                {
                    int row = 16 * w + (lane & 15);
                    uint32_t ad = aB + SW128(row * 128 + kb + ((lane >> 4) << 4));
                    LDSM_X4(a[0], a[1], a[2], a[3], ad);
                }
                uint32_t bv[4][4];
#pragma unroll
                for (int bt = 0; bt < 4; bt++) {
                    int row = bt * 16 + (lane & 7) + (((lane >> 4) & 1) << 3);
                    uint32_t bd = vB + SW128(row * 128 + kb + (((lane >> 3) & 1) << 4));
                    LDSM_X4(bv[bt][0], bv[bt][1], bv[bt][2], bv[bt][3], bd);
                }
#pragma unroll
                for (int nt = 0; nt < 8; nt++) {
                    int bt = nt >> 1, pr = (nt & 1) << 1;
                    MMA16816(O[nt], a, bv[bt][pr], bv[bt][pr + 1]);
                }
            }
        }
    }

    // ---- epilogue: O /= l, split bf16 hi/lo -> g_at{hi,lo}[b][n][h*64+d] ----
    const int b_i = bh >> 4, hhead = bh & 15;
    float inv[2] = {1.0f / lrow[0], 1.0f / lrow[1]};
#pragma unroll
    for (int nt = 0; nt < 8; nt++) {
        int c = hhead * 64 + nt * 8 + (lane & 3) * 2;
#pragma unroll
        for (int h = 0; h < 2; h++) {
            int n = n0 + 16 * w + (lane >> 2) + 8 * h;
            float o0 = O[nt][2 * h] * inv[h];
            float o1 = O[nt][2 * h + 1] * inv[h];
            __nv_bfloat16 h0 = __float2bfloat16(o0);
            __nv_bfloat16 h1 = __float2bfloat16(o1);
            __nv_bfloat16 l0 = __float2bfloat16(o0 - __bfloat162float(h0));
            __nv_bfloat16 l1 = __float2bfloat16(o1 - __bfloat162float(h1));
            size_t idx = ((size_t)b_i * NSEQ + n) * DIMC + c;
            *(__nv_bfloat162*)&g_athi[idx] = __nv_bfloat162(h0, h1);
            *(__nv_bfloat162*)&g_atlo[idx] = __nv_bfloat162(l0, l1);
        }
    }
}

// ============================================================================
extern "C" void kernel_launch(void* const* d_in, const int* in_sizes, int n_in,
                              void* d_out, int out_size)
{
    const float* x      = (const float*)d_in[0];
    const float* W_qkv  = (const float*)d_in[1];
    const float* W_proj = (const float*)d_in[2];
    const float* b_proj = (const float*)d_in[3];
    const float* Er     = (const float*)d_in[4];
    float* out = (float*)d_out;

    // 0) split fp32 -> bf16 hi/lo
    split_kernel<0><<<4096, 256>>>(x, 1048576);
    split_kernel<1><<<3072, 256>>>(W_qkv, 786432);
    split_kernel<2><<<1024, 256>>>(W_proj, 262144);
    split_kernel<4><<<64, 256>>>(Er, 16384);

    // 1) QKV via HMMA: M=4096, N=3072 -> bf16 hi/lo Q/K/V
    const int gsmem = 2 * 32768;
    cudaFuncSetAttribute(hmma_gemm<0>,
                         cudaFuncAttributeMaxDynamicSharedMemorySize, gsmem);
    cudaFuncSetAttribute(hmma_gemm<1>,
                         cudaFuncAttributeMaxDynamicSharedMemorySize, gsmem);
    hmma_gemm<0><<<dim3(24, 32), 256, gsmem>>>(nullptr, nullptr);

    // 2) tensor-core fused attention (8 q-blocks x 64 bh)
    cudaFuncSetAttribute(attn_kernel,
                         cudaFuncAttributeMaxDynamicSharedMemorySize, ATTN_SMEM);
    attn_kernel<<<dim3(8, 64), 256, ATTN_SMEM>>>();

    // 3) proj via HMMA: M=4096, N=1024, +bias
    hmma_gemm<1><<<dim3(8, 32), 256, gsmem>>>(b_proj, out);
}

// round 7
// speedup vs baseline: 2.4119x; 1.0084x over previous
#include <cuda_runtime.h>
#include <cuda_bf16.h>
#include <cstdint>

#define DIMC  1024
#define NSEQ  1024
#define BATCH 4
#define NHEAD 16
#define HD    64
#define BHTOT (BATCH*NHEAD)

// ---------------- scratch (device globals; no allocation at runtime) ----------
__device__ __nv_bfloat16 g_Qhi[(size_t)BHTOT*NSEQ*HD];
__device__ __nv_bfloat16 g_Qlo[(size_t)BHTOT*NSEQ*HD];
__device__ __nv_bfloat16 g_Khi[(size_t)BHTOT*NSEQ*HD];
__device__ __nv_bfloat16 g_Klo[(size_t)BHTOT*NSEQ*HD];
__device__ __nv_bfloat16 g_Vhi[(size_t)BHTOT*NSEQ*HD];
__device__ __nv_bfloat16 g_Vlo[(size_t)BHTOT*NSEQ*HD];

__device__ __nv_bfloat16 g_xhi[(size_t)BATCH*NSEQ*DIMC];
__device__ __nv_bfloat16 g_xlo[(size_t)BATCH*NSEQ*DIMC];
__device__ __nv_bfloat16 g_wqhi[(size_t)3*DIMC*DIMC];
__device__ __nv_bfloat16 g_wqlo[(size_t)3*DIMC*DIMC];
__device__ __nv_bfloat16 g_wphi[(size_t)DIMC*DIMC];
__device__ __nv_bfloat16 g_wplo[(size_t)DIMC*DIMC];
__device__ __nv_bfloat16 g_athi[(size_t)BATCH*NSEQ*DIMC];
__device__ __nv_bfloat16 g_atlo[(size_t)BATCH*NSEQ*DIMC];
__device__ __nv_bfloat16 g_erhi[(size_t)NSEQ*HD];
__device__ __nv_bfloat16 g_erlo[(size_t)NSEQ*HD];

// ---------------- helpers ------------------------------------------------------
__device__ __forceinline__ uint32_t smem_u32(const void* p) {
    uint32_t a;
    asm("{ .reg .u64 t; cvta.to.shared.u64 t, %1; cvt.u32.u64 %0, t; }"
        : "=r"(a) : "l"(p));
    return a;
}

__device__ __forceinline__ void cp_async16(uint32_t saddr, const void* gaddr) {
    asm volatile("cp.async.cg.shared.global [%0], [%1], 16;"
                 :: "r"(saddr), "l"(gaddr));
}
#define CP_COMMIT() asm volatile("cp.async.commit_group;" ::: "memory")
#define CP_WAIT(n)  asm volatile("cp.async.wait_group %0;" :: "n"(n) : "memory")

#define LDSM_X4(R0, R1, R2, R3, addr) \
    asm volatile("ldmatrix.sync.aligned.m8n8.x4.shared.b16 {%0,%1,%2,%3}, [%4];" \
                 : "=r"(R0), "=r"(R1), "=r"(R2), "=r"(R3) : "r"(addr))

#define LDSM_X4T(R0, R1, R2, R3, addr) \
    asm volatile("ldmatrix.sync.aligned.m8n8.x4.trans.shared.b16 {%0,%1,%2,%3}, [%4];" \
                 : "=r"(R0), "=r"(R1), "=r"(R2), "=r"(R3) : "r"(addr))

#define MMA16816(d, a, b0, b1) \
    asm volatile("mma.sync.aligned.m16n8k16.row.col.f32.bf16.bf16.f32 " \
                 "{%0,%1,%2,%3}, {%4,%5,%6,%7}, {%8,%9}, {%0,%1,%2,%3};" \
                 : "+f"((d)[0]), "+f"((d)[1]), "+f"((d)[2]), "+f"((d)[3]) \
                 : "r"((a)[0]), "r"((a)[1]), "r"((a)[2]), "r"((a)[3]),   \
                   "r"(b0), "r"(b1))

// SW128 (Swizzle<3,4,3>) on byte offsets inside a 1024B-aligned tile
#define SW128(off) (((uint32_t)(off)) ^ ((((uint32_t)(off)) >> 3) & 0x70))

// ============================================================================
// Combined split fp32 -> bf16 hi/lo for x, W_qkv, W_proj, Er (one launch).
// ============================================================================
#define NX4  1048576
#define NWQ4 786432
#define NWP4 262144
#define NER4 16384
#define NSPLIT4 (NX4 + NWQ4 + NWP4 + NER4)

__global__ void split_all(const float* __restrict__ x, const float* __restrict__ wq,
                          const float* __restrict__ wp, const float* __restrict__ er)
{
    int i = blockIdx.x * blockDim.x + threadIdx.x;
    const float* src;
    __nv_bfloat16 *hi, *lo;
    int j;
    if (i < NX4)                    { src = x;  hi = g_xhi;  lo = g_xlo;  j = i; }
    else if (i < NX4 + NWQ4)        { src = wq; hi = g_wqhi; lo = g_wqlo; j = i - NX4; }
    else if (i < NX4 + NWQ4 + NWP4) { src = wp; hi = g_wphi; lo = g_wplo; j = i - NX4 - NWQ4; }
    else if (i < NSPLIT4)           { src = er; hi = g_erhi; lo = g_erlo; j = i - NX4 - NWQ4 - NWP4; }
    else return;

    float4 v = ((const float4*)src)[j];
    __nv_bfloat16 h0 = __float2bfloat16(v.x);
    __nv_bfloat16 h1 = __float2bfloat16(v.y);
    __nv_bfloat16 h2 = __float2bfloat16(v.z);
    __nv_bfloat16 h3 = __float2bfloat16(v.w);
    __nv_bfloat16 l0 = __float2bfloat16(v.x - __bfloat162float(h0));
    __nv_bfloat16 l1 = __float2bfloat16(v.y - __bfloat162float(h1));
    __nv_bfloat16 l2 = __float2bfloat16(v.z - __bfloat162float(h2));
    __nv_bfloat16 l3 = __float2bfloat16(v.w - __bfloat162float(h3));
    ((__nv_bfloat162*)hi)[2*j]   = __nv_bfloat162(h0, h1);
    ((__nv_bfloat162*)hi)[2*j+1] = __nv_bfloat162(h2, h3);
    ((__nv_bfloat162*)lo)[2*j]   = __nv_bfloat162(l0, l1);
    ((__nv_bfloat162*)lo)[2*j+1] = __nv_bfloat162(l2, l3);
}

// ============================================================================
// HMMA split-precision GEMM, 3-stage cp.async pipeline.
// C = A(M,1024)*B(Nc,1024)^T.  Virtual K = 3x1024.
// MODE 0: QKV -> bf16 hi/lo into g_{Q,K,V}{hi,lo}.   MODE 1: proj +bias fp32.
// ============================================================================
#define NSTAGES 48

template<int MODE>
__global__ __launch_bounds__(256)
void hmma_gemm(const float* __restrict__ bias, float* __restrict__ C)
{
    extern __shared__ char dynsm[];
    const uint32_t sbase = smem_u32(dynsm);

    const int tid  = threadIdx.x;
    const int wid  = tid >> 5;
    const int lane = tid & 31;
    const int wm = wid & 3;
    const int wn = wid >> 2;
    const int m0 = blockIdx.y * 128;
    const int n0 = blockIdx.x * 128;

    const __nv_bfloat16* Ahi = (MODE == 0) ? g_xhi : g_athi;
    const __nv_bfloat16* Alo = (MODE == 0) ? g_xlo : g_atlo;
    const __nv_bfloat16* Bhi = (MODE == 0) ? g_wqhi : g_wphi;
    const __nv_bfloat16* Blo = (MODE == 0) ? g_wqlo : g_wplo;

    float d[2][8][4];
#pragma unroll
    for (int mt = 0; mt < 2; mt++)
#pragma unroll
        for (int nt = 0; nt < 8; nt++)
#pragma unroll
            for (int r = 0; r < 4; r++) d[mt][nt][r] = 0.0f;

    auto issue_stage = [&](int s) {
        const __nv_bfloat16* aS = (s < 32) ? Ahi : Alo;
        const __nv_bfloat16* bS = (s >= 16 && s < 32) ? Blo : Bhi;
        const int kin = (s & 15) * 64;
        const uint32_t stbase = sbase + (uint32_t)(s % 3) * 32768u;
#pragma unroll
        for (int t = 0; t < 8; t++) {
            int c   = tid + t * 256;
            int op  = c >> 10;
            int row = (c >> 3) & 127;
            int seg = c & 7;
            const __nv_bfloat16* src = op ? bS : aS;
            int r0 = op ? n0 : m0;
            const void* g = src + (size_t)(r0 + row) * 1024 + kin + seg * 8;
            uint32_t sa = stbase + (op ? 16384u : 0u)
                        + SW128((uint32_t)(row * 128 + seg * 16));
            cp_async16(sa, g);
        }
    };

    issue_stage(0); CP_COMMIT();
    issue_stage(1); CP_COMMIT();

    for (int s = 0; s < NSTAGES; s++) {
        if (s == NSTAGES - 1) { CP_WAIT(0); } else { CP_WAIT(1); }
        __syncthreads();
        if (s + 2 < NSTAGES) { issue_stage(s + 2); CP_COMMIT(); }

        const uint32_t aBase = sbase + (uint32_t)(s % 3) * 32768u;
        const uint32_t bBase = aBase + 16384u;

#pragma unroll
        for (int ks = 0; ks < 4; ks++) {
            const int kb = ks * 32;
            uint32_t a[2][4];
#pragma unroll
            for (int mt = 0; mt < 2; mt++) {
                int row = wm * 32 + mt * 16 + (lane & 15);
                uint32_t ad = aBase + SW128((uint32_t)(row * 128 + kb + ((lane >> 4) << 4)));
                LDSM_X4(a[mt][0], a[mt][1], a[mt][2], a[mt][3], ad);
            }
            uint32_t b[4][4];
#pragma unroll
            for (int bt = 0; bt < 4; bt++) {
                int row = wn * 64 + bt * 16 + (lane & 7) + (((lane >> 4) & 1) << 3);
                uint32_t bd = bBase + SW128((uint32_t)(row * 128 + kb + (((lane >> 3) & 1) << 4)));
                LDSM_X4(b[bt][0], b[bt][1], b[bt][2], b[bt][3], bd);
            }
#pragma unroll
            for (int mt = 0; mt < 2; mt++)
#pragma unroll
                for (int nt = 0; nt < 8; nt++) {
                    int bt = nt >> 1, pr = (nt & 1) << 1;
                    MMA16816(d[mt][nt], a[mt], b[bt][pr], b[bt][pr + 1]);
                }
        }
        __syncthreads();
    }

    // ---- epilogue ----
#pragma unroll
    for (int mt = 0; mt < 2; mt++) {
        int rbase = m0 + wm * 32 + mt * 16 + (lane >> 2);
#pragma unroll
        for (int nt = 0; nt < 8; nt++) {
            int f = n0 + wn * 64 + nt * 8 + (lane & 3) * 2;
#pragma unroll
            for (int half = 0; half < 2; half++) {
                int m = rbase + half * 8;
                float2 v = make_float2(d[mt][nt][half * 2], d[mt][nt][half * 2 + 1]);
                if (MODE == 0) {
                    int b_i = m >> 10, n = m & 1023;
                    int sec = f >> 10;
                    int hh = (f >> 6) & 15, dd = f & 63;
                    size_t idx = ((size_t)(b_i * NHEAD + hh) * NSEQ + n) * HD + dd;
                    __nv_bfloat16* dhi = (sec == 0) ? g_Qhi : (sec == 1) ? g_Khi : g_Vhi;
                    __nv_bfloat16* dlo = (sec == 0) ? g_Qlo : (sec == 1) ? g_Klo : g_Vlo;
                    __nv_bfloat16 h0 = __float2bfloat16(v.x);
                    __nv_bfloat16 h1 = __float2bfloat16(v.y);
                    __nv_bfloat16 l0 = __float2bfloat16(v.x - __bfloat162float(h0));
                    __nv_bfloat16 l1 = __float2bfloat16(v.y - __bfloat162float(h1));
                    *(__nv_bfloat162*)&dhi[idx] = __nv_bfloat162(h0, h1);
                    *(__nv_bfloat162*)&dlo[idx] = __nv_bfloat162(l0, l1);
                } else {
                    v.x += bias[f];
                    v.y += bias[f + 1];
                    *(float2*)&C[(size_t)m * DIMC + f] = v;
                }
            }
        }
    }
}

// ============================================================================
// Tensor-core fused causal flash attention with relative position term.
// q-block 128, key tile 64, 8 warps. P stays in registers (S-frag == A-frag).
// V row-major + ldmatrix.trans; V double-buffered, K/E/V prefetch under PV.
// ============================================================================
#define OFF_QHI  0u
#define OFF_QLO  16384u
#define OFF_KHI  32768u
#define OFF_KLO  40960u
#define OFF_EHI  49152u
#define OFF_ELO  73728u
#define OFF_V    98304u      // 2 bufs x (8KB hi + 8KB lo)
#define OFF_R    131072u     // 8 warps x 16 rows x 84 floats
#define ATTN_SMEM 174080

__global__ __launch_bounds__(256)
void attn_kernel()
{
    extern __shared__ char smc[];
    const uint32_t sb = smem_u32(smc);
    const int tid  = threadIdx.x;
    const int w    = tid >> 5;
    const int lane = tid & 31;
    const int bq = 7 - (int)blockIdx.x;     // heavy blocks first
    const int bh = blockIdx.y;
    const int n0 = bq * 128;

    const size_t bho = (size_t)bh * NSEQ * HD;
    const __nv_bfloat16* Qhi = g_Qhi + bho;
    const __nv_bfloat16* Qlo = g_Qlo + bho;
    const __nv_bfloat16* Khi = g_Khi + bho;
    const __nv_bfloat16* Klo = g_Klo + bho;
    const __nv_bfloat16* Vhi = g_Vhi + bho;
    const __nv_bfloat16* Vlo = g_Vlo + bho;

    // ---- load Q (128 rows hi + 128 rows lo) ----
#pragma unroll
    for (int t = 0; t < 8; t++) {
        int c = tid + t * 256;
        int buf = c >> 10;
        int row = (c >> 3) & 127;
        int seg = c & 7;
        const __nv_bfloat16* src = buf ? Qlo : Qhi;
        cp_async16(sb + (buf ? OFF_QLO : OFF_QHI) + SW128(row * 128 + seg * 16),
                   src + (size_t)(n0 + row) * HD + seg * 8);
    }

    auto issueKEV = [&](int kt) {
        const int km0 = kt * 64;
        const int base = NSEQ - 128 - n0 + km0;
        const uint32_t vB = OFF_V + (uint32_t)(kt & 1) * 16384u;
        // K: 64 rows hi + 64 lo
#pragma unroll
        for (int t = 0; t < 4; t++) {
            int c = tid + t * 256;
            int buf = c >> 9;
            int row = (c >> 3) & 63;
            int seg = c & 7;
            const __nv_bfloat16* src = buf ? Klo : Khi;
            cp_async16(sb + (buf ? OFF_KLO : OFF_KHI) + SW128(row * 128 + seg * 16),
                       src + (size_t)(km0 + row) * HD + seg * 8);
        }
        // V: 64 rows hi + 64 lo (row-major, double-buffered)
#pragma unroll
        for (int t = 0; t < 4; t++) {
            int c = tid + t * 256;
            int buf = c >> 9;
            int row = (c >> 3) & 63;
            int seg = c & 7;
            const __nv_bfloat16* src = buf ? Vlo : Vhi;
            cp_async16(sb + vB + (buf ? 8192u : 0u) + SW128(row * 128 + seg * 16),
                       src + (size_t)(km0 + row) * HD + seg * 8);
        }
        // E band: 192 rows hi + 192 lo (zero-fill e >= NSEQ)
#pragma unroll
        for (int t = 0; t < 12; t++) {
            int c = tid + t * 256;
            int buf = (c >= 1536) ? 1 : 0;
            int cc = c - buf * 1536;
            int row = cc >> 3;
            int seg = cc & 7;
            int e = base + row;
            uint32_t off = (buf ? OFF_ELO : OFF_EHI) + SW128(row * 128 + seg * 16);
            if (e < NSEQ) {
                const __nv_bfloat16* src = buf ? g_erlo : g_erhi;
                cp_async16(sb + off, src + (size_t)e * HD + seg * 8);
            } else {
                *(uint4*)(smc + off) = make_uint4(0u, 0u, 0u, 0u);
            }
        }
    };

    issueKEV(0);
    CP_COMMIT();

    float mrow[2] = {-1e30f, -1e30f};
    float lrow[2] = {0.0f, 0.0f};
    float O[8][4];
#pragma unroll
    for (int nt = 0; nt < 8; nt++)
#pragma unroll
        for (int r = 0; r < 4; r++) O[nt][r] = 0.0f;

    const int t0w = 112 - 16 * w;
    const int ktmax = 2 * bq + 1;

    for (int kt = 0; kt <= ktmax; kt++) {
        const int km0 = kt * 64;
        CP_WAIT(0);
        __syncthreads();    // K/E/V(kt) (+Q first iter) visible

        // ---- S = Q.K^T (n=64) and R = Q.E_band^T (n=80, warp-private band) ----
        float S[8][4], R[10][4];
#pragma unroll
        for (int nt = 0; nt < 8; nt++)
#pragma unroll
            for (int r = 0; r < 4; r++) S[nt][r] = 0.0f;
#pragma unroll
        for (int nt = 0; nt < 10; nt++)
#pragma unroll
            for (int r = 0; r < 4; r++) R[nt][r] = 0.0f;

#pragma unroll
        for (int seg3 = 0; seg3 < 3; seg3++) {
            const uint32_t aB = sb + (seg3 == 1 ? OFF_QLO : OFF_QHI);
            const uint32_t kB = sb + (seg3 == 2 ? OFF_KLO : OFF_KHI);
            const uint32_t eB = sb + (seg3 == 2 ? OFF_ELO : OFF_EHI);
#pragma unroll
            for (int ks = 0; ks < 4; ks++) {
                const int kb = ks * 32;
                uint32_t a[4];
                {
                    int row = 16 * w + (lane & 15);
                    uint32_t ad = aB + SW128(row * 128 + kb + ((lane >> 4) << 4));
                    LDSM_X4(a[0], a[1], a[2], a[3], ad);
                }
                uint32_t bk[4][4];
#pragma unroll
                for (int bt = 0; bt < 4; bt++) {
                    int row = bt * 16 + (lane & 7) + (((lane >> 4) & 1) << 3);
                    uint32_t bd = kB + SW128(row * 128 + kb + (((lane >> 3) & 1) << 4));
                    LDSM_X4(bk[bt][0], bk[bt][1], bk[bt][2], bk[bt][3], bd);
                }
                uint32_t be[5][4];
#pragma unroll
                for (int bt = 0; bt < 5; bt++) {
                    int row = t0w + bt * 16 + (lane & 7) + (((lane >> 4) & 1) << 3);
                    uint32_t bd = eB + SW128(row * 128 + kb + (((lane >> 3) & 1) << 4));
                    LDSM_X4(be[bt][0], be[bt][1], be[bt][2], be[bt][3], bd);
                }
#pragma unroll
                for (int nt = 0; nt < 8; nt++) {
                    int bt = nt >> 1, pr = (nt & 1) << 1;
                    MMA16816(S[nt], a, bk[bt][pr], bk[bt][pr + 1]);
                }
#pragma unroll
                for (int nt = 0; nt < 10; nt++) {
                    int bt = nt >> 1, pr = (nt & 1) << 1;
                    MMA16816(R[nt], a, be[bt][pr], be[bt][pr + 1]);
                }
            }
        }

        // ---- store R (warp-private region), gather diagonal, scale, mask ----
        float* sR = (float*)(smc + OFF_R) + w * 16 * 84;
        {
            int r0 = lane >> 2;
#pragma unroll
            for (int nt = 0; nt < 10; nt++) {
                int col = nt * 8 + (lane & 3) * 2;
                *(float2*)&sR[r0 * 84 + col]       = make_float2(R[nt][0], R[nt][1]);
                *(float2*)&sR[(r0 + 8) * 84 + col] = make_float2(R[nt][2], R[nt][3]);
            }
        }
        __syncwarp();

        const bool maskt = (kt >= 2 * bq);
#pragma unroll
        for (int nt = 0; nt < 8; nt++) {
            int j0 = nt * 8 + (lane & 3) * 2;
#pragma unroll
            for (int h = 0; h < 2; h++) {
                int il = (lane >> 2) + 8 * h;
                int col = 15 + j0 - il;
                float s0 = (S[nt][2 * h]     + sR[il * 84 + col])     * 0.125f;
                float s1 = (S[nt][2 * h + 1] + sR[il * 84 + col + 1]) * 0.125f;
                if (maskt) {
                    int ig = n0 + 16 * w + il;
                    int jg = km0 + j0;
                    if (jg > ig)     s0 = -1e30f;
                    if (jg + 1 > ig) s1 = -1e30f;
                }
                S[nt][2 * h]     = s0;
                S[nt][2 * h + 1] = s1;
            }
        }

        // ---- online softmax (rows warp-local; quad = 4 lanes per row) ----
        float alpha[2];
#pragma unroll
        for (int h = 0; h < 2; h++) {
            float v = -1e30f;
#pragma unroll
            for (int nt = 0; nt < 8; nt++)
                v = fmaxf(v, fmaxf(S[nt][2 * h], S[nt][2 * h + 1]));
            v = fmaxf(v, __shfl_xor_sync(0xffffffffu, v, 1));
            v = fmaxf(v, __shfl_xor_sync(0xffffffffu, v, 2));
            float mnew = fmaxf(mrow[h], v);
            alpha[h] = __expf(mrow[h] - mnew);
            mrow[h] = mnew;
        }
        float rsum[2] = {0.0f, 0.0f};
#pragma unroll
        for (int nt = 0; nt < 8; nt++)
#pragma unroll
            for (int h = 0; h < 2; h++) {
                float p0 = __expf(S[nt][2 * h]     - mrow[h]);
                float p1 = __expf(S[nt][2 * h + 1] - mrow[h]);
                S[nt][2 * h] = p0; S[nt][2 * h + 1] = p1;
                rsum[h] += p0 + p1;
            }
#pragma unroll
        for (int h = 0; h < 2; h++) {
            rsum[h] += __shfl_xor_sync(0xffffffffu, rsum[h], 1);
            rsum[h] += __shfl_xor_sync(0xffffffffu, rsum[h], 2);
            lrow[h] = lrow[h] * alpha[h] + rsum[h];
        }
#pragma unroll
        for (int nt = 0; nt < 8; nt++) {
            O[nt][0] *= alpha[0]; O[nt][1] *= alpha[0];
            O[nt][2] *= alpha[1]; O[nt][3] *= alpha[1];
        }

        // ---- pack P hi/lo in registers (S-frag layout == A-frag layout) ----
        uint32_t PH[8][2], PL[8][2];
#pragma unroll
        for (int nt = 0; nt < 8; nt++) {
#pragma unroll
            for (int pr = 0; pr < 2; pr++) {
                float p0 = S[nt][2 * pr], p1 = S[nt][2 * pr + 1];
                __nv_bfloat162 hh = __floats2bfloat162_rn(p0, p1);
                PH[nt][pr] = *(uint32_t*)&hh;
                __nv_bfloat162 ll = __floats2bfloat162_rn(
                    p0 - __bfloat162float(hh.x), p1 - __bfloat162float(hh.y));
                PL[nt][pr] = *(uint32_t*)&ll;
            }
        }

        __syncthreads();      // all warps done reading K/E -> safe to prefetch
        if (kt < ktmax) { issueKEV(kt + 1); CP_COMMIT(); }

        // ---- O += P.V  (split 3-pass, V via ldmatrix.trans, B frags) ----
        const uint32_t vhB = sb + OFF_V + (uint32_t)(kt & 1) * 16384u;
#pragma unroll
        for (int seg3 = 0; seg3 < 3; seg3++) {
            const bool aHi = (seg3 != 1);
            const uint32_t vB = vhB + (seg3 == 2 ? 8192u : 0u);
#pragma unroll
            for (int ks = 0; ks < 4; ks++) {
                uint32_t a[4];
                if (aHi) {
                    a[0] = PH[2*ks][0]; a[1] = PH[2*ks][1];
                    a[2] = PH[2*ks+1][0]; a[3] = PH[2*ks+1][1];
                } else {
                    a[0] = PL[2*ks][0]; a[1] = PL[2*ks][1];
                    a[2] = PL[2*ks+1][0]; a[3] = PL[2*ks+1][1];
                }
                int row = ks * 16 + (lane & 15);
#pragma unroll
                for (int bt = 0; bt < 4; bt++) {
                    uint32_t bd = vB + SW128(row * 128 + bt * 32 + ((lane >> 4) << 4));
                    uint32_t r0, r1, r2, r3;
                    LDSM_X4T(r0, r1, r2, r3, bd);
                    MMA16816(O[2*bt],     a, r0, r1);
                    MMA16816(O[2*bt + 1], a, r2, r3);
                }
            }
        }
    }

    // ---- epilogue: O /= l, split bf16 hi/lo -> g_at{hi,lo}[b][n][h*64+d] ----
    const int b_i = bh >> 4, hhead = bh & 15;
    float inv[2] = {1.0f / lrow[0], 1.0f / lrow[1]};
#pragma unroll
    for (int nt = 0; nt < 8; nt++) {
        int c = hhead * 64 + nt * 8 + (lane & 3) * 2;
#pragma unroll
        for (int h = 0; h < 2; h++) {
            int n = n0 + 16 * w + (lane >> 2) + 8 * h;
            float o0 = O[nt][2 * h] * inv[h];
            float o1 = O[nt][2 * h + 1] * inv[h];
            __nv_bfloat16 h0 = __float2bfloat16(o0);
            __nv_bfloat16 h1 = __float2bfloat16(o1);
            __nv_bfloat16 l0 = __float2bfloat16(o0 - __bfloat162float(h0));
            __nv_bfloat16 l1 = __float2bfloat16(o1 - __bfloat162float(h1));
            size_t idx = ((size_t)b_i * NSEQ + n) * DIMC + c;
            *(__nv_bfloat162*)&g_athi[idx] = __nv_bfloat162(h0, h1);
            *(__nv_bfloat162*)&g_atlo[idx] = __nv_bfloat162(l0, l1);
        }
    }
}

// ============================================================================
extern "C" void kernel_launch(void* const* d_in, const int* in_sizes, int n_in,
                              void* d_out, int out_size)
{
    const float* x      = (const float*)d_in[0];
    const float* W_qkv  = (const float*)d_in[1];
    const float* W_proj = (const float*)d_in[2];
    const float* b_proj = (const float*)d_in[3];
    const float* Er     = (const float*)d_in[4];
    float* out = (float*)d_out;

    // 0) split fp32 -> bf16 hi/lo (single launch)
    split_all<<<(NSPLIT4 + 255) / 256, 256>>>(x, W_qkv, W_proj, Er);

    // 1) QKV via HMMA: M=4096, N=3072 (3-stage smem = 96 KB)
    const int gsmem = 3 * 32768;
    cudaFuncSetAttribute(hmma_gemm<0>,
                         cudaFuncAttributeMaxDynamicSharedMemorySize, gsmem);
    cudaFuncSetAttribute(hmma_gemm<1>,
                         cudaFuncAttributeMaxDynamicSharedMemorySize, gsmem);
    hmma_gemm<0><<<dim3(24, 32), 256, gsmem>>>(nullptr, nullptr);

    // 2) tensor-core fused attention (8 q-blocks x 64 bh)
    cudaFuncSetAttribute(attn_kernel,
                         cudaFuncAttributeMaxDynamicSharedMemorySize, ATTN_SMEM);
    attn_kernel<<<dim3(8, 64), 256, ATTN_SMEM>>>();

    // 3) proj via HMMA: M=4096, N=1024, +bias
    hmma_gemm<1><<<dim3(8, 32), 256, gsmem>>>(b_proj, out);
}

// round 9
// speedup vs baseline: 2.6678x; 1.1061x over previous
#include <cuda_runtime.h>
#include <cuda_bf16.h>
#include <cstdint>

#define DIMC  1024
#define NSEQ  1024
#define BATCH 4
#define NHEAD 16
#define HD    64
#define BHTOT (BATCH*NHEAD)

// ---------------- scratch (device globals; no allocation at runtime) ----------
__device__ __nv_bfloat16 g_Qhi[(size_t)BHTOT*NSEQ*HD];
__device__ __nv_bfloat16 g_Qlo[(size_t)BHTOT*NSEQ*HD];
__device__ __nv_bfloat16 g_Khi[(size_t)BHTOT*NSEQ*HD];
__device__ __nv_bfloat16 g_Klo[(size_t)BHTOT*NSEQ*HD];
__device__ __nv_bfloat16 g_Vhi[(size_t)BHTOT*NSEQ*HD];
__device__ __nv_bfloat16 g_Vlo[(size_t)BHTOT*NSEQ*HD];

__device__ __nv_bfloat16 g_xhi[(size_t)BATCH*NSEQ*DIMC];
__device__ __nv_bfloat16 g_xlo[(size_t)BATCH*NSEQ*DIMC];
__device__ __nv_bfloat16 g_wqhi[(size_t)3*DIMC*DIMC];
__device__ __nv_bfloat16 g_wqlo[(size_t)3*DIMC*DIMC];
__device__ __nv_bfloat16 g_wphi[(size_t)DIMC*DIMC];
__device__ __nv_bfloat16 g_wplo[(size_t)DIMC*DIMC];
__device__ __nv_bfloat16 g_athi[(size_t)BATCH*NSEQ*DIMC];
__device__ __nv_bfloat16 g_atlo[(size_t)BATCH*NSEQ*DIMC];
__device__ __nv_bfloat16 g_erhi[(size_t)NSEQ*HD];
__device__ __nv_bfloat16 g_erlo[(size_t)NSEQ*HD];

// ---------------- helpers ------------------------------------------------------
__device__ __forceinline__ uint32_t smem_u32(const void* p) {
    uint32_t a;
    asm("{ .reg .u64 t; cvta.to.shared.u64 t, %1; cvt.u32.u64 %0, t; }"
        : "=r"(a) : "l"(p));
    return a;
}

__device__ __forceinline__ void cp_async16(uint32_t saddr, const void* gaddr) {
    asm volatile("cp.async.cg.shared.global [%0], [%1], 16;"
                 :: "r"(saddr), "l"(gaddr));
}
#define CP_COMMIT() asm volatile("cp.async.commit_group;" ::: "memory")
#define CP_WAIT(n)  asm volatile("cp.async.wait_group %0;" :: "n"(n) : "memory")

#define LDSM_X4(R0, R1, R2, R3, addr) \
    asm volatile("ldmatrix.sync.aligned.m8n8.x4.shared.b16 {%0,%1,%2,%3}, [%4];" \
                 : "=r"(R0), "=r"(R1), "=r"(R2), "=r"(R3) : "r"(addr))

#define LDSM_X4T(R0, R1, R2, R3, addr) \
    asm volatile("ldmatrix.sync.aligned.m8n8.x4.trans.shared.b16 {%0,%1,%2,%3}, [%4];" \
                 : "=r"(R0), "=r"(R1), "=r"(R2), "=r"(R3) : "r"(addr))

#define MMA16816(d, a, b0, b1) \
    asm volatile("mma.sync.aligned.m16n8k16.row.col.f32.bf16.bf16.f32 " \
                 "{%0,%1,%2,%3}, {%4,%5,%6,%7}, {%8,%9}, {%0,%1,%2,%3};" \
                 : "+f"((d)[0]), "+f"((d)[1]), "+f"((d)[2]), "+f"((d)[3]) \
                 : "r"((a)[0]), "r"((a)[1]), "r"((a)[2]), "r"((a)[3]),   \
                   "r"(b0), "r"(b1))

// SW128 (Swizzle<3,4,3>) on byte offsets inside a 1024B-aligned tile
#define SW128(off) (((uint32_t)(off)) ^ ((((uint32_t)(off)) >> 3) & 0x70))

// ============================================================================
// Combined split fp32 -> bf16 hi/lo for x, W_qkv, W_proj, Er (one launch).
// ============================================================================
#define NX4  1048576
#define NWQ4 786432
#define NWP4 262144
#define NER4 16384
#define NSPLIT4 (NX4 + NWQ4 + NWP4 + NER4)

__global__ void split_all(const float* __restrict__ x, const float* __restrict__ wq,
                          const float* __restrict__ wp, const float* __restrict__ er)
{
    int i = blockIdx.x * blockDim.x + threadIdx.x;
    const float* src;
    __nv_bfloat16 *hi, *lo;
    int j;
    if (i < NX4)                    { src = x;  hi = g_xhi;  lo = g_xlo;  j = i; }
    else if (i < NX4 + NWQ4)        { src = wq; hi = g_wqhi; lo = g_wqlo; j = i - NX4; }
    else if (i < NX4 + NWQ4 + NWP4) { src = wp; hi = g_wphi; lo = g_wplo; j = i - NX4 - NWQ4; }
    else if (i < NSPLIT4)           { src = er; hi = g_erhi; lo = g_erlo; j = i - NX4 - NWQ4 - NWP4; }
    else return;

    float4 v = ((const float4*)src)[j];
    __nv_bfloat16 h0 = __float2bfloat16(v.x);
    __nv_bfloat16 h1 = __float2bfloat16(v.y);
    __nv_bfloat16 h2 = __float2bfloat16(v.z);
    __nv_bfloat16 h3 = __float2bfloat16(v.w);
    __nv_bfloat16 l0 = __float2bfloat16(v.x - __bfloat162float(h0));
    __nv_bfloat16 l1 = __float2bfloat16(v.y - __bfloat162float(h1));
    __nv_bfloat16 l2 = __float2bfloat16(v.z - __bfloat162float(h2));
    __nv_bfloat16 l3 = __float2bfloat16(v.w - __bfloat162float(h3));
    ((__nv_bfloat162*)hi)[2*j]   = __nv_bfloat162(h0, h1);
    ((__nv_bfloat162*)hi)[2*j+1] = __nv_bfloat162(h2, h3);
    ((__nv_bfloat162*)lo)[2*j]   = __nv_bfloat162(l0, l1);
    ((__nv_bfloat162*)lo)[2*j+1] = __nv_bfloat162(l2, l3);
}

// ============================================================================
// HMMA split-precision GEMM, 3-stage cp.async pipeline.
// C = A(M,1024)*B(Nc,1024)^T.  Virtual K = 3x1024.
// MODE 0: QKV -> bf16 hi/lo into g_{Q,K,V}{hi,lo}.   MODE 1: proj +bias fp32.
// ============================================================================
#define NSTAGES 48

template<int MODE>
__global__ __launch_bounds__(256)
void hmma_gemm(const float* __restrict__ bias, float* __restrict__ C)
{
    extern __shared__ char dynsm[];
    const uint32_t sbase = smem_u32(dynsm);

    const int tid  = threadIdx.x;
    const int wid  = tid >> 5;
    const int lane = tid & 31;
    const int wm = wid & 3;
    const int wn = wid >> 2;
    const int m0 = blockIdx.y * 128;
    const int n0 = blockIdx.x * 128;

    const __nv_bfloat16* Ahi = (MODE == 0) ? g_xhi : g_athi;
    const __nv_bfloat16* Alo = (MODE == 0) ? g_xlo : g_atlo;
    const __nv_bfloat16* Bhi = (MODE == 0) ? g_wqhi : g_wphi;
    const __nv_bfloat16* Blo = (MODE == 0) ? g_wqlo : g_wplo;

    float d[2][8][4];
#pragma unroll
    for (int mt = 0; mt < 2; mt++)
#pragma unroll
        for (int nt = 0; nt < 8; nt++)
#pragma unroll
            for (int r = 0; r < 4; r++) d[mt][nt][r] = 0.0f;

    auto issue_stage = [&](int s) {
        const __nv_bfloat16* aS = (s < 32) ? Ahi : Alo;
        const __nv_bfloat16* bS = (s >= 16 && s < 32) ? Blo : Bhi;
        const int kin = (s & 15) * 64;
        const uint32_t stbase = sbase + (uint32_t)(s % 3) * 32768u;
#pragma unroll
        for (int t = 0; t < 8; t++) {
            int c   = tid + t * 256;
            int op  = c >> 10;
            int row = (c >> 3) & 127;
            int seg = c & 7;
            const __nv_bfloat16* src = op ? bS : aS;
            int r0 = op ? n0 : m0;
            const void* g = src + (size_t)(r0 + row) * 1024 + kin + seg * 8;
            uint32_t sa = stbase + (op ? 16384u : 0u)
                        + SW128((uint32_t)(row * 128 + seg * 16));
            cp_async16(sa, g);
        }
    };

    issue_stage(0); CP_COMMIT();
    issue_stage(1); CP_COMMIT();

    for (int s = 0; s < NSTAGES; s++) {
        if (s == NSTAGES - 1) { CP_WAIT(0); } else { CP_WAIT(1); }
        __syncthreads();
        if (s + 2 < NSTAGES) { issue_stage(s + 2); CP_COMMIT(); }

        const uint32_t aBase = sbase + (uint32_t)(s % 3) * 32768u;
        const uint32_t bBase = aBase + 16384u;

#pragma unroll
        for (int ks = 0; ks < 4; ks++) {
            const int kb = ks * 32;
            uint32_t a[2][4];
#pragma unroll
            for (int mt = 0; mt < 2; mt++) {
                int row = wm * 32 + mt * 16 + (lane & 15);
                uint32_t ad = aBase + SW128((uint32_t)(row * 128 + kb + ((lane >> 4) << 4)));
                LDSM_X4(a[mt][0], a[mt][1], a[mt][2], a[mt][3], ad);
            }
            uint32_t b[4][4];
#pragma unroll
            for (int bt = 0; bt < 4; bt++) {
                int row = wn * 64 + bt * 16 + (lane & 7) + (((lane >> 4) & 1) << 3);
                uint32_t bd = bBase + SW128((uint32_t)(row * 128 + kb + (((lane >> 3) & 1) << 4)));
                LDSM_X4(b[bt][0], b[bt][1], b[bt][2], b[bt][3], bd);
            }
#pragma unroll
            for (int mt = 0; mt < 2; mt++)
#pragma unroll
                for (int nt = 0; nt < 8; nt++) {
                    int bt = nt >> 1, pr = (nt & 1) << 1;
                    MMA16816(d[mt][nt], a[mt], b[bt][pr], b[bt][pr + 1]);
                }
        }
        __syncthreads();
    }

    // ---- epilogue ----
#pragma unroll
    for (int mt = 0; mt < 2; mt++) {
        int rbase = m0 + wm * 32 + mt * 16 + (lane >> 2);
#pragma unroll
        for (int nt = 0; nt < 8; nt++) {
            int f = n0 + wn * 64 + nt * 8 + (lane & 3) * 2;
#pragma unroll
            for (int half = 0; half < 2; half++) {
                int m = rbase + half * 8;
                float2 v = make_float2(d[mt][nt][half * 2], d[mt][nt][half * 2 + 1]);
                if (MODE == 0) {
                    int b_i = m >> 10, n = m & 1023;
                    int sec = f >> 10;
                    int hh = (f >> 6) & 15, dd = f & 63;
                    size_t idx = ((size_t)(b_i * NHEAD + hh) * NSEQ + n) * HD + dd;
                    __nv_bfloat16* dhi = (sec == 0) ? g_Qhi : (sec == 1) ? g_Khi : g_Vhi;
                    __nv_bfloat16* dlo = (sec == 0) ? g_Qlo : (sec == 1) ? g_Klo : g_Vlo;
                    __nv_bfloat16 h0 = __float2bfloat16(v.x);
                    __nv_bfloat16 h1 = __float2bfloat16(v.y);
                    __nv_bfloat16 l0 = __float2bfloat16(v.x - __bfloat162float(h0));
                    __nv_bfloat16 l1 = __float2bfloat16(v.y - __bfloat162float(h1));
                    *(__nv_bfloat162*)&dhi[idx] = __nv_bfloat162(h0, h1);
                    *(__nv_bfloat162*)&dlo[idx] = __nv_bfloat162(l0, l1);
                } else {
                    v.x += bias[f];
                    v.y += bias[f + 1];
                    *(float2*)&C[(size_t)m * DIMC + f] = v;
                }
            }
        }
    }
}

// ============================================================================
// Tensor-core fused causal flash attention with relative position term.
// q-block 128, key tile 64, 8 warps. P in registers. V via ldmatrix.trans.
// E band in a 4-slot x 64-row ring buffer: only 1 new chunk loaded per tile.
// R stored diagonal-shifted: gather is conflict-free aligned float2.
// ============================================================================
#define OFF_QHI  0u
#define OFF_QLO  16384u
#define OFF_KHI  32768u
#define OFF_KLO  40960u
#define OFF_V    49152u      // 2 bufs x (8KB hi + 8KB lo)
#define OFF_EHI  81920u      // 4 slots x 8KB
#define OFF_ELO  114688u     // 4 slots x 8KB
#define OFF_R    147456u     // 8 warps x 1600 floats (16 rows x ~100, shifted)
#define ATTN_SMEM 198656

__global__ __launch_bounds__(256)
void attn_kernel()
{
    extern __shared__ char smc[];
    const uint32_t sb = smem_u32(smc);
    const int tid  = threadIdx.x;
    const int w    = tid >> 5;
    const int lane = tid & 31;
    const int bq = 7 - (int)blockIdx.x;     // heavy blocks first
    const int bh = blockIdx.y;
    const int n0 = bq * 128;

    const size_t bho = (size_t)bh * NSEQ * HD;
    const __nv_bfloat16* Qhi = g_Qhi + bho;
    const __nv_bfloat16* Qlo = g_Qlo + bho;
    const __nv_bfloat16* Khi = g_Khi + bho;
    const __nv_bfloat16* Klo = g_Klo + bho;
    const __nv_bfloat16* Vhi = g_Vhi + bho;
    const __nv_bfloat16* Vlo = g_Vlo + bho;

    const int base0 = NSEQ - 128 - n0;      // 64-aligned, >= 0
    const int c0 = base0 >> 6;              // first E chunk index

    // ---- load Q (128 rows hi + 128 rows lo) ----
#pragma unroll
    for (int t = 0; t < 8; t++) {
        int c = tid + t * 256;
        int buf = c >> 10;
        int row = (c >> 3) & 127;
        int seg = c & 7;
        const __nv_bfloat16* src = buf ? Qlo : Qhi;
        cp_async16(sb + (buf ? OFF_QLO : OFF_QHI) + SW128(row * 128 + seg * 16),
                   src + (size_t)(n0 + row) * HD + seg * 8);
    }

    auto issueK = [&](int kt) {
        const int km0 = kt * 64;
#pragma unroll
        for (int t = 0; t < 4; t++) {
            int c = tid + t * 256;
            int buf = c >> 9;
            int row = (c >> 3) & 63;
            int seg = c & 7;
            const __nv_bfloat16* src = buf ? Klo : Khi;
            cp_async16(sb + (buf ? OFF_KLO : OFF_KHI) + SW128(row * 128 + seg * 16),
                       src + (size_t)(km0 + row) * HD + seg * 8);
        }
    };
    auto issueV = [&](int kt) {
        const int km0 = kt * 64;
        const uint32_t vB = OFF_V + (uint32_t)(kt & 1) * 16384u;
#pragma unroll
        for (int t = 0; t < 4; t++) {
            int c = tid + t * 256;
            int buf = c >> 9;
            int row = (c >> 3) & 63;
            int seg = c & 7;
            const __nv_bfloat16* src = buf ? Vlo : Vhi;
            cp_async16(sb + vB + (buf ? 8192u : 0u) + SW128(row * 128 + seg * 16),
                       src + (size_t)(km0 + row) * HD + seg * 8);
        }
    };
    // load one 64-row E chunk (hi+lo) into ring slot (ci & 3)
    auto issueEchunk = [&](int ci) {
        const int rb = ci << 6;
        const uint32_t slot = ((uint32_t)ci & 3u) * 8192u;
#pragma unroll
        for (int t = 0; t < 4; t++) {
            int c = tid + t * 256;
            int buf = c >> 9;
            int row = (c >> 3) & 63;
            int seg = c & 7;
            int r = rb + row;
            uint32_t off = (buf ? OFF_ELO : OFF_EHI) + slot + SW128(row * 128 + seg * 16);
            if (r < NSEQ) {
                const __nv_bfloat16* src = buf ? g_erlo : g_erhi;
                cp_async16(sb + off, src + (size_t)r * HD + seg * 8);
            } else {
                *(uint4*)(smc + off) = make_uint4(0u, 0u, 0u, 0u);
            }
        }
    };

    issueK(0); issueV(0);
    issueEchunk(c0); issueEchunk(c0 + 1); issueEchunk(c0 + 2);
    CP_COMMIT();

    float mrow[2] = {-1e30f, -1e30f};
    float lrow[2] = {0.0f, 0.0f};
    float O[8][4];
#pragma unroll
    for (int nt = 0; nt < 8; nt++)
#pragma unroll
        for (int r = 0; r < 4; r++) O[nt][r] = 0.0f;

    const int t0w = 112 - 16 * w;
    const int ktmax = 2 * bq + 1;
    // per-lane absolute E row base for ldmatrix (frag bt adds bt*16)
    const int eRow0 = base0 + t0w + (lane & 7) + (((lane >> 4) & 1) << 3);

    float* sRd = (float*)(smc + OFF_R) + w * 1600;

    for (int kt = 0; kt <= ktmax; kt++) {
        const int km0 = kt * 64;
        CP_WAIT(0);
        __syncthreads();    // K/E/V(kt) (+Q first iter) visible

        // ---- S = Q.K^T (n=64) and R = Q.E_band^T (n=80, warp-private band) ----
        float S[8][4], R[10][4];
#pragma unroll
        for (int nt = 0; nt < 8; nt++)
#pragma unroll
            for (int r = 0; r < 4; r++) S[nt][r] = 0.0f;
#pragma unroll
        for (int nt = 0; nt < 10; nt++)
#pragma unroll
            for (int r = 0; r < 4; r++) R[nt][r] = 0.0f;

        const int eRowK = eRow0 + km0;   // absolute E row for this tile

#pragma unroll
        for (int seg3 = 0; seg3 < 3; seg3++) {
            const uint32_t aB = sb + (seg3 == 1 ? OFF_QLO : OFF_QHI);
            const uint32_t kB = sb + (seg3 == 2 ? OFF_KLO : OFF_KHI);
            const uint32_t eB = sb + (seg3 == 2 ? OFF_ELO : OFF_EHI);
#pragma unroll
            for (int ks = 0; ks < 4; ks++) {
                const int kb = ks * 32;
                uint32_t a[4];
                {
                    int row = 16 * w + (lane & 15);
                    uint32_t ad = aB + SW128(row * 128 + kb + ((lane >> 4) << 4));
                    LDSM_X4(a[0], a[1], a[2], a[3], ad);
                }
                uint32_t bk[4][4];
#pragma unroll
                for (int bt = 0; bt < 4; bt++) {
                    int row = bt * 16 + (lane & 7) + (((lane >> 4) & 1) << 3);
                    uint32_t bd = kB + SW128(row * 128 + kb + (((lane >> 3) & 1) << 4));
                    LDSM_X4(bk[bt][0], bk[bt][1], bk[bt][2], bk[bt][3], bd);
                }
                uint32_t be[5][4];
#pragma unroll
                for (int bt = 0; bt < 5; bt++) {
                    int r = eRowK + bt * 16;             // absolute row in ring
                    uint32_t bd = eB + (((uint32_t)(r >> 6) & 3u) * 8192u)
                                + SW128((r & 63) * 128 + kb + (((lane >> 3) & 1) << 4));
                    LDSM_X4(be[bt][0], be[bt][1], be[bt][2], be[bt][3], bd);
                }
#pragma unroll
                for (int nt = 0; nt < 8; nt++) {
                    int bt = nt >> 1, pr = (nt & 1) << 1;
                    MMA16816(S[nt], a, bk[bt][pr], bk[bt][pr + 1]);
                }
#pragma unroll
                for (int nt = 0; nt < 10; nt++) {
                    int bt = nt >> 1, pr = (nt & 1) << 1;
                    MMA16816(R[nt], a, be[bt][pr], be[bt][pr + 1]);
                }
            }
        }

        // ---- store R diagonal-shifted: (r,c) -> idx 101*r + c + 1 ----
        {
            int r0 = lane >> 2;
#pragma unroll
            for (int nt = 0; nt < 10; nt++) {
                int cA = nt * 8 + (lane & 3) * 2;
                int i0 = 101 * r0 + cA + 1;
                sRd[i0]     = R[nt][0];
                sRd[i0 + 1] = R[nt][1];
                int i1 = i0 + 101 * 8;
                sRd[i1]     = R[nt][2];
                sRd[i1 + 1] = R[nt][3];
            }
        }
        __syncwarp();

        // ---- gather rel (aligned float2 at il*100 + j0 + 16), scale, mask ----
        const bool maskt = (kt >= 2 * bq);
#pragma unroll
        for (int nt = 0; nt < 8; nt++) {
            int j0 = nt * 8 + (lane & 3) * 2;
#pragma unroll
            for (int h = 0; h < 2; h++) {
                int il = (lane >> 2) + 8 * h;
                float2 rv = *(const float2*)&sRd[il * 100 + j0 + 16];
                float s0 = (S[nt][2 * h]     + rv.x) * 0.125f;
                float s1 = (S[nt][2 * h + 1] + rv.y) * 0.125f;
                if (maskt) {
                    int ig = n0 + 16 * w + il;
                    int jg = km0 + j0;
                    if (jg > ig)     s0 = -1e30f;
                    if (jg + 1 > ig) s1 = -1e30f;
                }
                S[nt][2 * h]     = s0;
                S[nt][2 * h + 1] = s1;
            }
        }

        // ---- online softmax (rows warp-local; quad = 4 lanes per row) ----
        float alpha[2];
#pragma unroll
        for (int h = 0; h < 2; h++) {
            float v = -1e30f;
#pragma unroll
            for (int nt = 0; nt < 8; nt++)
                v = fmaxf(v, fmaxf(S[nt][2 * h], S[nt][2 * h + 1]));
            v = fmaxf(v, __shfl_xor_sync(0xffffffffu, v, 1));
            v = fmaxf(v, __shfl_xor_sync(0xffffffffu, v, 2));
            float mnew = fmaxf(mrow[h], v);
            alpha[h] = __expf(mrow[h] - mnew);
            mrow[h] = mnew;
        }
        float rsum[2] = {0.0f, 0.0f};
#pragma unroll
        for (int nt = 0; nt < 8; nt++)
#pragma unroll
            for (int h = 0; h < 2; h++) {
                float p0 = __expf(S[nt][2 * h]     - mrow[h]);
                float p1 = __expf(S[nt][2 * h + 1] - mrow[h]);
                S[nt][2 * h] = p0; S[nt][2 * h + 1] = p1;
                rsum[h] += p0 + p1;
            }
#pragma unroll
        for (int h = 0; h < 2; h++) {
            rsum[h] += __shfl_xor_sync(0xffffffffu, rsum[h], 1);
            rsum[h] += __shfl_xor_sync(0xffffffffu, rsum[h], 2);
            lrow[h] = lrow[h] * alpha[h] + rsum[h];
        }
#pragma unroll
        for (int nt = 0; nt < 8; nt++) {
            O[nt][0] *= alpha[0]; O[nt][1] *= alpha[0];
            O[nt][2] *= alpha[1]; O[nt][3] *= alpha[1];
        }

        // ---- pack P hi/lo in registers (S-frag layout == A-frag layout) ----
        uint32_t PH[8][2], PL[8][2];
#pragma unroll
        for (int nt = 0; nt < 8; nt++) {
#pragma unroll
            for (int pr = 0; pr < 2; pr++) {
                float p0 = S[nt][2 * pr], p1 = S[nt][2 * pr + 1];
                __nv_bfloat162 hh = __floats2bfloat162_rn(p0, p1);
                PH[nt][pr] = *(uint32_t*)&hh;
                __nv_bfloat162 ll = __floats2bfloat162_rn(
                    p0 - __bfloat162float(hh.x), p1 - __bfloat162float(hh.y));
                PL[nt][pr] = *(uint32_t*)&ll;
            }
        }

        __syncthreads();      // all warps done reading K/E -> safe to prefetch
        if (kt < ktmax) {
            issueK(kt + 1); issueV(kt + 1); issueEchunk(c0 + kt + 3);
            CP_COMMIT();
        }

        // ---- O += P.V  (split 3-pass, V via ldmatrix.trans, B frags) ----
        const uint32_t vhB = sb + OFF_V + (uint32_t)(kt & 1) * 16384u;
#pragma unroll
        for (int seg3 = 0; seg3 < 3; seg3++) {
            const bool aHi = (seg3 != 1);
            const uint32_t vB = vhB + (seg3 == 2 ? 8192u : 0u);
#pragma unroll
            for (int ks = 0; ks < 4; ks++) {
                uint32_t a[4];
                if (aHi) {
                    a[0] = PH[2*ks][0]; a[1] = PH[2*ks][1];
                    a[2] = PH[2*ks+1][0]; a[3] = PH[2*ks+1][1];
                } else {
                    a[0] = PL[2*ks][0]; a[1] = PL[2*ks][1];
                    a[2] = PL[2*ks+1][0]; a[3] = PL[2*ks+1][1];
                }
                int row = ks * 16 + (lane & 15);
#pragma unroll
                for (int bt = 0; bt < 4; bt++) {
                    uint32_t bd = vB + SW128(row * 128 + bt * 32 + ((lane >> 4) << 4));
                    uint32_t r0, r1, r2, r3;
                    LDSM_X4T(r0, r1, r2, r3, bd);
                    MMA16816(O[2*bt],     a, r0, r1);
                    MMA16816(O[2*bt + 1], a, r2, r3);
                }
            }
        }
    }

    // ---- epilogue: O /= l, split bf16 hi/lo -> g_at{hi,lo}[b][n][h*64+d] ----
    const int b_i = bh >> 4, hhead = bh & 15;
    float inv[2] = {1.0f / lrow[0], 1.0f / lrow[1]};
#pragma unroll
    for (int nt = 0; nt < 8; nt++) {
        int c = hhead * 64 + nt * 8 + (lane & 3) * 2;
#pragma unroll
        for (int h = 0; h < 2; h++) {
            int n = n0 + 16 * w + (lane >> 2) + 8 * h;
            float o0 = O[nt][2 * h] * inv[h];
            float o1 = O[nt][2 * h + 1] * inv[h];
            __nv_bfloat16 h0 = __float2bfloat16(o0);
            __nv_bfloat16 h1 = __float2bfloat16(o1);
            __nv_bfloat16 l0 = __float2bfloat16(o0 - __bfloat162float(h0));
            __nv_bfloat16 l1 = __float2bfloat16(o1 - __bfloat162float(h1));
            size_t idx = ((size_t)b_i * NSEQ + n) * DIMC + c;
            *(__nv_bfloat162*)&g_athi[idx] = __nv_bfloat162(h0, h1);
            *(__nv_bfloat162*)&g_atlo[idx] = __nv_bfloat162(l0, l1);
        }
    }
}

// ============================================================================
extern "C" void kernel_launch(void* const* d_in, const int* in_sizes, int n_in,
                              void* d_out, int out_size)
{
    const float* x      = (const float*)d_in[0];
    const float* W_qkv  = (const float*)d_in[1];
    const float* W_proj = (const float*)d_in[2];
    const float* b_proj = (const float*)d_in[3];
    const float* Er     = (const float*)d_in[4];
    float* out = (float*)d_out;

    // 0) split fp32 -> bf16 hi/lo (single launch)
    split_all<<<(NSPLIT4 + 255) / 256, 256>>>(x, W_qkv, W_proj, Er);

    // 1) QKV via HMMA: M=4096, N=3072 (3-stage smem = 96 KB)
    const int gsmem = 3 * 32768;
    cudaFuncSetAttribute(hmma_gemm<0>,
                         cudaFuncAttributeMaxDynamicSharedMemorySize, gsmem);
    cudaFuncSetAttribute(hmma_gemm<1>,
                         cudaFuncAttributeMaxDynamicSharedMemorySize, gsmem);
    hmma_gemm<0><<<dim3(24, 32), 256, gsmem>>>(nullptr, nullptr);

    // 2) tensor-core fused attention (8 q-blocks x 64 bh)
    cudaFuncSetAttribute(attn_kernel,
                         cudaFuncAttributeMaxDynamicSharedMemorySize, ATTN_SMEM);
    attn_kernel<<<dim3(8, 64), 256, ATTN_SMEM>>>();

    // 3) proj via HMMA: M=4096, N=1024, +bias
    hmma_gemm<1><<<dim3(8, 32), 256, gsmem>>>(b_proj, out);
}

// round 10
// speedup vs baseline: 2.7844x; 1.0437x over previous
#include <cuda_runtime.h>
#include <cuda_bf16.h>
#include <cstdint>

#define DIMC  1024
#define NSEQ  1024
#define BATCH 4
#define NHEAD 16
#define HD    64
#define BHTOT (BATCH*NHEAD)

// ---------------- scratch (device globals; no allocation at runtime) ----------
__device__ __nv_bfloat16 g_Qhi[(size_t)BHTOT*NSEQ*HD];
__device__ __nv_bfloat16 g_Qlo[(size_t)BHTOT*NSEQ*HD];
__device__ __nv_bfloat16 g_Khi[(size_t)BHTOT*NSEQ*HD];
__device__ __nv_bfloat16 g_Klo[(size_t)BHTOT*NSEQ*HD];
__device__ __nv_bfloat16 g_Vhi[(size_t)BHTOT*NSEQ*HD];
__device__ __nv_bfloat16 g_Vlo[(size_t)BHTOT*NSEQ*HD];

__device__ __nv_bfloat16 g_xhi[(size_t)BATCH*NSEQ*DIMC];
__device__ __nv_bfloat16 g_xlo[(size_t)BATCH*NSEQ*DIMC];
__device__ __nv_bfloat16 g_wqhi[(size_t)3*DIMC*DIMC];
__device__ __nv_bfloat16 g_wqlo[(size_t)3*DIMC*DIMC];
__device__ __nv_bfloat16 g_wphi[(size_t)DIMC*DIMC];
__device__ __nv_bfloat16 g_wplo[(size_t)DIMC*DIMC];
__device__ __nv_bfloat16 g_athi[(size_t)BATCH*NSEQ*DIMC];
__device__ __nv_bfloat16 g_atlo[(size_t)BATCH*NSEQ*DIMC];
__device__ __nv_bfloat16 g_erhi[(size_t)NSEQ*HD];
__device__ __nv_bfloat16 g_erlo[(size_t)NSEQ*HD];

// ---------------- helpers ------------------------------------------------------
__device__ __forceinline__ uint32_t smem_u32(const void* p) {
    uint32_t a;
    asm("{ .reg .u64 t; cvta.to.shared.u64 t, %1; cvt.u32.u64 %0, t; }"
        : "=r"(a) : "l"(p));
    return a;
}

__device__ __forceinline__ void cp_async16(uint32_t saddr, const void* gaddr) {
    asm volatile("cp.async.cg.shared.global [%0], [%1], 16;"
                 :: "r"(saddr), "l"(gaddr));
}
#define CP_COMMIT() asm volatile("cp.async.commit_group;" ::: "memory")
#define CP_WAIT(n)  asm volatile("cp.async.wait_group %0;" :: "n"(n) : "memory")

#define LDSM_X4(R0, R1, R2, R3, addr) \
    asm volatile("ldmatrix.sync.aligned.m8n8.x4.shared.b16 {%0,%1,%2,%3}, [%4];" \
                 : "=r"(R0), "=r"(R1), "=r"(R2), "=r"(R3) : "r"(addr))

#define LDSM_X4T(R0, R1, R2, R3, addr) \
    asm volatile("ldmatrix.sync.aligned.m8n8.x4.trans.shared.b16 {%0,%1,%2,%3}, [%4];" \
                 : "=r"(R0), "=r"(R1), "=r"(R2), "=r"(R3) : "r"(addr))

#define MMA16816(d, a, b0, b1) \
    asm volatile("mma.sync.aligned.m16n8k16.row.col.f32.bf16.bf16.f32 " \
                 "{%0,%1,%2,%3}, {%4,%5,%6,%7}, {%8,%9}, {%0,%1,%2,%3};" \
                 : "+f"((d)[0]), "+f"((d)[1]), "+f"((d)[2]), "+f"((d)[3]) \
                 : "r"((a)[0]), "r"((a)[1]), "r"((a)[2]), "r"((a)[3]),   \
                   "r"(b0), "r"(b1))

// SW128 (Swizzle<3,4,3>) on byte offsets inside a 1024B-aligned tile
#define SW128(off) (((uint32_t)(off)) ^ ((((uint32_t)(off)) >> 3) & 0x70))

// ============================================================================
// Combined split fp32 -> bf16 hi/lo for x, W_qkv, W_proj, Er (one launch).
// ============================================================================
#define NX4  1048576
#define NWQ4 786432
#define NWP4 262144
#define NER4 16384
#define NSPLIT4 (NX4 + NWQ4 + NWP4 + NER4)

__global__ void split_all(const float* __restrict__ x, const float* __restrict__ wq,
                          const float* __restrict__ wp, const float* __restrict__ er)
{
    int i = blockIdx.x * blockDim.x + threadIdx.x;
    const float* src;
    __nv_bfloat16 *hi, *lo;
    int j;
    if (i < NX4)                    { src = x;  hi = g_xhi;  lo = g_xlo;  j = i; }
    else if (i < NX4 + NWQ4)        { src = wq; hi = g_wqhi; lo = g_wqlo; j = i - NX4; }
    else if (i < NX4 + NWQ4 + NWP4) { src = wp; hi = g_wphi; lo = g_wplo; j = i - NX4 - NWQ4; }
    else if (i < NSPLIT4)           { src = er; hi = g_erhi; lo = g_erlo; j = i - NX4 - NWQ4 - NWP4; }
    else return;

    float4 v = ((const float4*)src)[j];
    __nv_bfloat16 h0 = __float2bfloat16(v.x);
    __nv_bfloat16 h1 = __float2bfloat16(v.y);
    __nv_bfloat16 h2 = __float2bfloat16(v.z);
    __nv_bfloat16 h3 = __float2bfloat16(v.w);
    __nv_bfloat16 l0 = __float2bfloat16(v.x - __bfloat162float(h0));
    __nv_bfloat16 l1 = __float2bfloat16(v.y - __bfloat162float(h1));
    __nv_bfloat16 l2 = __float2bfloat16(v.z - __bfloat162float(h2));
    __nv_bfloat16 l3 = __float2bfloat16(v.w - __bfloat162float(h3));
    ((__nv_bfloat162*)hi)[2*j]   = __nv_bfloat162(h0, h1);
    ((__nv_bfloat162*)hi)[2*j+1] = __nv_bfloat162(h2, h3);
    ((__nv_bfloat162*)lo)[2*j]   = __nv_bfloat162(l0, l1);
    ((__nv_bfloat162*)lo)[2*j+1] = __nv_bfloat162(l2, l3);
}

// ============================================================================
// HMMA split-precision GEMM, 3-stage cp.async pipeline.  (unchanged)
// ============================================================================
#define NSTAGES 48

template<int MODE>
__global__ __launch_bounds__(256)
void hmma_gemm(const float* __restrict__ bias, float* __restrict__ C)
{
    extern __shared__ char dynsm[];
    const uint32_t sbase = smem_u32(dynsm);

    const int tid  = threadIdx.x;
    const int wid  = tid >> 5;
    const int lane = tid & 31;
    const int wm = wid & 3;
    const int wn = wid >> 2;
    const int m0 = blockIdx.y * 128;
    const int n0 = blockIdx.x * 128;

    const __nv_bfloat16* Ahi = (MODE == 0) ? g_xhi : g_athi;
    const __nv_bfloat16* Alo = (MODE == 0) ? g_xlo : g_atlo;
    const __nv_bfloat16* Bhi = (MODE == 0) ? g_wqhi : g_wphi;
    const __nv_bfloat16* Blo = (MODE == 0) ? g_wqlo : g_wplo;

    float d[2][8][4];
#pragma unroll
    for (int mt = 0; mt < 2; mt++)
#pragma unroll
        for (int nt = 0; nt < 8; nt++)
#pragma unroll
            for (int r = 0; r < 4; r++) d[mt][nt][r] = 0.0f;

    auto issue_stage = [&](int s) {
        const __nv_bfloat16* aS = (s < 32) ? Ahi : Alo;
        const __nv_bfloat16* bS = (s >= 16 && s < 32) ? Blo : Bhi;
        const int kin = (s & 15) * 64;
        const uint32_t stbase = sbase + (uint32_t)(s % 3) * 32768u;
#pragma unroll
        for (int t = 0; t < 8; t++) {
            int c   = tid + t * 256;
            int op  = c >> 10;
            int row = (c >> 3) & 127;
            int seg = c & 7;
            const __nv_bfloat16* src = op ? bS : aS;
            int r0 = op ? n0 : m0;
            const void* g = src + (size_t)(r0 + row) * 1024 + kin + seg * 8;
            uint32_t sa = stbase + (op ? 16384u : 0u)
                        + SW128((uint32_t)(row * 128 + seg * 16));
            cp_async16(sa, g);
        }
    };

    issue_stage(0); CP_COMMIT();
    issue_stage(1); CP_COMMIT();

    for (int s = 0; s < NSTAGES; s++) {
        if (s == NSTAGES - 1) { CP_WAIT(0); } else { CP_WAIT(1); }
        __syncthreads();
        if (s + 2 < NSTAGES) { issue_stage(s + 2); CP_COMMIT(); }

        const uint32_t aBase = sbase + (uint32_t)(s % 3) * 32768u;
        const uint32_t bBase = aBase + 16384u;

#pragma unroll
        for (int ks = 0; ks < 4; ks++) {
            const int kb = ks * 32;
            uint32_t a[2][4];
#pragma unroll
            for (int mt = 0; mt < 2; mt++) {
                int row = wm * 32 + mt * 16 + (lane & 15);
                uint32_t ad = aBase + SW128((uint32_t)(row * 128 + kb + ((lane >> 4) << 4)));
                LDSM_X4(a[mt][0], a[mt][1], a[mt][2], a[mt][3], ad);
            }
            uint32_t b[4][4];
#pragma unroll
            for (int bt = 0; bt < 4; bt++) {
                int row = wn * 64 + bt * 16 + (lane & 7) + (((lane >> 4) & 1) << 3);
                uint32_t bd = bBase + SW128((uint32_t)(row * 128 + kb + (((lane >> 3) & 1) << 4)));
                LDSM_X4(b[bt][0], b[bt][1], b[bt][2], b[bt][3], bd);
            }
#pragma unroll
            for (int mt = 0; mt < 2; mt++)
#pragma unroll
                for (int nt = 0; nt < 8; nt++) {
                    int bt = nt >> 1, pr = (nt & 1) << 1;
                    MMA16816(d[mt][nt], a[mt], b[bt][pr], b[bt][pr + 1]);
                }
        }
        __syncthreads();
    }

    // ---- epilogue ----
#pragma unroll
    for (int mt = 0; mt < 2; mt++) {
        int rbase = m0 + wm * 32 + mt * 16 + (lane >> 2);
#pragma unroll
        for (int nt = 0; nt < 8; nt++) {
            int f = n0 + wn * 64 + nt * 8 + (lane & 3) * 2;
#pragma unroll
            for (int half = 0; half < 2; half++) {
                int m = rbase + half * 8;
                float2 v = make_float2(d[mt][nt][half * 2], d[mt][nt][half * 2 + 1]);
                if (MODE == 0) {
                    int b_i = m >> 10, n = m & 1023;
                    int sec = f >> 10;
                    int hh = (f >> 6) & 15, dd = f & 63;
                    size_t idx = ((size_t)(b_i * NHEAD + hh) * NSEQ + n) * HD + dd;
                    __nv_bfloat16* dhi = (sec == 0) ? g_Qhi : (sec == 1) ? g_Khi : g_Vhi;
                    __nv_bfloat16* dlo = (sec == 0) ? g_Qlo : (sec == 1) ? g_Klo : g_Vlo;
                    __nv_bfloat16 h0 = __float2bfloat16(v.x);
                    __nv_bfloat16 h1 = __float2bfloat16(v.y);
                    __nv_bfloat16 l0 = __float2bfloat16(v.x - __bfloat162float(h0));
                    __nv_bfloat16 l1 = __float2bfloat16(v.y - __bfloat162float(h1));
                    *(__nv_bfloat162*)&dhi[idx] = __nv_bfloat162(h0, h1);
                    *(__nv_bfloat162*)&dlo[idx] = __nv_bfloat162(l0, l1);
                } else {
                    v.x += bias[f];
                    v.y += bias[f + 1];
                    *(float2*)&C[(size_t)m * DIMC + f] = v;
                }
            }
        }
    }
}

// ============================================================================
// Tensor-core fused causal flash attention with relative position term.
// q-block 128, key tile 64, 8 warps. Split-bf16 passes fused per k16 slice
// (operands loaded once, used by hi*hi + hi*lo + lo*hi). K and V double-
// buffered; E in a 4-slot ring. Prefetch issued right after S/R MMAs and
// overlaps softmax + PV. One __syncthreads per tile.
// ============================================================================
#define OFF_QHI  0u
#define OFF_QLO  16384u
#define OFF_K    32768u      // + (kt&1)*16384 ; hi +0, lo +8192
#define OFF_V    65536u      // + (kt&1)*16384 ; hi +0, lo +8192
#define OFF_EHI  98304u      // 4 slots x 8KB
#define OFF_ELO  131072u     // 4 slots x 8KB
#define OFF_R    163840u     // 8 warps x 1600 floats
#define ATTN_SMEM 215040

__global__ __launch_bounds__(256)
void attn_kernel()
{
    extern __shared__ char smc[];
    const uint32_t sb = smem_u32(smc);
    const int tid  = threadIdx.x;
    const int w    = tid >> 5;
    const int lane = tid & 31;
    const int bq = 7 - (int)blockIdx.x;     // heavy blocks first
    const int bh = blockIdx.y;
    const int n0 = bq * 128;

    const size_t bho = (size_t)bh * NSEQ * HD;
    const __nv_bfloat16* Qhi = g_Qhi + bho;
    const __nv_bfloat16* Qlo = g_Qlo + bho;
    const __nv_bfloat16* Khi = g_Khi + bho;
    const __nv_bfloat16* Klo = g_Klo + bho;
    const __nv_bfloat16* Vhi = g_Vhi + bho;
    const __nv_bfloat16* Vlo = g_Vlo + bho;

    const int base0 = NSEQ - 128 - n0;      // 64-aligned, >= 0
    const int c0 = base0 >> 6;              // first E chunk index

    // ---- load Q (128 rows hi + 128 rows lo) ----
#pragma unroll
    for (int t = 0; t < 8; t++) {
        int c = tid + t * 256;
        int buf = c >> 10;
        int row = (c >> 3) & 127;
        int seg = c & 7;
        const __nv_bfloat16* src = buf ? Qlo : Qhi;
        cp_async16(sb + (buf ? OFF_QLO : OFF_QHI) + SW128(row * 128 + seg * 16),
                   src + (size_t)(n0 + row) * HD + seg * 8);
    }

    auto issueK = [&](int kt) {
        const int km0 = kt * 64;
        const uint32_t kB = OFF_K + (uint32_t)(kt & 1) * 16384u;
#pragma unroll
        for (int t = 0; t < 4; t++) {
            int c = tid + t * 256;
            int buf = c >> 9;
            int row = (c >> 3) & 63;
            int seg = c & 7;
            const __nv_bfloat16* src = buf ? Klo : Khi;
            cp_async16(sb + kB + (buf ? 8192u : 0u) + SW128(row * 128 + seg * 16),
                       src + (size_t)(km0 + row) * HD + seg * 8);
        }
    };
    auto issueV = [&](int kt) {
        const int km0 = kt * 64;
        const uint32_t vB = OFF_V + (uint32_t)(kt & 1) * 16384u;
#pragma unroll
        for (int t = 0; t < 4; t++) {
            int c = tid + t * 256;
            int buf = c >> 9;
            int row = (c >> 3) & 63;
            int seg = c & 7;
            const __nv_bfloat16* src = buf ? Vlo : Vhi;
            cp_async16(sb + vB + (buf ? 8192u : 0u) + SW128(row * 128 + seg * 16),
                       src + (size_t)(km0 + row) * HD + seg * 8);
        }
    };
    // load one 64-row E chunk (hi+lo) into ring slot (ci & 3)
    auto issueEchunk = [&](int ci) {
        const int rb = ci << 6;
        const uint32_t slot = ((uint32_t)ci & 3u) * 8192u;
#pragma unroll
        for (int t = 0; t < 4; t++) {
            int c = tid + t * 256;
            int buf = c >> 9;
            int row = (c >> 3) & 63;
            int seg = c & 7;
            int r = rb + row;
            uint32_t off = (buf ? OFF_ELO : OFF_EHI) + slot + SW128(row * 128 + seg * 16);
            if (r < NSEQ) {
                const __nv_bfloat16* src = buf ? g_erlo : g_erhi;
                cp_async16(sb + off, src + (size_t)r * HD + seg * 8);
            } else {
                *(uint4*)(smc + off) = make_uint4(0u, 0u, 0u, 0u);
            }
        }
    };

    issueK(0); issueV(0);
    issueEchunk(c0); issueEchunk(c0 + 1); issueEchunk(c0 + 2);
    CP_COMMIT();

    float mrow[2] = {-1e30f, -1e30f};
    float lrow[2] = {0.0f, 0.0f};
    float O[8][4];
#pragma unroll
    for (int nt = 0; nt < 8; nt++)
#pragma unroll
        for (int r = 0; r < 4; r++) O[nt][r] = 0.0f;

    const int t0w = 112 - 16 * w;
    const int ktmax = 2 * bq + 1;
    // per-lane absolute E row base for ldmatrix (frag bt adds bt*16)
    const int eRow0 = base0 + t0w + (lane & 7) + (((lane >> 4) & 1) << 3);

    float* sRd = (float*)(smc + OFF_R) + w * 1600;

    for (int kt = 0; kt <= ktmax; kt++) {
        const int km0 = kt * 64;
        CP_WAIT(0);
        __syncthreads();    // K/E/V(kt) (+Q first iter) visible; prior reads done

        float S[8][4], R[10][4];
#pragma unroll
        for (int nt = 0; nt < 8; nt++)
#pragma unroll
            for (int r = 0; r < 4; r++) S[nt][r] = 0.0f;
#pragma unroll
        for (int nt = 0; nt < 10; nt++)
#pragma unroll
            for (int r = 0; r < 4; r++) R[nt][r] = 0.0f;

        const int eRowK = eRow0 + km0;
        const uint32_t kHiB = sb + OFF_K + (uint32_t)(kt & 1) * 16384u;
        const uint32_t kLoB = kHiB + 8192u;
        const uint32_t eHiB = sb + OFF_EHI;
        const uint32_t eLoB = sb + OFF_ELO;

        // ---- S = Q.K^T and R = Q.E^T, all split passes fused per k16 slice --
#pragma unroll
        for (int ks = 0; ks < 4; ks++) {
            const int kb = ks * 32;
            const int arow = 16 * w + (lane & 15);
            const uint32_t aoff = SW128(arow * 128 + kb + ((lane >> 4) << 4));
            uint32_t aH[4], aL[4];
            LDSM_X4(aH[0], aH[1], aH[2], aH[3], sb + OFF_QHI + aoff);
            LDSM_X4(aL[0], aL[1], aL[2], aL[3], sb + OFF_QLO + aoff);

            uint32_t bb[5][4];
            // K hi: used by aH and aL
#pragma unroll
            for (int bt = 0; bt < 4; bt++) {
                int row = bt * 16 + (lane & 7) + (((lane >> 4) & 1) << 3);
                uint32_t bd = kHiB + SW128(row * 128 + kb + (((lane >> 3) & 1) << 4));
                LDSM_X4(bb[bt][0], bb[bt][1], bb[bt][2], bb[bt][3], bd);
            }
#pragma unroll
            for (int nt = 0; nt < 8; nt++) {
                int bt = nt >> 1, pr = (nt & 1) << 1;
                MMA16816(S[nt], aH, bb[bt][pr], bb[bt][pr + 1]);
            }
#pragma unroll
            for (int nt = 0; nt < 8; nt++) {
                int bt = nt >> 1, pr = (nt & 1) << 1;
                MMA16816(S[nt], aL, bb[bt][pr], bb[bt][pr + 1]);
            }
            // K lo: used by aH
#pragma unroll
            for (int bt = 0; bt < 4; bt++) {
                int row = bt * 16 + (lane & 7) + (((lane >> 4) & 1) << 3);
                uint32_t bd = kLoB + SW128(row * 128 + kb + (((lane >> 3) & 1) << 4));
                LDSM_X4(bb[bt][0], bb[bt][1], bb[bt][2], bb[bt][3], bd);
            }
#pragma unroll
            for (int nt = 0; nt < 8; nt++) {
                int bt = nt >> 1, pr = (nt & 1) << 1;
                MMA16816(S[nt], aH, bb[bt][pr], bb[bt][pr + 1]);
            }
            // E hi: used by aH and aL
#pragma unroll
            for (int bt = 0; bt < 5; bt++) {
                int r = eRowK + bt * 16;
                uint32_t bd = eHiB + (((uint32_t)(r >> 6) & 3u) * 8192u)
                            + SW128((r & 63) * 128 + kb + (((lane >> 3) & 1) << 4));
                LDSM_X4(bb[bt][0], bb[bt][1], bb[bt][2], bb[bt][3], bd);
            }
#pragma unroll
            for (int nt = 0; nt < 10; nt++) {
                int bt = nt >> 1, pr = (nt & 1) << 1;
                MMA16816(R[nt], aH, bb[bt][pr], bb[bt][pr + 1]);
            }
#pragma unroll
            for (int nt = 0; nt < 10; nt++) {
                int bt = nt >> 1, pr = (nt & 1) << 1;
                MMA16816(R[nt], aL, bb[bt][pr], bb[bt][pr + 1]);
            }
            // E lo: used by aH
#pragma unroll
            for (int bt = 0; bt < 5; bt++) {
                int r = eRowK + bt * 16;
                uint32_t bd = eLoB + (((uint32_t)(r >> 6) & 3u) * 8192u)
                            + SW128((r & 63) * 128 + kb + (((lane >> 3) & 1) << 4));
                LDSM_X4(bb[bt][0], bb[bt][1], bb[bt][2], bb[bt][3], bd);
            }
#pragma unroll
            for (int nt = 0; nt < 10; nt++) {
                int bt = nt >> 1, pr = (nt & 1) << 1;
                MMA16816(R[nt], aH, bb[bt][pr], bb[bt][pr + 1]);
            }
        }

        // ---- prefetch next tile (disjoint buffers/slots; no sync needed) ----
        if (kt < ktmax) {
            issueK(kt + 1); issueV(kt + 1); issueEchunk(c0 + kt + 3);
            CP_COMMIT();
        }

        // ---- store R diagonal-shifted: (r,c) -> idx 101*r + c + 1 ----
        {
            int r0 = lane >> 2;
#pragma unroll
            for (int nt = 0; nt < 10; nt++) {
                int cA = nt * 8 + (lane & 3) * 2;
                int i0 = 101 * r0 + cA + 1;
                sRd[i0]     = R[nt][0];
                sRd[i0 + 1] = R[nt][1];
                int i1 = i0 + 101 * 8;
                sRd[i1]     = R[nt][2];
                sRd[i1 + 1] = R[nt][3];
            }
        }
        __syncwarp();

        // ---- gather rel (aligned float2 at il*100 + j0 + 16), scale, mask ----
        const bool maskt = (kt >= 2 * bq);
#pragma unroll
        for (int nt = 0; nt < 8; nt++) {
            int j0 = nt * 8 + (lane & 3) * 2;
#pragma unroll
            for (int h = 0; h < 2; h++) {
                int il = (lane >> 2) + 8 * h;
                float2 rv = *(const float2*)&sRd[il * 100 + j0 + 16];
                float s0 = (S[nt][2 * h]     + rv.x) * 0.125f;
                float s1 = (S[nt][2 * h + 1] + rv.y) * 0.125f;
                if (maskt) {
                    int ig = n0 + 16 * w + il;
                    int jg = km0 + j0;
                    if (jg > ig)     s0 = -1e30f;
                    if (jg + 1 > ig) s1 = -1e30f;
                }
                S[nt][2 * h]     = s0;
                S[nt][2 * h + 1] = s1;
            }
        }

        // ---- online softmax (rows warp-local; quad = 4 lanes per row) ----
        float alpha[2];
#pragma unroll
        for (int h = 0; h < 2; h++) {
            float v = -1e30f;
#pragma unroll
            for (int nt = 0; nt < 8; nt++)
                v = fmaxf(v, fmaxf(S[nt][2 * h], S[nt][2 * h + 1]));
            v = fmaxf(v, __shfl_xor_sync(0xffffffffu, v, 1));
            v = fmaxf(v, __shfl_xor_sync(0xffffffffu, v, 2));
            float mnew = fmaxf(mrow[h], v);
            alpha[h] = __expf(mrow[h] - mnew);
            mrow[h] = mnew;
        }
        float rsum[2] = {0.0f, 0.0f};
#pragma unroll
        for (int nt = 0; nt < 8; nt++)
#pragma unroll
            for (int h = 0; h < 2; h++) {
                float p0 = __expf(S[nt][2 * h]     - mrow[h]);
                float p1 = __expf(S[nt][2 * h + 1] - mrow[h]);
                S[nt][2 * h] = p0; S[nt][2 * h + 1] = p1;
                rsum[h] += p0 + p1;
            }
#pragma unroll
        for (int h = 0; h < 2; h++) {
            rsum[h] += __shfl_xor_sync(0xffffffffu, rsum[h], 1);
            rsum[h] += __shfl_xor_sync(0xffffffffu, rsum[h], 2);
            lrow[h] = lrow[h] * alpha[h] + rsum[h];
        }
#pragma unroll
        for (int nt = 0; nt < 8; nt++) {
            O[nt][0] *= alpha[0]; O[nt][1] *= alpha[0];
            O[nt][2] *= alpha[1]; O[nt][3] *= alpha[1];
        }

        // ---- pack P hi/lo in registers (S-frag layout == A-frag layout) ----
        uint32_t PH[8][2], PL[8][2];
#pragma unroll
        for (int nt = 0; nt < 8; nt++) {
#pragma unroll
            for (int pr = 0; pr < 2; pr++) {
                float p0 = S[nt][2 * pr], p1 = S[nt][2 * pr + 1];
                __nv_bfloat162 hh = __floats2bfloat162_rn(p0, p1);
                PH[nt][pr] = *(uint32_t*)&hh;
                __nv_bfloat162 ll = __floats2bfloat162_rn(
                    p0 - __bfloat162float(hh.x), p1 - __bfloat162float(hh.y));
                PL[nt][pr] = *(uint32_t*)&ll;
            }
        }

        // ---- O += P.V  (V frags loaded once, used by PH and PL) ----
        const uint32_t vHiB = sb + OFF_V + (uint32_t)(kt & 1) * 16384u;
        const uint32_t vLoB = vHiB + 8192u;
#pragma unroll
        for (int ks = 0; ks < 4; ks++) {
            uint32_t aPH[4] = {PH[2*ks][0], PH[2*ks][1], PH[2*ks+1][0], PH[2*ks+1][1]};
            uint32_t aPL[4] = {PL[2*ks][0], PL[2*ks][1], PL[2*ks+1][0], PL[2*ks+1][1]};
            int row = ks * 16 + (lane & 15);
            // V hi: used by PH and PL
#pragma unroll
            for (int bt = 0; bt < 4; bt++) {
                uint32_t bd = vHiB + SW128(row * 128 + bt * 32 + ((lane >> 4) << 4));
                uint32_t r0, r1, r2, r3;
                LDSM_X4T(r0, r1, r2, r3, bd);
                MMA16816(O[2*bt],     aPH, r0, r1);
                MMA16816(O[2*bt + 1], aPH, r2, r3);
                MMA16816(O[2*bt],     aPL, r0, r1);
                MMA16816(O[2*bt + 1], aPL, r2, r3);
            }
            // V lo: used by PH
#pragma unroll
            for (int bt = 0; bt < 4; bt++) {
                uint32_t bd = vLoB + SW128(row * 128 + bt * 32 + ((lane >> 4) << 4));
                uint32_t r0, r1, r2, r3;
                LDSM_X4T(r0, r1, r2, r3, bd);
                MMA16816(O[2*bt],     aPH, r0, r1);
                MMA16816(O[2*bt + 1], aPH, r2, r3);
            }
        }
    }

    // ---- epilogue: O /= l, split bf16 hi/lo -> g_at{hi,lo}[b][n][h*64+d] ----
    const int b_i = bh >> 4, hhead = bh & 15;
    float inv[2] = {1.0f / lrow[0], 1.0f / lrow[1]};
#pragma unroll
    for (int nt = 0; nt < 8; nt++) {
        int c = hhead * 64 + nt * 8 + (lane & 3) * 2;
#pragma unroll
        for (int h = 0; h < 2; h++) {
            int n = n0 + 16 * w + (lane >> 2) + 8 * h;
            float o0 = O[nt][2 * h] * inv[h];
            float o1 = O[nt][2 * h + 1] * inv[h];
            __nv_bfloat16 h0 = __float2bfloat16(o0);
            __nv_bfloat16 h1 = __float2bfloat16(o1);
            __nv_bfloat16 l0 = __float2bfloat16(o0 - __bfloat162float(h0));
            __nv_bfloat16 l1 = __float2bfloat16(o1 - __bfloat162float(h1));
            size_t idx = ((size_t)b_i * NSEQ + n) * DIMC + c;
            *(__nv_bfloat162*)&g_athi[idx] = __nv_bfloat162(h0, h1);
            *(__nv_bfloat162*)&g_atlo[idx] = __nv_bfloat162(l0, l1);
        }
    }
}

// ============================================================================
extern "C" void kernel_launch(void* const* d_in, const int* in_sizes, int n_in,
                              void* d_out, int out_size)
{
    const float* x      = (const float*)d_in[0];
    const float* W_qkv  = (const float*)d_in[1];
    const float* W_proj = (const float*)d_in[2];
    const float* b_proj = (const float*)d_in[3];
    const float* Er     = (const float*)d_in[4];
    float* out = (float*)d_out;

    // 0) split fp32 -> bf16 hi/lo (single launch)
    split_all<<<(NSPLIT4 + 255) / 256, 256>>>(x, W_qkv, W_proj, Er);

    // 1) QKV via HMMA: M=4096, N=3072 (3-stage smem = 96 KB)
    const int gsmem = 3 * 32768;
    cudaFuncSetAttribute(hmma_gemm<0>,
                         cudaFuncAttributeMaxDynamicSharedMemorySize, gsmem);
    cudaFuncSetAttribute(hmma_gemm<1>,
                         cudaFuncAttributeMaxDynamicSharedMemorySize, gsmem);
    hmma_gemm<0><<<dim3(24, 32), 256, gsmem>>>(nullptr, nullptr);

    // 2) tensor-core fused attention (8 q-blocks x 64 bh)
    cudaFuncSetAttribute(attn_kernel,
                         cudaFuncAttributeMaxDynamicSharedMemorySize, ATTN_SMEM);
    attn_kernel<<<dim3(8, 64), 256, ATTN_SMEM>>>();

    // 3) proj via HMMA: M=4096, N=1024, +bias
    hmma_gemm<1><<<dim3(8, 32), 256, gsmem>>>(b_proj, out);
}

// round 11
// speedup vs baseline: 3.2315x; 1.1606x over previous
#include <cuda_runtime.h>
#include <cuda_bf16.h>
#include <cuda_fp16.h>
#include <cstdint>

#define DIMC  1024
#define NSEQ  1024
#define BATCH 4
#define NHEAD 16
#define HD    64
#define BHTOT (BATCH*NHEAD)

// ---------------- scratch (device globals; no allocation at runtime) ----------
__device__ __half g_Qh[(size_t)BHTOT*NSEQ*HD];          // fp16 single
__device__ __half g_Kh[(size_t)BHTOT*NSEQ*HD];          // fp16 single
__device__ __nv_bfloat16 g_Vhi[(size_t)BHTOT*NSEQ*HD];  // bf16 split
__device__ __nv_bfloat16 g_Vlo[(size_t)BHTOT*NSEQ*HD];

__device__ __nv_bfloat16 g_xhi[(size_t)BATCH*NSEQ*DIMC];
__device__ __nv_bfloat16 g_xlo[(size_t)BATCH*NSEQ*DIMC];
__device__ __nv_bfloat16 g_wqhi[(size_t)3*DIMC*DIMC];
__device__ __nv_bfloat16 g_wqlo[(size_t)3*DIMC*DIMC];
__device__ __nv_bfloat16 g_wphi[(size_t)DIMC*DIMC];
__device__ __nv_bfloat16 g_wplo[(size_t)DIMC*DIMC];
__device__ __nv_bfloat16 g_athi[(size_t)BATCH*NSEQ*DIMC];
__device__ __nv_bfloat16 g_atlo[(size_t)BATCH*NSEQ*DIMC];
__device__ __half g_erh[(size_t)NSEQ*HD];               // fp16 hi
__device__ __half g_erl[(size_t)NSEQ*HD];               // fp16 lo

// ---------------- helpers ------------------------------------------------------
__device__ __forceinline__ uint32_t smem_u32(const void* p) {
    uint32_t a;
    asm("{ .reg .u64 t; cvta.to.shared.u64 t, %1; cvt.u32.u64 %0, t; }"
        : "=r"(a) : "l"(p));
    return a;
}

__device__ __forceinline__ void cp_async16(uint32_t saddr, const void* gaddr) {
    asm volatile("cp.async.cg.shared.global [%0], [%1], 16;"
                 :: "r"(saddr), "l"(gaddr));
}
#define CP_COMMIT() asm volatile("cp.async.commit_group;" ::: "memory")
#define CP_WAIT(n)  asm volatile("cp.async.wait_group %0;" :: "n"(n) : "memory")

#define LDSM_X4(R0, R1, R2, R3, addr) \
    asm volatile("ldmatrix.sync.aligned.m8n8.x4.shared.b16 {%0,%1,%2,%3}, [%4];" \
                 : "=r"(R0), "=r"(R1), "=r"(R2), "=r"(R3) : "r"(addr))

#define LDSM_X4T(R0, R1, R2, R3, addr) \
    asm volatile("ldmatrix.sync.aligned.m8n8.x4.trans.shared.b16 {%0,%1,%2,%3}, [%4];" \
                 : "=r"(R0), "=r"(R1), "=r"(R2), "=r"(R3) : "r"(addr))

#define MMA16816(d, a, b0, b1) \
    asm volatile("mma.sync.aligned.m16n8k16.row.col.f32.bf16.bf16.f32 " \
                 "{%0,%1,%2,%3}, {%4,%5,%6,%7}, {%8,%9}, {%0,%1,%2,%3};" \
                 : "+f"((d)[0]), "+f"((d)[1]), "+f"((d)[2]), "+f"((d)[3]) \
                 : "r"((a)[0]), "r"((a)[1]), "r"((a)[2]), "r"((a)[3]),   \
                   "r"(b0), "r"(b1))

#define MMAH16816(d, a, b0, b1) \
    asm volatile("mma.sync.aligned.m16n8k16.row.col.f32.f16.f16.f32 " \
                 "{%0,%1,%2,%3}, {%4,%5,%6,%7}, {%8,%9}, {%0,%1,%2,%3};" \
                 : "+f"((d)[0]), "+f"((d)[1]), "+f"((d)[2]), "+f"((d)[3]) \
                 : "r"((a)[0]), "r"((a)[1]), "r"((a)[2]), "r"((a)[3]),   \
                   "r"(b0), "r"(b1))

// SW128 (Swizzle<3,4,3>) on byte offsets inside a 1024B-aligned tile
#define SW128(off) (((uint32_t)(off)) ^ ((((uint32_t)(off)) >> 3) & 0x70))

// ============================================================================
// Combined split: x/W_qkv/W_proj -> bf16 hi/lo ;  Er -> fp16 hi/lo
// ============================================================================
#define NX4  1048576
#define NWQ4 786432
#define NWP4 262144
#define NER4 16384
#define NSPLIT4 (NX4 + NWQ4 + NWP4 + NER4)

__global__ void split_all(const float* __restrict__ x, const float* __restrict__ wq,
                          const float* __restrict__ wp, const float* __restrict__ er)
{
    int i = blockIdx.x * blockDim.x + threadIdx.x;
    if (i >= NSPLIT4) return;

    if (i >= NX4 + NWQ4 + NWP4) {           // Er -> fp16 hi/lo
        int j = i - NX4 - NWQ4 - NWP4;
        float4 v = ((const float4*)er)[j];
        __half2 h01 = __floats2half2_rn(v.x, v.y);
        __half2 h23 = __floats2half2_rn(v.z, v.w);
        __half2 l01 = __floats2half2_rn(v.x - __half2float(__low2half(h01)),
                                        v.y - __half2float(__high2half(h01)));
        __half2 l23 = __floats2half2_rn(v.z - __half2float(__low2half(h23)),
                                        v.w - __half2float(__high2half(h23)));
        ((__half2*)g_erh)[2*j]   = h01;
        ((__half2*)g_erh)[2*j+1] = h23;
        ((__half2*)g_erl)[2*j]   = l01;
        ((__half2*)g_erl)[2*j+1] = l23;
        return;
    }

    const float* src;
    __nv_bfloat16 *hi, *lo;
    int j;
    if (i < NX4)             { src = x;  hi = g_xhi;  lo = g_xlo;  j = i; }
    else if (i < NX4 + NWQ4) { src = wq; hi = g_wqhi; lo = g_wqlo; j = i - NX4; }
    else                     { src = wp; hi = g_wphi; lo = g_wplo; j = i - NX4 - NWQ4; }

    float4 v = ((const float4*)src)[j];
    __nv_bfloat16 h0 = __float2bfloat16(v.x);
    __nv_bfloat16 h1 = __float2bfloat16(v.y);
    __nv_bfloat16 h2 = __float2bfloat16(v.z);
    __nv_bfloat16 h3 = __float2bfloat16(v.w);
    __nv_bfloat16 l0 = __float2bfloat16(v.x - __bfloat162float(h0));
    __nv_bfloat16 l1 = __float2bfloat16(v.y - __bfloat162float(h1));
    __nv_bfloat16 l2 = __float2bfloat16(v.z - __bfloat162float(h2));
    __nv_bfloat16 l3 = __float2bfloat16(v.w - __bfloat162float(h3));
    ((__nv_bfloat162*)hi)[2*j]   = __nv_bfloat162(h0, h1);
    ((__nv_bfloat162*)hi)[2*j+1] = __nv_bfloat162(h2, h3);
    ((__nv_bfloat162*)lo)[2*j]   = __nv_bfloat162(l0, l1);
    ((__nv_bfloat162*)lo)[2*j+1] = __nv_bfloat162(l2, l3);
}

// ============================================================================
// HMMA split-precision GEMM, 3-stage cp.async pipeline, single sync per stage.
// MODE 0: QKV -> Q,K fp16 single; V bf16 hi/lo.   MODE 1: proj +bias fp32.
// ============================================================================
#define NSTAGES 48

template<int MODE>
__global__ __launch_bounds__(256)
void hmma_gemm(const float* __restrict__ bias, float* __restrict__ C)
{
    extern __shared__ char dynsm[];
    const uint32_t sbase = smem_u32(dynsm);

    const int tid  = threadIdx.x;
    const int wid  = tid >> 5;
    const int lane = tid & 31;
    const int wm = wid & 3;
    const int wn = wid >> 2;
    const int m0 = blockIdx.y * 128;
    const int n0 = blockIdx.x * 128;

    const __nv_bfloat16* Ahi = (MODE == 0) ? g_xhi : g_athi;
    const __nv_bfloat16* Alo = (MODE == 0) ? g_xlo : g_atlo;
    const __nv_bfloat16* Bhi = (MODE == 0) ? g_wqhi : g_wphi;
    const __nv_bfloat16* Blo = (MODE == 0) ? g_wqlo : g_wplo;

    float d[2][8][4];
#pragma unroll
    for (int mt = 0; mt < 2; mt++)
#pragma unroll
        for (int nt = 0; nt < 8; nt++)
#pragma unroll
            for (int r = 0; r < 4; r++) d[mt][nt][r] = 0.0f;

    auto issue_stage = [&](int s) {
        const __nv_bfloat16* aS = (s < 32) ? Ahi : Alo;
        const __nv_bfloat16* bS = (s >= 16 && s < 32) ? Blo : Bhi;
        const int kin = (s & 15) * 64;
        const uint32_t stbase = sbase + (uint32_t)(s % 3) * 32768u;
#pragma unroll
        for (int t = 0; t < 8; t++) {
            int c   = tid + t * 256;
            int op  = c >> 10;
            int row = (c >> 3) & 127;
            int seg = c & 7;
            const __nv_bfloat16* src = op ? bS : aS;
            int r0 = op ? n0 : m0;
            const void* g = src + (size_t)(r0 + row) * 1024 + kin + seg * 8;
            uint32_t sa = stbase + (op ? 16384u : 0u)
                        + SW128((uint32_t)(row * 128 + seg * 16));
            cp_async16(sa, g);
        }
    };

    issue_stage(0); CP_COMMIT();
    issue_stage(1); CP_COMMIT();

    for (int s = 0; s < NSTAGES; s++) {
        if (s == NSTAGES - 1) { CP_WAIT(0); } else { CP_WAIT(1); }
        __syncthreads();   // stage s resident; everyone done with stage s-1
        if (s + 2 < NSTAGES) { issue_stage(s + 2); CP_COMMIT(); }

        const uint32_t aBase = sbase + (uint32_t)(s % 3) * 32768u;
        const uint32_t bBase = aBase + 16384u;

#pragma unroll
        for (int ks = 0; ks < 4; ks++) {
            const int kb = ks * 32;
            uint32_t a[2][4];
#pragma unroll
            for (int mt = 0; mt < 2; mt++) {
                int row = wm * 32 + mt * 16 + (lane & 15);
                uint32_t ad = aBase + SW128((uint32_t)(row * 128 + kb + ((lane >> 4) << 4)));
                LDSM_X4(a[mt][0], a[mt][1], a[mt][2], a[mt][3], ad);
            }
            uint32_t b[4][4];
#pragma unroll
            for (int bt = 0; bt < 4; bt++) {
                int row = wn * 64 + bt * 16 + (lane & 7) + (((lane >> 4) & 1) << 3);
                uint32_t bd = bBase + SW128((uint32_t)(row * 128 + kb + (((lane >> 3) & 1) << 4)));
                LDSM_X4(b[bt][0], b[bt][1], b[bt][2], b[bt][3], bd);
            }
#pragma unroll
            for (int mt = 0; mt < 2; mt++)
#pragma unroll
                for (int nt = 0; nt < 8; nt++) {
                    int bt = nt >> 1, pr = (nt & 1) << 1;
                    MMA16816(d[mt][nt], a[mt], b[bt][pr], b[bt][pr + 1]);
                }
        }
        // no trailing sync: next iter's top-sync orders slot reuse
    }

    // ---- epilogue ----
#pragma unroll
    for (int mt = 0; mt < 2; mt++) {
        int rbase = m0 + wm * 32 + mt * 16 + (lane >> 2);
#pragma unroll
        for (int nt = 0; nt < 8; nt++) {
            int f = n0 + wn * 64 + nt * 8 + (lane & 3) * 2;
#pragma unroll
            for (int half = 0; half < 2; half++) {
                int m = rbase + half * 8;
                float2 v = make_float2(d[mt][nt][half * 2], d[mt][nt][half * 2 + 1]);
                if (MODE == 0) {
                    int b_i = m >> 10, n = m & 1023;
                    int sec = f >> 10;
                    int hh = (f >> 6) & 15, dd = f & 63;
                    size_t idx = ((size_t)(b_i * NHEAD + hh) * NSEQ + n) * HD + dd;
                    if (sec == 2) {
                        __nv_bfloat16 h0 = __float2bfloat16(v.x);
                        __nv_bfloat16 h1 = __float2bfloat16(v.y);
                        __nv_bfloat16 l0 = __float2bfloat16(v.x - __bfloat162float(h0));
                        __nv_bfloat16 l1 = __float2bfloat16(v.y - __bfloat162float(h1));
                        *(__nv_bfloat162*)&g_Vhi[idx] = __nv_bfloat162(h0, h1);
                        *(__nv_bfloat162*)&g_Vlo[idx] = __nv_bfloat162(l0, l1);
                    } else {
                        __half* dst = (sec == 0) ? g_Qh : g_Kh;
                        *(__half2*)&dst[idx] = __floats2half2_rn(v.x, v.y);
                    }
                } else {
                    v.x += bias[f];
                    v.y += bias[f + 1];
                    *(float2*)&C[(size_t)m * DIMC + f] = v;
                }
            }
        }
    }
}

// ============================================================================
// Tensor-core fused causal flash attention with relative position term.
// fp16: S = Qh.Kh (1 pass), R = Qh.(Ehi + Elo) (2 passes).  PV bf16 3-pass.
// K double-buffered (8KB each), V double-buffered, E fp16 hi/lo 4-slot rings.
// ============================================================================
#define OFF_Q    0u          // 16KB fp16
#define OFF_K    16384u      // 2 bufs x 8KB fp16
#define OFF_V    32768u      // 2 bufs x (8KB hi + 8KB lo) bf16
#define OFF_EHI  65536u      // 4 slots x 8KB fp16
#define OFF_ELO  98304u      // 4 slots x 8KB fp16
#define OFF_R    131072u     // 8 warps x 1600 floats
#define ATTN_SMEM 182272

__global__ __launch_bounds__(256)
void attn_kernel()
{
    extern __shared__ char smc[];
    const uint32_t sb = smem_u32(smc);
    const int tid  = threadIdx.x;
    const int w    = tid >> 5;
    const int lane = tid & 31;
    const int bq = 7 - (int)blockIdx.x;     // heavy blocks first
    const int bh = blockIdx.y;
    const int n0 = bq * 128;

    const size_t bho = (size_t)bh * NSEQ * HD;
    const __half* Qg = g_Qh + bho;
    const __half* Kg = g_Kh + bho;
    const __nv_bfloat16* Vhi = g_Vhi + bho;
    const __nv_bfloat16* Vlo = g_Vlo + bho;

    const int base0 = NSEQ - 128 - n0;      // 64-aligned, >= 0
    const int c0 = base0 >> 6;              // first E chunk index

    // ---- load Q (128 rows fp16, 16KB) ----
#pragma unroll
    for (int t = 0; t < 4; t++) {
        int c = tid + t * 256;              // 0..1023
        int row = c >> 3;
        int seg = c & 7;
        cp_async16(sb + OFF_Q + SW128(row * 128 + seg * 16),
                   Qg + (size_t)(n0 + row) * HD + seg * 8);
    }

    auto issueK = [&](int kt) {
        const int km0 = kt * 64;
        const uint32_t kB = OFF_K + (uint32_t)(kt & 1) * 8192u;
#pragma unroll
        for (int t = 0; t < 2; t++) {
            int c = tid + t * 256;          // 0..511
            int row = c >> 3;
            int seg = c & 7;
            cp_async16(sb + kB + SW128(row * 128 + seg * 16),
                       Kg + (size_t)(km0 + row) * HD + seg * 8);
        }
    };
    auto issueV = [&](int kt) {
        const int km0 = kt * 64;
        const uint32_t vB = OFF_V + (uint32_t)(kt & 1) * 16384u;
#pragma unroll
        for (int t = 0; t < 4; t++) {
            int c = tid + t * 256;
            int buf = c >> 9;
            int row = (c >> 3) & 63;
            int seg = c & 7;
            const __nv_bfloat16* src = buf ? Vlo : Vhi;
            cp_async16(sb + vB + (buf ? 8192u : 0u) + SW128(row * 128 + seg * 16),
                       src + (size_t)(km0 + row) * HD + seg * 8);
        }
    };
    // one 64-row E chunk (fp16 hi+lo) into ring slot (ci & 3)
    auto issueEchunk = [&](int ci) {
        const int rb = ci << 6;
        const uint32_t slot = ((uint32_t)ci & 3u) * 8192u;
#pragma unroll
        for (int t = 0; t < 4; t++) {
            int c = tid + t * 256;          // 0..1023
            int buf = c >> 9;
            int row = (c >> 3) & 63;
            int seg = c & 7;
            int r = rb + row;
            uint32_t off = (buf ? OFF_ELO : OFF_EHI) + slot + SW128(row * 128 + seg * 16);
            if (r < NSEQ) {
                const __half* src = buf ? g_erl : g_erh;
                cp_async16(sb + off, src + (size_t)r * HD + seg * 8);
            } else {
                *(uint4*)(smc + off) = make_uint4(0u, 0u, 0u, 0u);
            }
        }
    };

    issueK(0); issueV(0);
    issueEchunk(c0); issueEchunk(c0 + 1); issueEchunk(c0 + 2);
    CP_COMMIT();

    float mrow[2] = {-1e30f, -1e30f};
    float lrow[2] = {0.0f, 0.0f};
    float O[8][4];
#pragma unroll
    for (int nt = 0; nt < 8; nt++)
#pragma unroll
        for (int r = 0; r < 4; r++) O[nt][r] = 0.0f;

    const int t0w = 112 - 16 * w;
    const int ktmax = 2 * bq + 1;
    const int eRow0 = base0 + t0w + (lane & 7) + (((lane >> 4) & 1) << 3);

    float* sRd = (float*)(smc + OFF_R) + w * 1600;

    for (int kt = 0; kt <= ktmax; kt++) {
        const int km0 = kt * 64;
        CP_WAIT(0);
        __syncthreads();    // K/E/V(kt) (+Q first iter) visible; prior reads done

        float S[8][4], R[10][4];
#pragma unroll
        for (int nt = 0; nt < 8; nt++)
#pragma unroll
            for (int r = 0; r < 4; r++) S[nt][r] = 0.0f;
#pragma unroll
        for (int nt = 0; nt < 10; nt++)
#pragma unroll
            for (int r = 0; r < 4; r++) R[nt][r] = 0.0f;

        const int eRowK = eRow0 + km0;
        const uint32_t kB   = sb + OFF_K + (uint32_t)(kt & 1) * 8192u;
        const uint32_t eHiB = sb + OFF_EHI;
        const uint32_t eLoB = sb + OFF_ELO;

        // ---- S = Qh.Kh^T (1 pass) and R = Qh.(Ehi+Elo)^T (2 passes) ----
#pragma unroll
        for (int ks = 0; ks < 4; ks++) {
            const int kb = ks * 32;
            const int arow = 16 * w + (lane & 15);
            uint32_t aH[4];
            LDSM_X4(aH[0], aH[1], aH[2], aH[3],
                    sb + OFF_Q + SW128(arow * 128 + kb + ((lane >> 4) << 4)));

            uint32_t bb[5][4];
            // K
#pragma unroll
            for (int bt = 0; bt < 4; bt++) {
                int row = bt * 16 + (lane & 7) + (((lane >> 4) & 1) << 3);
                uint32_t bd = kB + SW128(row * 128 + kb + (((lane >> 3) & 1) << 4));
                LDSM_X4(bb[bt][0], bb[bt][1], bb[bt][2], bb[bt][3], bd);
            }
#pragma unroll
            for (int nt = 0; nt < 8; nt++) {
                int bt = nt >> 1, pr = (nt & 1) << 1;
                MMAH16816(S[nt], aH, bb[bt][pr], bb[bt][pr + 1]);
            }
            // E hi
#pragma unroll
            for (int bt = 0; bt < 5; bt++) {
                int r = eRowK + bt * 16;
                uint32_t bd = eHiB + (((uint32_t)(r >> 6) & 3u) * 8192u)
                            + SW128((r & 63) * 128 + kb + (((lane >> 3) & 1) << 4));
                LDSM_X4(bb[bt][0], bb[bt][1], bb[bt][2], bb[bt][3], bd);
            }
#pragma unroll
            for (int nt = 0; nt < 10; nt++) {
                int bt = nt >> 1, pr = (nt & 1) << 1;
                MMAH16816(R[nt], aH, bb[bt][pr], bb[bt][pr + 1]);
            }
            // E lo
#pragma unroll
            for (int bt = 0; bt < 5; bt++) {
                int r = eRowK + bt * 16;
                uint32_t bd = eLoB + (((uint32_t)(r >> 6) & 3u) * 8192u)
                            + SW128((r & 63) * 128 + kb + (((lane >> 3) & 1) << 4));
                LDSM_X4(bb[bt][0], bb[bt][1], bb[bt][2], bb[bt][3], bd);
            }
#pragma unroll
            for (int nt = 0; nt < 10; nt++) {
                int bt = nt >> 1, pr = (nt & 1) << 1;
                MMAH16816(R[nt], aH, bb[bt][pr], bb[bt][pr + 1]);
            }
        }

        // ---- prefetch next tile (disjoint buffers/slots; no sync needed) ----
        if (kt < ktmax) {
            issueK(kt + 1); issueV(kt + 1); issueEchunk(c0 + kt + 3);
            CP_COMMIT();
        }

        // ---- store R diagonal-shifted: (r,c) -> idx 101*r + c + 1 ----
        {
            int r0 = lane >> 2;
#pragma unroll
            for (int nt = 0; nt < 10; nt++) {
                int cA = nt * 8 + (lane & 3) * 2;
                int i0 = 101 * r0 + cA + 1;
                sRd[i0]     = R[nt][0];
                sRd[i0 + 1] = R[nt][1];
                int i1 = i0 + 101 * 8;
                sRd[i1]     = R[nt][2];
                sRd[i1 + 1] = R[nt][3];
            }
        }
        __syncwarp();

        // ---- gather rel (aligned float2 at il*100 + j0 + 16), scale, mask ----
        const bool maskt = (kt >= 2 * bq);
#pragma unroll
        for (int nt = 0; nt < 8; nt++) {
            int j0 = nt * 8 + (lane & 3) * 2;
#pragma unroll
            for (int h = 0; h < 2; h++) {
                int il = (lane >> 2) + 8 * h;
                float2 rv = *(const float2*)&sRd[il * 100 + j0 + 16];
                float s0 = (S[nt][2 * h]     + rv.x) * 0.125f;
                float s1 = (S[nt][2 * h + 1] + rv.y) * 0.125f;
                if (maskt) {
                    int ig = n0 + 16 * w + il;
                    int jg = km0 + j0;
                    if (jg > ig)     s0 = -1e30f;
                    if (jg + 1 > ig) s1 = -1e30f;
                }
                S[nt][2 * h]     = s0;
                S[nt][2 * h + 1] = s1;
            }
        }

        // ---- online softmax (rows warp-local; quad = 4 lanes per row) ----
        float alpha[2];
#pragma unroll
        for (int h = 0; h < 2; h++) {
            float v = -1e30f;
#pragma unroll
            for (int nt = 0; nt < 8; nt++)
                v = fmaxf(v, fmaxf(S[nt][2 * h], S[nt][2 * h + 1]));
            v = fmaxf(v, __shfl_xor_sync(0xffffffffu, v, 1));
            v = fmaxf(v, __shfl_xor_sync(0xffffffffu, v, 2));
            float mnew = fmaxf(mrow[h], v);
            alpha[h] = __expf(mrow[h] - mnew);
            mrow[h] = mnew;
        }
        float rsum[2] = {0.0f, 0.0f};
#pragma unroll
        for (int nt = 0; nt < 8; nt++)
#pragma unroll
            for (int h = 0; h < 2; h++) {
                float p0 = __expf(S[nt][2 * h]     - mrow[h]);
                float p1 = __expf(S[nt][2 * h + 1] - mrow[h]);
                S[nt][2 * h] = p0; S[nt][2 * h + 1] = p1;
                rsum[h] += p0 + p1;
            }
#pragma unroll
        for (int h = 0; h < 2; h++) {
            rsum[h] += __shfl_xor_sync(0xffffffffu, rsum[h], 1);
            rsum[h] += __shfl_xor_sync(0xffffffffu, rsum[h], 2);
            lrow[h] = lrow[h] * alpha[h] + rsum[h];
        }
#pragma unroll
        for (int nt = 0; nt < 8; nt++) {
            O[nt][0] *= alpha[0]; O[nt][1] *= alpha[0];
            O[nt][2] *= alpha[1]; O[nt][3] *= alpha[1];
        }

        // ---- pack P hi/lo bf16 in registers (S-frag layout == A-frag layout) ----
        uint32_t PH[8][2], PL[8][2];
#pragma unroll
        for (int nt = 0; nt < 8; nt++) {
#pragma unroll
            for (int pr = 0; pr < 2; pr++) {
                float p0 = S[nt][2 * pr], p1 = S[nt][2 * pr + 1];
                __nv_bfloat162 hh = __floats2bfloat162_rn(p0, p1);
                PH[nt][pr] = *(uint32_t*)&hh;
                __nv_bfloat162 ll = __floats2bfloat162_rn(
                    p0 - __bfloat162float(hh.x), p1 - __bfloat162float(hh.y));
                PL[nt][pr] = *(uint32_t*)&ll;
            }
        }

        // ---- O += P.V  (bf16 3-pass; V frags loaded once, used by PH & PL) ----
        const uint32_t vHiB = sb + OFF_V + (uint32_t)(kt & 1) * 16384u;
        const uint32_t vLoB = vHiB + 8192u;
#pragma unroll
        for (int ks = 0; ks < 4; ks++) {
            uint32_t aPH[4] = {PH[2*ks][0], PH[2*ks][1], PH[2*ks+1][0], PH[2*ks+1][1]};
            uint32_t aPL[4] = {PL[2*ks][0], PL[2*ks][1], PL[2*ks+1][0], PL[2*ks+1][1]};
            int row = ks * 16 + (lane & 15);
#pragma unroll
            for (int bt = 0; bt < 4; bt++) {
                uint32_t bd = vHiB + SW128(row * 128 + bt * 32 + ((lane >> 4) << 4));
                uint32_t r0, r1, r2, r3;
                LDSM_X4T(r0, r1, r2, r3, bd);
                MMA16816(O[2*bt],     aPH, r0, r1);
                MMA16816(O[2*bt + 1], aPH, r2, r3);
                MMA16816(O[2*bt],     aPL, r0, r1);
                MMA16816(O[2*bt + 1], aPL, r2, r3);
            }
#pragma unroll
            for (int bt = 0; bt < 4; bt++) {
                uint32_t bd = vLoB + SW128(row * 128 + bt * 32 + ((lane >> 4) << 4));
                uint32_t r0, r1, r2, r3;
                LDSM_X4T(r0, r1, r2, r3, bd);
                MMA16816(O[2*bt],     aPH, r0, r1);
                MMA16816(O[2*bt + 1], aPH, r2, r3);
            }
        }
    }

    // ---- epilogue: O /= l, split bf16 hi/lo -> g_at{hi,lo}[b][n][h*64+d] ----
    const int b_i = bh >> 4, hhead = bh & 15;
    float inv[2] = {1.0f / lrow[0], 1.0f / lrow[1]};
#pragma unroll
    for (int nt = 0; nt < 8; nt++) {
        int c = hhead * 64 + nt * 8 + (lane & 3) * 2;
#pragma unroll
        for (int h = 0; h < 2; h++) {
            int n = n0 + 16 * w + (lane >> 2) + 8 * h;
            float o0 = O[nt][2 * h] * inv[h];
            float o1 = O[nt][2 * h + 1] * inv[h];
            __nv_bfloat16 h0 = __float2bfloat16(o0);
            __nv_bfloat16 h1 = __float2bfloat16(o1);
            __nv_bfloat16 l0 = __float2bfloat16(o0 - __bfloat162float(h0));
            __nv_bfloat16 l1 = __float2bfloat16(o1 - __bfloat162float(h1));
            size_t idx = ((size_t)b_i * NSEQ + n) * DIMC + c;
            *(__nv_bfloat162*)&g_athi[idx] = __nv_bfloat162(h0, h1);
            *(__nv_bfloat162*)&g_atlo[idx] = __nv_bfloat162(l0, l1);
        }
    }
}

// ============================================================================
extern "C" void kernel_launch(void* const* d_in, const int* in_sizes, int n_in,
                              void* d_out, int out_size)
{
    const float* x      = (const float*)d_in[0];
    const float* W_qkv  = (const float*)d_in[1];
    const float* W_proj = (const float*)d_in[2];
    const float* b_proj = (const float*)d_in[3];
    const float* Er     = (const float*)d_in[4];
    float* out = (float*)d_out;

    // 0) splits (single launch)
    split_all<<<(NSPLIT4 + 255) / 256, 256>>>(x, W_qkv, W_proj, Er);

    // 1) QKV via HMMA: M=4096, N=3072 (3-stage smem = 96 KB)
    const int gsmem = 3 * 32768;
    cudaFuncSetAttribute(hmma_gemm<0>,
                         cudaFuncAttributeMaxDynamicSharedMemorySize, gsmem);
    cudaFuncSetAttribute(hmma_gemm<1>,
                         cudaFuncAttributeMaxDynamicSharedMemorySize, gsmem);
    hmma_gemm<0><<<dim3(24, 32), 256, gsmem>>>(nullptr, nullptr);

    // 2) tensor-core fused attention (8 q-blocks x 64 bh)
    cudaFuncSetAttribute(attn_kernel,
                         cudaFuncAttributeMaxDynamicSharedMemorySize, ATTN_SMEM);
    attn_kernel<<<dim3(8, 64), 256, ATTN_SMEM>>>();

    // 3) proj via HMMA: M=4096, N=1024, +bias
    hmma_gemm<1><<<dim3(8, 32), 256, gsmem>>>(b_proj, out);
}

// round 12
// speedup vs baseline: 3.5084x; 1.0857x over previous
#include <cuda_runtime.h>
#include <cuda_bf16.h>
#include <cuda_fp16.h>
#include <cstdint>

#define DIMC  1024
#define NSEQ  1024
#define BATCH 4
#define NHEAD 16
#define HD    64
#define BHTOT (BATCH*NHEAD)

// ---------------- scratch (device globals; no allocation at runtime) ----------
__device__ __half g_Qh[(size_t)BHTOT*NSEQ*HD];          // fp16 single
__device__ __half g_Kh[(size_t)BHTOT*NSEQ*HD];          // fp16 single
__device__ __half g_Vh[(size_t)BHTOT*NSEQ*HD];          // fp16 split
__device__ __half g_Vl[(size_t)BHTOT*NSEQ*HD];

__device__ __nv_bfloat16 g_xhi[(size_t)BATCH*NSEQ*DIMC];
__device__ __nv_bfloat16 g_xlo[(size_t)BATCH*NSEQ*DIMC];
__device__ __nv_bfloat16 g_wqhi[(size_t)3*DIMC*DIMC];
__device__ __nv_bfloat16 g_wqlo[(size_t)3*DIMC*DIMC];
__device__ __nv_bfloat16 g_wphi[(size_t)DIMC*DIMC];
__device__ __nv_bfloat16 g_wplo[(size_t)DIMC*DIMC];
__device__ __nv_bfloat16 g_athi[(size_t)BATCH*NSEQ*DIMC];
__device__ __nv_bfloat16 g_atlo[(size_t)BATCH*NSEQ*DIMC];
__device__ __half g_erh[(size_t)NSEQ*HD];               // fp16 hi (lo unused)

// ---------------- helpers ------------------------------------------------------
__device__ __forceinline__ uint32_t smem_u32(const void* p) {
    uint32_t a;
    asm("{ .reg .u64 t; cvta.to.shared.u64 t, %1; cvt.u32.u64 %0, t; }"
        : "=r"(a) : "l"(p));
    return a;
}

__device__ __forceinline__ void cp_async16(uint32_t saddr, const void* gaddr) {
    asm volatile("cp.async.cg.shared.global [%0], [%1], 16;"
                 :: "r"(saddr), "l"(gaddr));
}
#define CP_COMMIT() asm volatile("cp.async.commit_group;" ::: "memory")
#define CP_WAIT(n)  asm volatile("cp.async.wait_group %0;" :: "n"(n) : "memory")

#define LDSM_X4(R0, R1, R2, R3, addr) \
    asm volatile("ldmatrix.sync.aligned.m8n8.x4.shared.b16 {%0,%1,%2,%3}, [%4];" \
                 : "=r"(R0), "=r"(R1), "=r"(R2), "=r"(R3) : "r"(addr))

#define LDSM_X4T(R0, R1, R2, R3, addr) \
    asm volatile("ldmatrix.sync.aligned.m8n8.x4.trans.shared.b16 {%0,%1,%2,%3}, [%4];" \
                 : "=r"(R0), "=r"(R1), "=r"(R2), "=r"(R3) : "r"(addr))

#define MMA16816(d, a, b0, b1) \
    asm volatile("mma.sync.aligned.m16n8k16.row.col.f32.bf16.bf16.f32 " \
                 "{%0,%1,%2,%3}, {%4,%5,%6,%7}, {%8,%9}, {%0,%1,%2,%3};" \
                 : "+f"((d)[0]), "+f"((d)[1]), "+f"((d)[2]), "+f"((d)[3]) \
                 : "r"((a)[0]), "r"((a)[1]), "r"((a)[2]), "r"((a)[3]),   \
                   "r"(b0), "r"(b1))

#define MMAH16816(d, a, b0, b1) \
    asm volatile("mma.sync.aligned.m16n8k16.row.col.f32.f16.f16.f32 " \
                 "{%0,%1,%2,%3}, {%4,%5,%6,%7}, {%8,%9}, {%0,%1,%2,%3};" \
                 : "+f"((d)[0]), "+f"((d)[1]), "+f"((d)[2]), "+f"((d)[3]) \
                 : "r"((a)[0]), "r"((a)[1]), "r"((a)[2]), "r"((a)[3]),   \
                   "r"(b0), "r"(b1))

// SW128 (Swizzle<3,4,3>) on byte offsets inside a 1024B-aligned tile
#define SW128(off) (((uint32_t)(off)) ^ ((((uint32_t)(off)) >> 3) & 0x70))

// ============================================================================
// Combined split: x/W_qkv/W_proj -> bf16 hi/lo ;  Er -> fp16 hi
// ============================================================================
#define NX4  1048576
#define NWQ4 786432
#define NWP4 262144
#define NER4 16384
#define NSPLIT4 (NX4 + NWQ4 + NWP4 + NER4)

__global__ void split_all(const float* __restrict__ x, const float* __restrict__ wq,
                          const float* __restrict__ wp, const float* __restrict__ er)
{
    int i = blockIdx.x * blockDim.x + threadIdx.x;
    if (i >= NSPLIT4) return;

    if (i >= NX4 + NWQ4 + NWP4) {           // Er -> fp16 (hi only)
        int j = i - NX4 - NWQ4 - NWP4;
        float4 v = ((const float4*)er)[j];
        ((__half2*)g_erh)[2*j]   = __floats2half2_rn(v.x, v.y);
        ((__half2*)g_erh)[2*j+1] = __floats2half2_rn(v.z, v.w);
        return;
    }

    const float* src;
    __nv_bfloat16 *hi, *lo;
    int j;
    if (i < NX4)             { src = x;  hi = g_xhi;  lo = g_xlo;  j = i; }
    else if (i < NX4 + NWQ4) { src = wq; hi = g_wqhi; lo = g_wqlo; j = i - NX4; }
    else                     { src = wp; hi = g_wphi; lo = g_wplo; j = i - NX4 - NWQ4; }

    float4 v = ((const float4*)src)[j];
    __nv_bfloat16 h0 = __float2bfloat16(v.x);
    __nv_bfloat16 h1 = __float2bfloat16(v.y);
    __nv_bfloat16 h2 = __float2bfloat16(v.z);
    __nv_bfloat16 h3 = __float2bfloat16(v.w);
    __nv_bfloat16 l0 = __float2bfloat16(v.x - __bfloat162float(h0));
    __nv_bfloat16 l1 = __float2bfloat16(v.y - __bfloat162float(h1));
    __nv_bfloat16 l2 = __float2bfloat16(v.z - __bfloat162float(h2));
    __nv_bfloat16 l3 = __float2bfloat16(v.w - __bfloat162float(h3));
    ((__nv_bfloat162*)hi)[2*j]   = __nv_bfloat162(h0, h1);
    ((__nv_bfloat162*)hi)[2*j+1] = __nv_bfloat162(h2, h3);
    ((__nv_bfloat162*)lo)[2*j]   = __nv_bfloat162(l0, l1);
    ((__nv_bfloat162*)lo)[2*j+1] = __nv_bfloat162(l2, l3);
}

// ============================================================================
// HMMA split-precision GEMM, FUSED stages: each stage loads {Ahi,Alo,Bhi,Blo}
// for one K=64 chunk (64KB) and runs all 3 products from resident tiles.
// 16 stages, 2-stage double buffer (128KB smem).
// MODE 0: QKV -> Q,K fp16 single; V fp16 hi/lo.   MODE 1: proj +bias fp32.
// ============================================================================
template<int MODE>
__global__ __launch_bounds__(256, 1)
void hmma_gemm(const float* __restrict__ bias, float* __restrict__ C)
{
    extern __shared__ char dynsm[];
    const uint32_t sbase = smem_u32(dynsm);

    const int tid  = threadIdx.x;
    const int wid  = tid >> 5;
    const int lane = tid & 31;
    const int wm = wid & 3;
    const int wn = wid >> 2;
    const int m0 = blockIdx.y * 128;
    const int n0 = blockIdx.x * 128;

    const __nv_bfloat16* Ahi = (MODE == 0) ? g_xhi : g_athi;
    const __nv_bfloat16* Alo = (MODE == 0) ? g_xlo : g_atlo;
    const __nv_bfloat16* Bhi = (MODE == 0) ? g_wqhi : g_wphi;
    const __nv_bfloat16* Blo = (MODE == 0) ? g_wqlo : g_wplo;

    float d[2][8][4];
#pragma unroll
    for (int mt = 0; mt < 2; mt++)
#pragma unroll
        for (int nt = 0; nt < 8; nt++)
#pragma unroll
            for (int r = 0; r < 4; r++) d[mt][nt][r] = 0.0f;

    // stage buffer: Ahi +0, Alo +16K, Bhi +32K, Blo +48K
    auto issue_stage = [&](int s) {
        const int kin = s * 64;
        const uint32_t stbase = sbase + (uint32_t)(s & 1) * 65536u;
#pragma unroll
        for (int t = 0; t < 16; t++) {
            int c    = tid + t * 256;
            int part = c >> 10;
            int row  = (c >> 3) & 127;
            int seg  = c & 7;
            const __nv_bfloat16* src = (part == 0) ? Ahi : (part == 1) ? Alo
                                     : (part == 2) ? Bhi : Blo;
            int r0 = (part >= 2) ? n0 : m0;
            cp_async16(stbase + (uint32_t)part * 16384u
                           + SW128((uint32_t)(row * 128 + seg * 16)),
                       src + (size_t)(r0 + row) * 1024 + kin + seg * 8);
        }
    };

    issue_stage(0); CP_COMMIT();

    for (int s = 0; s < 16; s++) {
        CP_WAIT(0);
        __syncthreads();   // stage s resident; all reads of buf (s&1) from s-2 done
        if (s + 1 < 16) { issue_stage(s + 1); CP_COMMIT(); }

        const uint32_t aHiB = sbase + (uint32_t)(s & 1) * 65536u;
        const uint32_t aLoB = aHiB + 16384u;
        const uint32_t bHiB = aHiB + 32768u;
        const uint32_t bLoB = aHiB + 49152u;

#pragma unroll
        for (int ks = 0; ks < 4; ks++) {
            const int kb = ks * 32;
            uint32_t aH[2][4], aL[2][4];
#pragma unroll
            for (int mt = 0; mt < 2; mt++) {
                int row = wm * 32 + mt * 16 + (lane & 15);
                uint32_t off = SW128((uint32_t)(row * 128 + kb + ((lane >> 4) << 4)));
                LDSM_X4(aH[mt][0], aH[mt][1], aH[mt][2], aH[mt][3], aHiB + off);
                LDSM_X4(aL[mt][0], aL[mt][1], aL[mt][2], aL[mt][3], aLoB + off);
            }
            uint32_t bb[4][4];
            // B hi: used by aH and aL
#pragma unroll
            for (int bt = 0; bt < 4; bt++) {
                int row = wn * 64 + bt * 16 + (lane & 7) + (((lane >> 4) & 1) << 3);
                uint32_t bd = bHiB + SW128((uint32_t)(row * 128 + kb + (((lane >> 3) & 1) << 4)));
                LDSM_X4(bb[bt][0], bb[bt][1], bb[bt][2], bb[bt][3], bd);
            }
#pragma unroll
            for (int mt = 0; mt < 2; mt++)
#pragma unroll
                for (int nt = 0; nt < 8; nt++) {
                    int bt = nt >> 1, pr = (nt & 1) << 1;
                    MMA16816(d[mt][nt], aH[mt], bb[bt][pr], bb[bt][pr + 1]);
                }
#pragma unroll
            for (int mt = 0; mt < 2; mt++)
#pragma unroll
                for (int nt = 0; nt < 8; nt++) {
                    int bt = nt >> 1, pr = (nt & 1) << 1;
                    MMA16816(d[mt][nt], aL[mt], bb[bt][pr], bb[bt][pr + 1]);
                }
            // B lo: used by aH
#pragma unroll
            for (int bt = 0; bt < 4; bt++) {
                int row = wn * 64 + bt * 16 + (lane & 7) + (((lane >> 4) & 1) << 3);
                uint32_t bd = bLoB + SW128((uint32_t)(row * 128 + kb + (((lane >> 3) & 1) << 4)));
                LDSM_X4(bb[bt][0], bb[bt][1], bb[bt][2], bb[bt][3], bd);
            }
#pragma unroll
            for (int mt = 0; mt < 2; mt++)
#pragma unroll
                for (int nt = 0; nt < 8; nt++) {
                    int bt = nt >> 1, pr = (nt & 1) << 1;
                    MMA16816(d[mt][nt], aH[mt], bb[bt][pr], bb[bt][pr + 1]);
                }
        }
    }

    // ---- epilogue ----
#pragma unroll
    for (int mt = 0; mt < 2; mt++) {
        int rbase = m0 + wm * 32 + mt * 16 + (lane >> 2);
#pragma unroll
        for (int nt = 0; nt < 8; nt++) {
            int f = n0 + wn * 64 + nt * 8 + (lane & 3) * 2;
#pragma unroll
            for (int half = 0; half < 2; half++) {
                int m = rbase + half * 8;
                float2 v = make_float2(d[mt][nt][half * 2], d[mt][nt][half * 2 + 1]);
                if (MODE == 0) {
                    int b_i = m >> 10, n = m & 1023;
                    int sec = f >> 10;
                    int hh = (f >> 6) & 15, dd = f & 63;
                    size_t idx = ((size_t)(b_i * NHEAD + hh) * NSEQ + n) * HD + dd;
                    if (sec == 2) {
                        __half h0 = __float2half_rn(v.x);
                        __half h1 = __float2half_rn(v.y);
                        __half l0 = __float2half_rn(v.x - __half2float(h0));
                        __half l1 = __float2half_rn(v.y - __half2float(h1));
                        *(__half2*)&g_Vh[idx] = __halves2half2(h0, h1);
                        *(__half2*)&g_Vl[idx] = __halves2half2(l0, l1);
                    } else {
                        __half* dst = (sec == 0) ? g_Qh : g_Kh;
                        *(__half2*)&dst[idx] = __floats2half2_rn(v.x, v.y);
                    }
                } else {
                    v.x += bias[f];
                    v.y += bias[f + 1];
                    *(float2*)&C[(size_t)m * DIMC + f] = v;
                }
            }
        }
    }
}

// ============================================================================
// Tensor-core fused causal flash attention with relative position term.
// fp16: S = Qh.Kh (1 pass), R = Qh.Ehi (1 pass), PV = Ph.(Vh + Vl) (2 passes).
// K/V double-buffered, E fp16 hi 4-slot ring.
// ============================================================================
#define OFF_Q    0u          // 16KB fp16
#define OFF_K    16384u      // 2 bufs x 8KB fp16
#define OFF_V    32768u      // 2 bufs x (8KB hi + 8KB lo) fp16
#define OFF_EHI  65536u      // 4 slots x 8KB fp16
#define OFF_R    98304u      // 8 warps x 1600 floats
#define ATTN_SMEM 149504

__global__ __launch_bounds__(256)
void attn_kernel()
{
    extern __shared__ char smc[];
    const uint32_t sb = smem_u32(smc);
    const int tid  = threadIdx.x;
    const int w    = tid >> 5;
    const int lane = tid & 31;
    const int bq = 7 - (int)blockIdx.x;     // heavy blocks first
    const int bh = blockIdx.y;
    const int n0 = bq * 128;

    const size_t bho = (size_t)bh * NSEQ * HD;
    const __half* Qg = g_Qh + bho;
    const __half* Kg = g_Kh + bho;
    const __half* Vhg = g_Vh + bho;
    const __half* Vlg = g_Vl + bho;

    const int base0 = NSEQ - 128 - n0;      // 64-aligned, >= 0
    const int c0 = base0 >> 6;              // first E chunk index

    // ---- load Q (128 rows fp16, 16KB) ----
#pragma unroll
    for (int t = 0; t < 4; t++) {
        int c = tid + t * 256;
        int row = c >> 3;
        int seg = c & 7;
        cp_async16(sb + OFF_Q + SW128(row * 128 + seg * 16),
                   Qg + (size_t)(n0 + row) * HD + seg * 8);
    }

    auto issueK = [&](int kt) {
        const int km0 = kt * 64;
        const uint32_t kB = OFF_K + (uint32_t)(kt & 1) * 8192u;
#pragma unroll
        for (int t = 0; t < 2; t++) {
            int c = tid + t * 256;
            int row = c >> 3;
            int seg = c & 7;
            cp_async16(sb + kB + SW128(row * 128 + seg * 16),
                       Kg + (size_t)(km0 + row) * HD + seg * 8);
        }
    };
    auto issueV = [&](int kt) {
        const int km0 = kt * 64;
        const uint32_t vB = OFF_V + (uint32_t)(kt & 1) * 16384u;
#pragma unroll
        for (int t = 0; t < 4; t++) {
            int c = tid + t * 256;
            int buf = c >> 9;
            int row = (c >> 3) & 63;
            int seg = c & 7;
            const __half* src = buf ? Vlg : Vhg;
            cp_async16(sb + vB + (buf ? 8192u : 0u) + SW128(row * 128 + seg * 16),
                       src + (size_t)(km0 + row) * HD + seg * 8);
        }
    };
    auto issueEchunk = [&](int ci) {
        const int rb = ci << 6;
        const uint32_t slot = ((uint32_t)ci & 3u) * 8192u;
#pragma unroll
        for (int t = 0; t < 2; t++) {
            int c = tid + t * 256;
            int row = c >> 3;
            int seg = c & 7;
            int r = rb + row;
            uint32_t off = OFF_EHI + slot + SW128(row * 128 + seg * 16);
            if (r < NSEQ) {
                cp_async16(sb + off, g_erh + (size_t)r * HD + seg * 8);
            } else {
                *(uint4*)(smc + off) = make_uint4(0u, 0u, 0u, 0u);
            }
        }
    };

    issueK(0); issueV(0);
    issueEchunk(c0); issueEchunk(c0 + 1); issueEchunk(c0 + 2);
    CP_COMMIT();

    float mrow[2] = {-1e30f, -1e30f};
    float lrow[2] = {0.0f, 0.0f};
    float O[8][4];
#pragma unroll
    for (int nt = 0; nt < 8; nt++)
#pragma unroll
        for (int r = 0; r < 4; r++) O[nt][r] = 0.0f;

    const int t0w = 112 - 16 * w;
    const int ktmax = 2 * bq + 1;
    const int eRow0 = base0 + t0w + (lane & 7) + (((lane >> 4) & 1) << 3);

    float* sRd = (float*)(smc + OFF_R) + w * 1600;

    for (int kt = 0; kt <= ktmax; kt++) {
        const int km0 = kt * 64;
        CP_WAIT(0);
        __syncthreads();    // K/E/V(kt) (+Q first iter) visible; prior reads done

        float S[8][4], R[10][4];
#pragma unroll
        for (int nt = 0; nt < 8; nt++)
#pragma unroll
            for (int r = 0; r < 4; r++) S[nt][r] = 0.0f;
#pragma unroll
        for (int nt = 0; nt < 10; nt++)
#pragma unroll
            for (int r = 0; r < 4; r++) R[nt][r] = 0.0f;

        const int eRowK = eRow0 + km0;
        const uint32_t kB   = sb + OFF_K + (uint32_t)(kt & 1) * 8192u;
        const uint32_t eHiB = sb + OFF_EHI;

        // ---- S = Qh.Kh^T and R = Qh.Ehi^T (single pass each) ----
#pragma unroll
        for (int ks = 0; ks < 4; ks++) {
            const int kb = ks * 32;
            const int arow = 16 * w + (lane & 15);
            uint32_t aH[4];
            LDSM_X4(aH[0], aH[1], aH[2], aH[3],
                    sb + OFF_Q + SW128(arow * 128 + kb + ((lane >> 4) << 4)));

            uint32_t bb[5][4];
#pragma unroll
            for (int bt = 0; bt < 4; bt++) {
                int row = bt * 16 + (lane & 7) + (((lane >> 4) & 1) << 3);
                uint32_t bd = kB + SW128(row * 128 + kb + (((lane >> 3) & 1) << 4));
                LDSM_X4(bb[bt][0], bb[bt][1], bb[bt][2], bb[bt][3], bd);
            }
#pragma unroll
            for (int nt = 0; nt < 8; nt++) {
                int bt = nt >> 1, pr = (nt & 1) << 1;
                MMAH16816(S[nt], aH, bb[bt][pr], bb[bt][pr + 1]);
            }
#pragma unroll
            for (int bt = 0; bt < 5; bt++) {
                int r = eRowK + bt * 16;
                uint32_t bd = eHiB + (((uint32_t)(r >> 6) & 3u) * 8192u)
                            + SW128((r & 63) * 128 + kb + (((lane >> 3) & 1) << 4));
                LDSM_X4(bb[bt][0], bb[bt][1], bb[bt][2], bb[bt][3], bd);
            }
#pragma unroll
            for (int nt = 0; nt < 10; nt++) {
                int bt = nt >> 1, pr = (nt & 1) << 1;
                MMAH16816(R[nt], aH, bb[bt][pr], bb[bt][pr + 1]);
            }
        }

        // ---- prefetch next tile (disjoint buffers/slots; no sync needed) ----
        if (kt < ktmax) {
            issueK(kt + 1); issueV(kt + 1); issueEchunk(c0 + kt + 3);
            CP_COMMIT();
        }

        // ---- store R diagonal-shifted: (r,c) -> idx 101*r + c + 1 ----
        {
            int r0 = lane >> 2;
#pragma unroll
            for (int nt = 0; nt < 10; nt++) {
                int cA = nt * 8 + (lane & 3) * 2;
                int i0 = 101 * r0 + cA + 1;
                sRd[i0]     = R[nt][0];
                sRd[i0 + 1] = R[nt][1];
                int i1 = i0 + 101 * 8;
                sRd[i1]     = R[nt][2];
                sRd[i1 + 1] = R[nt][3];
            }
        }
        __syncwarp();

        // ---- gather rel (aligned float2 at il*100 + j0 + 16), scale, mask ----
        const bool maskt = (kt >= 2 * bq);
#pragma unroll
        for (int nt = 0; nt < 8; nt++) {
            int j0 = nt * 8 + (lane & 3) * 2;
#pragma unroll
            for (int h = 0; h < 2; h++) {
                int il = (lane >> 2) + 8 * h;
                float2 rv = *(const float2*)&sRd[il * 100 + j0 + 16];
                float s0 = (S[nt][2 * h]     + rv.x) * 0.125f;
                float s1 = (S[nt][2 * h + 1] + rv.y) * 0.125f;
                if (maskt) {
                    int ig = n0 + 16 * w + il;
                    int jg = km0 + j0;
                    if (jg > ig)     s0 = -1e30f;
                    if (jg + 1 > ig) s1 = -1e30f;
                }
                S[nt][2 * h]     = s0;
                S[nt][2 * h + 1] = s1;
            }
        }

        // ---- online softmax (rows warp-local; quad = 4 lanes per row) ----
        float alpha[2];
#pragma unroll
        for (int h = 0; h < 2; h++) {
            float v = -1e30f;
#pragma unroll
            for (int nt = 0; nt < 8; nt++)
                v = fmaxf(v, fmaxf(S[nt][2 * h], S[nt][2 * h + 1]));
            v = fmaxf(v, __shfl_xor_sync(0xffffffffu, v, 1));
            v = fmaxf(v, __shfl_xor_sync(0xffffffffu, v, 2));
            float mnew = fmaxf(mrow[h], v);
            alpha[h] = __expf(mrow[h] - mnew);
            mrow[h] = mnew;
        }
        float rsum[2] = {0.0f, 0.0f};
#pragma unroll
        for (int nt = 0; nt < 8; nt++)
#pragma unroll
            for (int h = 0; h < 2; h++) {
                float p0 = __expf(S[nt][2 * h]     - mrow[h]);
                float p1 = __expf(S[nt][2 * h + 1] - mrow[h]);
                S[nt][2 * h] = p0; S[nt][2 * h + 1] = p1;
                rsum[h] += p0 + p1;
            }
#pragma unroll
        for (int h = 0; h < 2; h++) {
            rsum[h] += __shfl_xor_sync(0xffffffffu, rsum[h], 1);
            rsum[h] += __shfl_xor_sync(0xffffffffu, rsum[h], 2);
            lrow[h] = lrow[h] * alpha[h] + rsum[h];
        }
#pragma unroll
        for (int nt = 0; nt < 8; nt++) {
            O[nt][0] *= alpha[0]; O[nt][1] *= alpha[0];
            O[nt][2] *= alpha[1]; O[nt][3] *= alpha[1];
        }

        // ---- pack P single fp16 in registers (S-frag layout == A-frag) ----
        uint32_t PH[8][2];
#pragma unroll
        for (int nt = 0; nt < 8; nt++) {
#pragma unroll
            for (int pr = 0; pr < 2; pr++) {
                __half2 hh = __floats2half2_rn(S[nt][2 * pr], S[nt][2 * pr + 1]);
                PH[nt][pr] = *(uint32_t*)&hh;
            }
        }

        // ---- O += P.(Vh + Vl)  (fp16, 2 passes) ----
        const uint32_t vHiB = sb + OFF_V + (uint32_t)(kt & 1) * 16384u;
        const uint32_t vLoB = vHiB + 8192u;
#pragma unroll
        for (int ks = 0; ks < 4; ks++) {
            uint32_t aP[4] = {PH[2*ks][0], PH[2*ks][1], PH[2*ks+1][0], PH[2*ks+1][1]};
            int row = ks * 16 + (lane & 15);
#pragma unroll
            for (int bt = 0; bt < 4; bt++) {
                uint32_t bd = vHiB + SW128(row * 128 + bt * 32 + ((lane >> 4) << 4));
                uint32_t r0, r1, r2, r3;
                LDSM_X4T(r0, r1, r2, r3, bd);
                MMAH16816(O[2*bt],     aP, r0, r1);
                MMAH16816(O[2*bt + 1], aP, r2, r3);
            }
#pragma unroll
            for (int bt = 0; bt < 4; bt++) {
                uint32_t bd = vLoB + SW128(row * 128 + bt * 32 + ((lane >> 4) << 4));
                uint32_t r0, r1, r2, r3;
                LDSM_X4T(r0, r1, r2, r3, bd);
                MMAH16816(O[2*bt],     aP, r0, r1);
                MMAH16816(O[2*bt + 1], aP, r2, r3);
            }
        }
    }

    // ---- epilogue: O /= l, split bf16 hi/lo -> g_at{hi,lo}[b][n][h*64+d] ----
    const int b_i = bh >> 4, hhead = bh & 15;
    float inv[2] = {1.0f / lrow[0], 1.0f / lrow[1]};
#pragma unroll
    for (int nt = 0; nt < 8; nt++) {
        int c = hhead * 64 + nt * 8 + (lane & 3) * 2;
#pragma unroll
        for (int h = 0; h < 2; h++) {
            int n = n0 + 16 * w + (lane >> 2) + 8 * h;
            float o0 = O[nt][2 * h] * inv[h];
            float o1 = O[nt][2 * h + 1] * inv[h];
            __nv_bfloat16 h0 = __float2bfloat16(o0);
            __nv_bfloat16 h1 = __float2bfloat16(o1);
            __nv_bfloat16 l0 = __float2bfloat16(o0 - __bfloat162float(h0));
            __nv_bfloat16 l1 = __float2bfloat16(o1 - __bfloat162float(h1));
            size_t idx = ((size_t)b_i * NSEQ + n) * DIMC + c;
            *(__nv_bfloat162*)&g_athi[idx] = __nv_bfloat162(h0, h1);
            *(__nv_bfloat162*)&g_atlo[idx] = __nv_bfloat162(l0, l1);
        }
    }
}

// ============================================================================
extern "C" void kernel_launch(void* const* d_in, const int* in_sizes, int n_in,
                              void* d_out, int out_size)
{
    const float* x      = (const float*)d_in[0];
    const float* W_qkv  = (const float*)d_in[1];
    const float* W_proj = (const float*)d_in[2];
    const float* b_proj = (const float*)d_in[3];
    const float* Er     = (const float*)d_in[4];
    float* out = (float*)d_out;

    // 0) splits (single launch)
    split_all<<<(NSPLIT4 + 255) / 256, 256>>>(x, W_qkv, W_proj, Er);

    // 1) QKV via fused HMMA: M=4096, N=3072 (2-stage x 64KB = 128 KB)
    const int gsmem = 2 * 65536;
    cudaFuncSetAttribute(hmma_gemm<0>,
                         cudaFuncAttributeMaxDynamicSharedMemorySize, gsmem);
    cudaFuncSetAttribute(hmma_gemm<1>,
                         cudaFuncAttributeMaxDynamicSharedMemorySize, gsmem);
    hmma_gemm<0><<<dim3(24, 32), 256, gsmem>>>(nullptr, nullptr);

    // 2) tensor-core fused attention (8 q-blocks x 64 bh)
    cudaFuncSetAttribute(attn_kernel,
                         cudaFuncAttributeMaxDynamicSharedMemorySize, ATTN_SMEM);
    attn_kernel<<<dim3(8, 64), 256, ATTN_SMEM>>>();

    // 3) proj via fused HMMA: M=4096, N=1024, +bias
    hmma_gemm<1><<<dim3(8, 32), 256, gsmem>>>(b_proj, out);
}

// round 13
// speedup vs baseline: 4.5036x; 1.2837x over previous
#include <cuda_runtime.h>
#include <cuda_bf16.h>
#include <cuda_fp16.h>
#include <cstdint>

#define DIMC  1024
#define NSEQ  1024
#define BATCH 4
#define NHEAD 16
#define HD    64
#define BHTOT (BATCH*NHEAD)

// ---------------- scratch (device globals; no allocation at runtime) ----------
__device__ __half g_Qh[(size_t)BHTOT*NSEQ*HD];          // fp16 single
__device__ __half g_Kh[(size_t)BHTOT*NSEQ*HD];          // fp16 single
__device__ __half g_Vh[(size_t)BHTOT*NSEQ*HD];          // fp16 split
__device__ __half g_Vl[(size_t)BHTOT*NSEQ*HD];

__device__ __half g_xh[(size_t)BATCH*NSEQ*DIMC];        // fp16 split
__device__ __half g_xl[(size_t)BATCH*NSEQ*DIMC];
__device__ __half g_wqh[(size_t)3*DIMC*DIMC];
__device__ __half g_wql[(size_t)3*DIMC*DIMC];
__device__ __half g_wph[(size_t)DIMC*DIMC];
__device__ __half g_wpl[(size_t)DIMC*DIMC];
__device__ __half g_ath[(size_t)BATCH*NSEQ*DIMC];
__device__ __half g_atl[(size_t)BATCH*NSEQ*DIMC];
__device__ __half g_erh[(size_t)NSEQ*HD];               // fp16 hi

// ---------------- helpers ------------------------------------------------------
__device__ __forceinline__ uint32_t smem_u32(const void* p) {
    uint32_t a;
    asm("{ .reg .u64 t; cvta.to.shared.u64 t, %1; cvt.u32.u64 %0, t; }"
        : "=r"(a) : "l"(p));
    return a;
}

__device__ __forceinline__ void cp_async16(uint32_t saddr, const void* gaddr) {
    asm volatile("cp.async.cg.shared.global [%0], [%1], 16;"
                 :: "r"(saddr), "l"(gaddr));
}
#define CP_COMMIT() asm volatile("cp.async.commit_group;" ::: "memory")
#define CP_WAIT(n)  asm volatile("cp.async.wait_group %0;" :: "n"(n) : "memory")

#define LDSM_X4(R0, R1, R2, R3, addr) \
    asm volatile("ldmatrix.sync.aligned.m8n8.x4.shared.b16 {%0,%1,%2,%3}, [%4];" \
                 : "=r"(R0), "=r"(R1), "=r"(R2), "=r"(R3) : "r"(addr))

#define LDSM_X4T(R0, R1, R2, R3, addr) \
    asm volatile("ldmatrix.sync.aligned.m8n8.x4.trans.shared.b16 {%0,%1,%2,%3}, [%4];" \
                 : "=r"(R0), "=r"(R1), "=r"(R2), "=r"(R3) : "r"(addr))

#define MMAH16816(d, a, b0, b1) \
    asm volatile("mma.sync.aligned.m16n8k16.row.col.f32.f16.f16.f32 " \
                 "{%0,%1,%2,%3}, {%4,%5,%6,%7}, {%8,%9}, {%0,%1,%2,%3};" \
                 : "+f"((d)[0]), "+f"((d)[1]), "+f"((d)[2]), "+f"((d)[3]) \
                 : "r"((a)[0]), "r"((a)[1]), "r"((a)[2]), "r"((a)[3]),   \
                   "r"(b0), "r"(b1))

// SW128 (Swizzle<3,4,3>) on byte offsets inside a 1024B-aligned tile
#define SW128(off) (((uint32_t)(off)) ^ ((((uint32_t)(off)) >> 3) & 0x70))

// ============================================================================
// Combined split: x/W_qkv/W_proj -> fp16 hi/lo ;  Er -> fp16 hi
// ============================================================================
#define NX4  1048576
#define NWQ4 786432
#define NWP4 262144
#define NER4 16384
#define NSPLIT4 (NX4 + NWQ4 + NWP4 + NER4)

__global__ void split_all(const float* __restrict__ x, const float* __restrict__ wq,
                          const float* __restrict__ wp, const float* __restrict__ er)
{
    int i = blockIdx.x * blockDim.x + threadIdx.x;
    if (i >= NSPLIT4) return;

    if (i >= NX4 + NWQ4 + NWP4) {           // Er -> fp16 (hi only)
        int j = i - NX4 - NWQ4 - NWP4;
        float4 v = ((const float4*)er)[j];
        ((__half2*)g_erh)[2*j]   = __floats2half2_rn(v.x, v.y);
        ((__half2*)g_erh)[2*j+1] = __floats2half2_rn(v.z, v.w);
        return;
    }

    const float* src;
    __half *hi, *lo;
    int j;
    if (i < NX4)             { src = x;  hi = g_xh;  lo = g_xl;  j = i; }
    else if (i < NX4 + NWQ4) { src = wq; hi = g_wqh; lo = g_wql; j = i - NX4; }
    else                     { src = wp; hi = g_wph; lo = g_wpl; j = i - NX4 - NWQ4; }

    float4 v = ((const float4*)src)[j];
    __half h0 = __float2half_rn(v.x);
    __half h1 = __float2half_rn(v.y);
    __half h2 = __float2half_rn(v.z);
    __half h3 = __float2half_rn(v.w);
    __half l0 = __float2half_rn(v.x - __half2float(h0));
    __half l1 = __float2half_rn(v.y - __half2float(h1));
    __half l2 = __float2half_rn(v.z - __half2float(h2));
    __half l3 = __float2half_rn(v.w - __half2float(h3));
    ((__half2*)hi)[2*j]   = __halves2half2(h0, h1);
    ((__half2*)hi)[2*j+1] = __halves2half2(h2, h3);
    ((__half2*)lo)[2*j]   = __halves2half2(l0, l1);
    ((__half2*)lo)[2*j+1] = __halves2half2(l2, l3);
}

// ============================================================================
// HMMA fp16 2-product GEMM: C = (Ah+Al) * Bh^T  (drops Ah*Bl, rel ~2.8e-4).
// Stage loads {Ah, Al, Bh} for one K=64 chunk (48KB); 2-stage ring (96KB).
// 16 stages. 2 CTAs/SM (reg cap 128).
// MODE 0: QKV -> Q,K fp16 single; V fp16 hi/lo.   MODE 1: proj +bias fp32.
// ============================================================================
template<int MODE>
__global__ __launch_bounds__(256, 2)
void hmma_gemm(const float* __restrict__ bias, float* __restrict__ C)
{
    extern __shared__ char dynsm[];
    const uint32_t sbase = smem_u32(dynsm);

    const int tid  = threadIdx.x;
    const int wid  = tid >> 5;
    const int lane = tid & 31;
    const int wm = wid & 3;
    const int wn = wid >> 2;
    const int m0 = blockIdx.y * 128;
    const int n0 = blockIdx.x * 128;

    const __half* Ahi = (MODE == 0) ? g_xh : g_ath;
    const __half* Alo = (MODE == 0) ? g_xl : g_atl;
    const __half* Bhi = (MODE == 0) ? g_wqh : g_wph;

    float d[2][8][4];
#pragma unroll
    for (int mt = 0; mt < 2; mt++)
#pragma unroll
        for (int nt = 0; nt < 8; nt++)
#pragma unroll
            for (int r = 0; r < 4; r++) d[mt][nt][r] = 0.0f;

    // stage buffer: Ah +0, Al +16K, Bh +32K  (48KB per stage)
    auto issue_stage = [&](int s) {
        const int kin = s * 64;
        const uint32_t stbase = sbase + (uint32_t)(s & 1) * 49152u;
#pragma unroll
        for (int t = 0; t < 12; t++) {
            int c    = tid + t * 256;
            int part = c >> 10;
            int row  = (c >> 3) & 127;
            int seg  = c & 7;
            const __half* src = (part == 0) ? Ahi : (part == 1) ? Alo : Bhi;
            int r0 = (part == 2) ? n0 : m0;
            cp_async16(stbase + (uint32_t)part * 16384u
                           + SW128((uint32_t)(row * 128 + seg * 16)),
                       src + (size_t)(r0 + row) * 1024 + kin + seg * 8);
        }
    };

    issue_stage(0); CP_COMMIT();

    for (int s = 0; s < 16; s++) {
        CP_WAIT(0);
        __syncthreads();   // stage s resident; all reads of buf (s&1) from s-2 done
        if (s + 1 < 16) { issue_stage(s + 1); CP_COMMIT(); }

        const uint32_t aHiB = sbase + (uint32_t)(s & 1) * 49152u;
        const uint32_t aLoB = aHiB + 16384u;
        const uint32_t bHiB = aHiB + 32768u;

#pragma unroll
        for (int ks = 0; ks < 4; ks++) {
            const int kb = ks * 32;
            uint32_t aH[2][4], aL[2][4];
#pragma unroll
            for (int mt = 0; mt < 2; mt++) {
                int row = wm * 32 + mt * 16 + (lane & 15);
                uint32_t off = SW128((uint32_t)(row * 128 + kb + ((lane >> 4) << 4)));
                LDSM_X4(aH[mt][0], aH[mt][1], aH[mt][2], aH[mt][3], aHiB + off);
                LDSM_X4(aL[mt][0], aL[mt][1], aL[mt][2], aL[mt][3], aLoB + off);
            }
            uint32_t bb[4][4];
#pragma unroll
            for (int bt = 0; bt < 4; bt++) {
                int row = wn * 64 + bt * 16 + (lane & 7) + (((lane >> 4) & 1) << 3);
                uint32_t bd = bHiB + SW128((uint32_t)(row * 128 + kb + (((lane >> 3) & 1) << 4)));
                LDSM_X4(bb[bt][0], bb[bt][1], bb[bt][2], bb[bt][3], bd);
            }
#pragma unroll
            for (int mt = 0; mt < 2; mt++)
#pragma unroll
                for (int nt = 0; nt < 8; nt++) {
                    int bt = nt >> 1, pr = (nt & 1) << 1;
                    MMAH16816(d[mt][nt], aH[mt], bb[bt][pr], bb[bt][pr + 1]);
                }
#pragma unroll
            for (int mt = 0; mt < 2; mt++)
#pragma unroll
                for (int nt = 0; nt < 8; nt++) {
                    int bt = nt >> 1, pr = (nt & 1) << 1;
                    MMAH16816(d[mt][nt], aL[mt], bb[bt][pr], bb[bt][pr + 1]);
                }
        }
    }

    // ---- epilogue ----
#pragma unroll
    for (int mt = 0; mt < 2; mt++) {
        int rbase = m0 + wm * 32 + mt * 16 + (lane >> 2);
#pragma unroll
        for (int nt = 0; nt < 8; nt++) {
            int f = n0 + wn * 64 + nt * 8 + (lane & 3) * 2;
#pragma unroll
            for (int half = 0; half < 2; half++) {
                int m = rbase + half * 8;
                float2 v = make_float2(d[mt][nt][half * 2], d[mt][nt][half * 2 + 1]);
                if (MODE == 0) {
                    int b_i = m >> 10, n = m & 1023;
                    int sec = f >> 10;
                    int hh = (f >> 6) & 15, dd = f & 63;
                    size_t idx = ((size_t)(b_i * NHEAD + hh) * NSEQ + n) * HD + dd;
                    if (sec == 2) {
                        __half h0 = __float2half_rn(v.x);
                        __half h1 = __float2half_rn(v.y);
                        __half l0 = __float2half_rn(v.x - __half2float(h0));
                        __half l1 = __float2half_rn(v.y - __half2float(h1));
                        *(__half2*)&g_Vh[idx] = __halves2half2(h0, h1);
                        *(__half2*)&g_Vl[idx] = __halves2half2(l0, l1);
                    } else {
                        __half* dst = (sec == 0) ? g_Qh : g_Kh;
                        *(__half2*)&dst[idx] = __floats2half2_rn(v.x, v.y);
                    }
                } else {
                    v.x += bias[f];
                    v.y += bias[f + 1];
                    *(float2*)&C[(size_t)m * DIMC + f] = v;
                }
            }
        }
    }
}

// ============================================================================
// Tensor-core fused causal flash attention with relative position term.
// fp16: S = Qh.Kh (1 pass), R = Qh.Ehi (1 pass), PV = Ph.(Vh + Vl) (2 passes).
// K/V double-buffered, E fp16 hi 4-slot ring.
// ============================================================================
#define OFF_Q    0u          // 16KB fp16
#define OFF_K    16384u      // 2 bufs x 8KB fp16
#define OFF_V    32768u      // 2 bufs x (8KB hi + 8KB lo) fp16
#define OFF_EHI  65536u      // 4 slots x 8KB fp16
#define OFF_R    98304u      // 8 warps x 1600 floats
#define ATTN_SMEM 149504

__global__ __launch_bounds__(256)
void attn_kernel()
{
    extern __shared__ char smc[];
    const uint32_t sb = smem_u32(smc);
    const int tid  = threadIdx.x;
    const int w    = tid >> 5;
    const int lane = tid & 31;
    const int bq = 7 - (int)blockIdx.x;     // heavy blocks first
    const int bh = blockIdx.y;
    const int n0 = bq * 128;

    const size_t bho = (size_t)bh * NSEQ * HD;
    const __half* Qg = g_Qh + bho;
    const __half* Kg = g_Kh + bho;
    const __half* Vhg = g_Vh + bho;
    const __half* Vlg = g_Vl + bho;

    const int base0 = NSEQ - 128 - n0;      // 64-aligned, >= 0
    const int c0 = base0 >> 6;              // first E chunk index

    // ---- load Q (128 rows fp16, 16KB) ----
#pragma unroll
    for (int t = 0; t < 4; t++) {
        int c = tid + t * 256;
        int row = c >> 3;
        int seg = c & 7;
        cp_async16(sb + OFF_Q + SW128(row * 128 + seg * 16),
                   Qg + (size_t)(n0 + row) * HD + seg * 8);
    }

    auto issueK = [&](int kt) {
        const int km0 = kt * 64;
        const uint32_t kB = OFF_K + (uint32_t)(kt & 1) * 8192u;
#pragma unroll
        for (int t = 0; t < 2; t++) {
            int c = tid + t * 256;
            int row = c >> 3;
            int seg = c & 7;
            cp_async16(sb + kB + SW128(row * 128 + seg * 16),
                       Kg + (size_t)(km0 + row) * HD + seg * 8);
        }
    };
    auto issueV = [&](int kt) {
        const int km0 = kt * 64;
        const uint32_t vB = OFF_V + (uint32_t)(kt & 1) * 16384u;
#pragma unroll
        for (int t = 0; t < 4; t++) {
            int c = tid + t * 256;
            int buf = c >> 9;
            int row = (c >> 3) & 63;
            int seg = c & 7;
            const __half* src = buf ? Vlg : Vhg;
            cp_async16(sb + vB + (buf ? 8192u : 0u) + SW128(row * 128 + seg * 16),
                       src + (size_t)(km0 + row) * HD + seg * 8);
        }
    };
    auto issueEchunk = [&](int ci) {
        const int rb = ci << 6;
        const uint32_t slot = ((uint32_t)ci & 3u) * 8192u;
#pragma unroll
        for (int t = 0; t < 2; t++) {
            int c = tid + t * 256;
            int row = c >> 3;
            int seg = c & 7;
            int r = rb + row;
            uint32_t off = OFF_EHI + slot + SW128(row * 128 + seg * 16);
            if (r < NSEQ) {
                cp_async16(sb + off, g_erh + (size_t)r * HD + seg * 8);
            } else {
                *(uint4*)(smc + off) = make_uint4(0u, 0u, 0u, 0u);
            }
        }
    };

    issueK(0); issueV(0);
    issueEchunk(c0); issueEchunk(c0 + 1); issueEchunk(c0 + 2);
    CP_COMMIT();

    float mrow[2] = {-1e30f, -1e30f};
    float lrow[2] = {0.0f, 0.0f};
    float O[8][4];
#pragma unroll
    for (int nt = 0; nt < 8; nt++)
#pragma unroll
        for (int r = 0; r < 4; r++) O[nt][r] = 0.0f;

    const int t0w = 112 - 16 * w;
    const int ktmax = 2 * bq + 1;
    const int eRow0 = base0 + t0w + (lane & 7) + (((lane >> 4) & 1) << 3);

    float* sRd = (float*)(smc + OFF_R) + w * 1600;

    for (int kt = 0; kt <= ktmax; kt++) {
        const int km0 = kt * 64;
        CP_WAIT(0);
        __syncthreads();    // K/E/V(kt) (+Q first iter) visible; prior reads done

        float S[8][4], R[10][4];
#pragma unroll
        for (int nt = 0; nt < 8; nt++)
#pragma unroll
            for (int r = 0; r < 4; r++) S[nt][r] = 0.0f;
#pragma unroll
        for (int nt = 0; nt < 10; nt++)
#pragma unroll
            for (int r = 0; r < 4; r++) R[nt][r] = 0.0f;

        const int eRowK = eRow0 + km0;
        const uint32_t kB   = sb + OFF_K + (uint32_t)(kt & 1) * 8192u;
        const uint32_t eHiB = sb + OFF_EHI;

        // ---- S = Qh.Kh^T and R = Qh.Ehi^T (single pass each) ----
#pragma unroll
        for (int ks = 0; ks < 4; ks++) {
            const int kb = ks * 32;
            const int arow = 16 * w + (lane & 15);
            uint32_t aH[4];
            LDSM_X4(aH[0], aH[1], aH[2], aH[3],
                    sb + OFF_Q + SW128(arow * 128 + kb + ((lane >> 4) << 4)));

            uint32_t bb[5][4];
#pragma unroll
            for (int bt = 0; bt < 4; bt++) {
                int row = bt * 16 + (lane & 7) + (((lane >> 4) & 1) << 3);
                uint32_t bd = kB + SW128(row * 128 + kb + (((lane >> 3) & 1) << 4));
                LDSM_X4(bb[bt][0], bb[bt][1], bb[bt][2], bb[bt][3], bd);
            }
#pragma unroll
            for (int nt = 0; nt < 8; nt++) {
                int bt = nt >> 1, pr = (nt & 1) << 1;
                MMAH16816(S[nt], aH, bb[bt][pr], bb[bt][pr + 1]);
            }
#pragma unroll
            for (int bt = 0; bt < 5; bt++) {
                int r = eRowK + bt * 16;
                uint32_t bd = eHiB + (((uint32_t)(r >> 6) & 3u) * 8192u)
                            + SW128((r & 63) * 128 + kb + (((lane >> 3) & 1) << 4));
                LDSM_X4(bb[bt][0], bb[bt][1], bb[bt][2], bb[bt][3], bd);
            }
#pragma unroll
            for (int nt = 0; nt < 10; nt++) {
                int bt = nt >> 1, pr = (nt & 1) << 1;
                MMAH16816(R[nt], aH, bb[bt][pr], bb[bt][pr + 1]);
            }
        }

        // ---- prefetch next tile (disjoint buffers/slots; no sync needed) ----
        if (kt < ktmax) {
            issueK(kt + 1); issueV(kt + 1); issueEchunk(c0 + kt + 3);
            CP_COMMIT();
        }

        // ---- store R diagonal-shifted: (r,c) -> idx 101*r + c + 1 ----
        {
            int r0 = lane >> 2;
#pragma unroll
            for (int nt = 0; nt < 10; nt++) {
                int cA = nt * 8 + (lane & 3) * 2;
                int i0 = 101 * r0 + cA + 1;
                sRd[i0]     = R[nt][0];
                sRd[i0 + 1] = R[nt][1];
                int i1 = i0 + 101 * 8;
                sRd[i1]     = R[nt][2];
                sRd[i1 + 1] = R[nt][3];
            }
        }
        __syncwarp();

        // ---- gather rel (aligned float2 at il*100 + j0 + 16), scale, mask ----
        const bool maskt = (kt >= 2 * bq);
#pragma unroll
        for (int nt = 0; nt < 8; nt++) {
            int j0 = nt * 8 + (lane & 3) * 2;
#pragma unroll
            for (int h = 0; h < 2; h++) {
                int il = (lane >> 2) + 8 * h;
                float2 rv = *(const float2*)&sRd[il * 100 + j0 + 16];
                float s0 = (S[nt][2 * h]     + rv.x) * 0.125f;
                float s1 = (S[nt][2 * h + 1] + rv.y) * 0.125f;
                if (maskt) {
                    int ig = n0 + 16 * w + il;
                    int jg = km0 + j0;
                    if (jg > ig)     s0 = -1e30f;
                    if (jg + 1 > ig) s1 = -1e30f;
                }
                S[nt][2 * h]     = s0;
                S[nt][2 * h + 1] = s1;
            }
        }

        // ---- online softmax (rows warp-local; quad = 4 lanes per row) ----
        float alpha[2];
#pragma unroll
        for (int h = 0; h < 2; h++) {
            float v = -1e30f;
#pragma unroll
            for (int nt = 0; nt < 8; nt++)
                v = fmaxf(v, fmaxf(S[nt][2 * h], S[nt][2 * h + 1]));
            v = fmaxf(v, __shfl_xor_sync(0xffffffffu, v, 1));
            v = fmaxf(v, __shfl_xor_sync(0xffffffffu, v, 2));
            float mnew = fmaxf(mrow[h], v);
            alpha[h] = __expf(mrow[h] - mnew);
            mrow[h] = mnew;
        }
        float rsum[2] = {0.0f, 0.0f};
#pragma unroll
        for (int nt = 0; nt < 8; nt++)
#pragma unroll
            for (int h = 0; h < 2; h++) {
                float p0 = __expf(S[nt][2 * h]     - mrow[h]);
                float p1 = __expf(S[nt][2 * h + 1] - mrow[h]);
                S[nt][2 * h] = p0; S[nt][2 * h + 1] = p1;
                rsum[h] += p0 + p1;
            }
#pragma unroll
        for (int h = 0; h < 2; h++) {
            rsum[h] += __shfl_xor_sync(0xffffffffu, rsum[h], 1);
            rsum[h] += __shfl_xor_sync(0xffffffffu, rsum[h], 2);
            lrow[h] = lrow[h] * alpha[h] + rsum[h];
        }
#pragma unroll
        for (int nt = 0; nt < 8; nt++) {
            O[nt][0] *= alpha[0]; O[nt][1] *= alpha[0];
            O[nt][2] *= alpha[1]; O[nt][3] *= alpha[1];
        }

        // ---- pack P single fp16 in registers (S-frag layout == A-frag) ----
        uint32_t PH[8][2];
#pragma unroll
        for (int nt = 0; nt < 8; nt++) {
#pragma unroll
            for (int pr = 0; pr < 2; pr++) {
                __half2 hh = __floats2half2_rn(S[nt][2 * pr], S[nt][2 * pr + 1]);
                PH[nt][pr] = *(uint32_t*)&hh;
            }
        }

        // ---- O += P.(Vh + Vl)  (fp16, 2 passes) ----
        const uint32_t vHiB = sb + OFF_V + (uint32_t)(kt & 1) * 16384u;
        const uint32_t vLoB = vHiB + 8192u;
#pragma unroll
        for (int ks = 0; ks < 4; ks++) {
            uint32_t aP[4] = {PH[2*ks][0], PH[2*ks][1], PH[2*ks+1][0], PH[2*ks+1][1]};
            int row = ks * 16 + (lane & 15);
#pragma unroll
            for (int bt = 0; bt < 4; bt++) {
                uint32_t bd = vHiB + SW128(row * 128 + bt * 32 + ((lane >> 4) << 4));
                uint32_t r0, r1, r2, r3;
                LDSM_X4T(r0, r1, r2, r3, bd);
                MMAH16816(O[2*bt],     aP, r0, r1);
                MMAH16816(O[2*bt + 1], aP, r2, r3);
            }
#pragma unroll
            for (int bt = 0; bt < 4; bt++) {
                uint32_t bd = vLoB + SW128(row * 128 + bt * 32 + ((lane >> 4) << 4));
                uint32_t r0, r1, r2, r3;
                LDSM_X4T(r0, r1, r2, r3, bd);
                MMAH16816(O[2*bt],     aP, r0, r1);
                MMAH16816(O[2*bt + 1], aP, r2, r3);
            }
        }
    }

    // ---- epilogue: O /= l, split fp16 hi/lo -> g_at{h,l}[b][n][h*64+d] ----
    const int b_i = bh >> 4, hhead = bh & 15;
    float inv[2] = {1.0f / lrow[0], 1.0f / lrow[1]};
#pragma unroll
    for (int nt = 0; nt < 8; nt++) {
        int c = hhead * 64 + nt * 8 + (lane & 3) * 2;
#pragma unroll
        for (int h = 0; h < 2; h++) {
            int n = n0 + 16 * w + (lane >> 2) + 8 * h;
            float o0 = O[nt][2 * h] * inv[h];
            float o1 = O[nt][2 * h + 1] * inv[h];
            __half h0 = __float2half_rn(o0);
            __half h1 = __float2half_rn(o1);
            __half l0 = __float2half_rn(o0 - __half2float(h0));
            __half l1 = __float2half_rn(o1 - __half2float(h1));
            size_t idx = ((size_t)b_i * NSEQ + n) * DIMC + c;
            *(__half2*)&g_ath[idx] = __halves2half2(h0, h1);
            *(__half2*)&g_atl[idx] = __halves2half2(l0, l1);
        }
    }
}

// ============================================================================
extern "C" void kernel_launch(void* const* d_in, const int* in_sizes, int n_in,
                              void* d_out, int out_size)
{
    const float* x      = (const float*)d_in[0];
    const float* W_qkv  = (const float*)d_in[1];
    const float* W_proj = (const float*)d_in[2];
    const float* b_proj = (const float*)d_in[3];
    const float* Er     = (const float*)d_in[4];
    float* out = (float*)d_out;

    // 0) splits (single launch)
    split_all<<<(NSPLIT4 + 255) / 256, 256>>>(x, W_qkv, W_proj, Er);

    // 1) QKV via fp16 2-product HMMA: M=4096, N=3072 (2-stage x 48KB = 96 KB)
    const int gsmem = 2 * 49152;
    cudaFuncSetAttribute(hmma_gemm<0>,
                         cudaFuncAttributeMaxDynamicSharedMemorySize, gsmem);
    cudaFuncSetAttribute(hmma_gemm<1>,
                         cudaFuncAttributeMaxDynamicSharedMemorySize, gsmem);
    hmma_gemm<0><<<dim3(24, 32), 256, gsmem>>>(nullptr, nullptr);

    // 2) tensor-core fused attention (8 q-blocks x 64 bh)
    cudaFuncSetAttribute(attn_kernel,
                         cudaFuncAttributeMaxDynamicSharedMemorySize, ATTN_SMEM);
    attn_kernel<<<dim3(8, 64), 256, ATTN_SMEM>>>();

    // 3) proj via fp16 2-product HMMA: M=4096, N=1024, +bias
    hmma_gemm<1><<<dim3(8, 32), 256, gsmem>>>(b_proj, out);
}